// round 3
// baseline (speedup 1.0000x reference)
#include <cuda_runtime.h>
#include <cuda_bf16.h>
#include <math.h>

// ---------------- problem constants ----------------
#define Bz   2
#define Sz   2048
#define Dz   2048
#define Hz   16
#define HDz  128
#define RNz  32
#define FFz  4096
#define WINz 256
#define TOK  (Bz*Sz)          // 4096 tokens
#define EPSF 1e-5f
#define SCALEF 0.08838834764831845f   // 1/sqrt(128)

// ---------------- scratch (device globals; no allocation allowed) ----------------
__device__ float g_nx [TOK*Dz];        // LN(x) for attention
__device__ float g_f  [TOK*Dz];        // LN(x) for ffn
__device__ float g_qkv[TOK*3*Dz];      // qkv (q,k rewritten in place after rms/rope)
__device__ float g_y  [TOK*Dz];        // attention output
__device__ float g_h  [TOK*Dz];        // x + attn_out
__device__ float g_ffn[TOK*FFz];       // gelu(f@w1+b1)

// ---------------- fused double LayerNorm ----------------
// one block per token row (2048 cols), 256 threads, each thread owns float4 slots tid and tid+256
__global__ void ln_kernel(const float* __restrict__ x,
                          const float* __restrict__ aw, const float* __restrict__ ab,
                          const float* __restrict__ fw, const float* __restrict__ fb,
                          float* __restrict__ nx, float* __restrict__ f)
{
    int row = blockIdx.x;
    int tid = threadIdx.x;
    const float4* xr = (const float4*)(x + (size_t)row * Dz);
    float4 a = xr[tid];
    float4 b = xr[tid + 256];
    float s  = a.x + a.y + a.z + a.w + b.x + b.y + b.z + b.w;
    float ss = a.x*a.x + a.y*a.y + a.z*a.z + a.w*a.w
             + b.x*b.x + b.y*b.y + b.z*b.z + b.w*b.w;
    #pragma unroll
    for (int o = 16; o; o >>= 1) {
        s  += __shfl_xor_sync(0xffffffffu, s,  o);
        ss += __shfl_xor_sync(0xffffffffu, ss, o);
    }
    __shared__ float r1[8], r2[8];
    __shared__ float mv[2];
    int wid = tid >> 5;
    if ((tid & 31) == 0) { r1[wid] = s; r2[wid] = ss; }
    __syncthreads();
    if (tid == 0) {
        float S = 0.f, SS = 0.f;
        #pragma unroll
        for (int i = 0; i < 8; i++) { S += r1[i]; SS += r2[i]; }
        float m   = S * (1.f / Dz);
        float var = SS * (1.f / Dz) - m * m;
        mv[0] = m;
        mv[1] = rsqrtf(var + EPSF);
    }
    __syncthreads();
    float m = mv[0], r = mv[1];

    float4* nxr = (float4*)(nx + (size_t)row * Dz);
    float4* fr  = (float4*)(f  + (size_t)row * Dz);
    const float4* aw4 = (const float4*)aw;  const float4* ab4 = (const float4*)ab;
    const float4* fw4 = (const float4*)fw;  const float4* fb4 = (const float4*)fb;
    #pragma unroll
    for (int e = 0; e < 2; e++) {
        int slot = tid + e * 256;
        float4 v = (e == 0) ? a : b;
        float4 w1 = aw4[slot], b1 = ab4[slot], w2 = fw4[slot], b2 = fb4[slot];
        float4 o1, o2;
        o1.x = (v.x - m) * r * w1.x + b1.x;  o2.x = (v.x - m) * r * w2.x + b2.x;
        o1.y = (v.y - m) * r * w1.y + b1.y;  o2.y = (v.y - m) * r * w2.y + b2.y;
        o1.z = (v.z - m) * r * w1.z + b1.z;  o2.z = (v.z - m) * r * w2.z + b2.z;
        o1.w = (v.w - m) * r * w1.w + b1.w;  o2.w = (v.w - m) * r * w2.w + b2.w;
        nxr[slot] = o1;
        fr[slot]  = o2;
    }
}

// ---------------- SGEMM: C[M,N] = A[M,K] @ B[K,N] (+bias, +optional gelu, +optional residual) ----------------
// 128x128 block, BK=16, 256 threads, 8x8 micro-tile per thread
#define BM 128
#define BN 128
#define BK 16

__global__ __launch_bounds__(256, 2)
void sgemm_kernel(const float* __restrict__ A, const float* __restrict__ Bm,
                  const float* __restrict__ bias, const float* __restrict__ res,
                  float* __restrict__ C, int M, int N, int K, int do_gelu)
{
    __shared__ float As[BK][BM];
    __shared__ float Bs[BK][BN];
    int tid = threadIdx.x;
    int tx = tid & 15, ty = tid >> 4;
    int row0 = blockIdx.y * BM;
    int col0 = blockIdx.x * BN;

    float acc[8][8];
    #pragma unroll
    for (int i = 0; i < 8; i++)
        #pragma unroll
        for (int j = 0; j < 8; j++) acc[i][j] = 0.f;

    for (int k0 = 0; k0 < K; k0 += BK) {
        #pragma unroll
        for (int i = 0; i < 2; i++) {
            int s = tid * 2 + i;
            // A tile: 128 rows x 16 cols -> store transposed As[k][m]
            int ra = s >> 2, ca = (s & 3) * 4;
            float4 va = *(const float4*)(A + (size_t)(row0 + ra) * K + k0 + ca);
            As[ca + 0][ra] = va.x; As[ca + 1][ra] = va.y;
            As[ca + 2][ra] = va.z; As[ca + 3][ra] = va.w;
            // B tile: 16 rows x 128 cols -> direct
            int rb = s >> 5, cb = (s & 31) * 4;
            float4 vb = *(const float4*)(Bm + (size_t)(k0 + rb) * N + col0 + cb);
            *(float4*)&Bs[rb][cb] = vb;
        }
        __syncthreads();
        #pragma unroll
        for (int kk = 0; kk < BK; kk++) {
            float ar[8], br[8];
            *(float4*)(ar)     = *(const float4*)&As[kk][ty * 8];
            *(float4*)(ar + 4) = *(const float4*)&As[kk][ty * 8 + 4];
            *(float4*)(br)     = *(const float4*)&Bs[kk][tx * 8];
            *(float4*)(br + 4) = *(const float4*)&Bs[kk][tx * 8 + 4];
            #pragma unroll
            for (int i = 0; i < 8; i++)
                #pragma unroll
                for (int j = 0; j < 8; j++)
                    acc[i][j] = fmaf(ar[i], br[j], acc[i][j]);
        }
        __syncthreads();
    }

    // epilogue
    int c0 = col0 + tx * 8;
    float4 bi0 = *(const float4*)&bias[c0];
    float4 bi1 = *(const float4*)&bias[c0 + 4];
    #pragma unroll
    for (int i = 0; i < 8; i++) {
        size_t r = (size_t)(row0 + ty * 8 + i);
        float v[8];
        v[0] = acc[i][0] + bi0.x; v[1] = acc[i][1] + bi0.y;
        v[2] = acc[i][2] + bi0.z; v[3] = acc[i][3] + bi0.w;
        v[4] = acc[i][4] + bi1.x; v[5] = acc[i][5] + bi1.y;
        v[6] = acc[i][6] + bi1.z; v[7] = acc[i][7] + bi1.w;
        if (do_gelu) {
            #pragma unroll
            for (int j = 0; j < 8; j++)
                v[j] = 0.5f * v[j] * (1.f + erff(v[j] * 0.70710678118654752f));
        }
        if (res) {
            float4 r0 = *(const float4*)&res[r * N + c0];
            float4 r1 = *(const float4*)&res[r * N + c0 + 4];
            v[0] += r0.x; v[1] += r0.y; v[2] += r0.z; v[3] += r0.w;
            v[4] += r1.x; v[5] += r1.y; v[6] += r1.z; v[7] += r1.w;
        }
        *(float4*)&C[r * N + c0]     = make_float4(v[0], v[1], v[2], v[3]);
        *(float4*)&C[r * N + c0 + 4] = make_float4(v[4], v[5], v[6], v[7]);
    }
}

// ---------------- per-head RMS norm + RoPE (interleaved layout) + q scaling, in place ----------------
// grid = TOK*H blocks, 256 threads: threads [0,128) -> q head, [128,256) -> k head
__global__ void qkrope_kernel(float* __restrict__ qkv, const float* __restrict__ fc,
                              const float* __restrict__ qn_w, const float* __restrict__ kn_w)
{
    int blk   = blockIdx.x;
    int token = blk >> 4;        // / H
    int h     = blk & 15;
    int s     = token & (Sz - 1);
    int sel   = threadIdx.x >> 7;   // 0 = q, 1 = k
    int d     = threadIdx.x & 127;
    float* ptr = qkv + (size_t)token * (3 * Dz) + sel * Dz + h * HDz;
    float v = ptr[d];
    float ss = v * v;
    #pragma unroll
    for (int o = 16; o; o >>= 1) ss += __shfl_xor_sync(0xffffffffu, ss, o);
    __shared__ float red[8];
    __shared__ float rstd_s[2];
    int wid = threadIdx.x >> 5;
    if ((threadIdx.x & 31) == 0) red[wid] = ss;
    __syncthreads();
    if (d == 0) {
        float t = red[sel * 4] + red[sel * 4 + 1] + red[sel * 4 + 2] + red[sel * 4 + 3];
        rstd_s[sel] = rsqrtf(t * (1.f / HDz) + EPSF);
    }
    __syncthreads();
    float rstd = rstd_s[sel];
    float w = sel ? kn_w[d] : qn_w[d];
    float nv = v * rstd * w;
    if (d < RNz) {                 // warp-uniform: dims 0..31 form one full warp per group
        int j = d >> 1;
        float c  = fc[(s * 16 + j) * 2];
        float sn = fc[(s * 16 + j) * 2 + 1];
        float a = __shfl_sync(0xffffffffu, nv, j);        // x0[j]
        float b = __shfl_sync(0xffffffffu, nv, j + 16);   // x1[j]
        nv = (d & 1) ? (b * c + a * sn) : (a * c - b * sn);
    }
    if (sel == 0) nv *= SCALEF;    // fold softmax scale into q
    ptr[d] = nv;
}

// ---------------- sliding-window flash attention: one warp per query ----------------
// q pre-scaled; masked keys hard-skipped (exactly equivalent to NEG=-65504 masking)
__global__ void attn_kernel(const float* __restrict__ qkv, float* __restrict__ y)
{
    int gw  = (blockIdx.x * blockDim.x + threadIdx.x) >> 5;   // global warp = (b,h,q)
    int lane = threadIdx.x & 31;
    int qi = gw & (Sz - 1);
    int h  = (gw >> 11) & (Hz - 1);
    int b  = gw >> 15;

    const float* qrow = qkv + (size_t)(b * Sz + qi) * (3 * Dz) + h * HDz;
    float4 qv = *(const float4*)(qrow + lane * 4);

    int jstart = qi - (WINz - 1); if (jstart < 0) jstart = 0;
    float m = -1e30f, l = 0.f;
    float4 acc = make_float4(0.f, 0.f, 0.f, 0.f);

    for (int j = jstart; j <= qi; j++) {
        const float* base = qkv + (size_t)(b * Sz + j) * (3 * Dz) + h * HDz;
        float4 kv = *(const float4*)(base + Dz + lane * 4);
        float p = qv.x * kv.x + qv.y * kv.y + qv.z * kv.z + qv.w * kv.w;
        #pragma unroll
        for (int o = 16; o; o >>= 1) p += __shfl_xor_sync(0xffffffffu, p, o);
        float mn   = fmaxf(m, p);
        float corr = __expf(m - mn);
        float e    = __expf(p - mn);
        l = l * corr + e;
        m = mn;
        float4 vv = *(const float4*)(base + 2 * Dz + lane * 4);
        acc.x = acc.x * corr + e * vv.x;
        acc.y = acc.y * corr + e * vv.y;
        acc.z = acc.z * corr + e * vv.z;
        acc.w = acc.w * corr + e * vv.w;
    }
    float inv = 1.f / l;
    float4 o = make_float4(acc.x * inv, acc.y * inv, acc.z * inv, acc.w * inv);
    *(float4*)(y + (size_t)(b * Sz + qi) * Dz + h * HDz + lane * 4) = o;
}

// ---------------- launch ----------------
extern "C" void kernel_launch(void* const* d_in, const int* in_sizes, int n_in,
                              void* d_out, int out_size)
{
    const float* x      = (const float*)d_in[0];
    const float* fc     = (const float*)d_in[1];
    // d_in[2] = mask (implicit: causal sliding window of 256)
    const float* wqkv_w = (const float*)d_in[3];
    const float* wqkv_b = (const float*)d_in[4];
    const float* wo_w   = (const float*)d_in[5];
    const float* wo_b   = (const float*)d_in[6];
    const float* qn_w   = (const float*)d_in[7];
    const float* kn_w   = (const float*)d_in[8];
    const float* aln_w  = (const float*)d_in[9];
    const float* aln_b  = (const float*)d_in[10];
    const float* fln_w  = (const float*)d_in[11];
    const float* fln_b  = (const float*)d_in[12];
    const float* w1_w   = (const float*)d_in[13];
    const float* w1_b   = (const float*)d_in[14];
    const float* w2_w   = (const float*)d_in[15];
    const float* w2_b   = (const float*)d_in[16];
    float* out = (float*)d_out;

    float *nx, *f, *qkv, *y, *h, *ffn;
    cudaGetSymbolAddress((void**)&nx,  g_nx);
    cudaGetSymbolAddress((void**)&f,   g_f);
    cudaGetSymbolAddress((void**)&qkv, g_qkv);
    cudaGetSymbolAddress((void**)&y,   g_y);
    cudaGetSymbolAddress((void**)&h,   g_h);
    cudaGetSymbolAddress((void**)&ffn, g_ffn);

    // 1. fused LN (attn + ffn branches share mean/var)
    ln_kernel<<<TOK, 256>>>(x, aln_w, aln_b, fln_w, fln_b, nx, f);

    // 2. qkv = nx @ wqkv + b          [4096 x 6144] = [4096 x 2048] @ [2048 x 6144]
    sgemm_kernel<<<dim3(3 * Dz / BN, TOK / BM), 256>>>(nx, wqkv_w, wqkv_b, nullptr, qkv,
                                                        TOK, 3 * Dz, Dz, 0);

    // 3. per-head rms norm + rope + scale fold (in place on qkv)
    qkrope_kernel<<<TOK * Hz, 256>>>(qkv, fc, qn_w, kn_w);

    // 4. windowed attention -> y
    attn_kernel<<<(Bz * Hz * Sz * 32) / 256, 256>>>(qkv, y);

    // 5. h = y @ wo + b + x
    sgemm_kernel<<<dim3(Dz / BN, TOK / BM), 256>>>(y, wo_w, wo_b, x, h,
                                                    TOK, Dz, Dz, 0);

    // 6. ffn = gelu_exact(f @ w1 + b1)
    sgemm_kernel<<<dim3(FFz / BN, TOK / BM), 256>>>(f, w1_w, w1_b, nullptr, ffn,
                                                     TOK, FFz, Dz, 1);

    // 7. out = ffn @ w2 + b2 + h
    sgemm_kernel<<<dim3(Dz / BN, TOK / BM), 256>>>(ffn, w2_w, w2_b, h, out,
                                                    TOK, Dz, FFz, 0);
}

// round 5
// speedup vs baseline: 2.5511x; 2.5511x over previous
#include <cuda_runtime.h>
#include <cuda_bf16.h>
#include <math.h>
#include <stdint.h>

// ---------------- problem constants ----------------
#define Bz   2
#define Sz   2048
#define Dz   2048
#define Hz   16
#define HDz  128
#define RNz  32
#define FFz  4096
#define WINz 256
#define TOK  (Bz*Sz)          // 4096 tokens
#define EPSF 1e-5f
#define SCALEF 0.08838834764831845f   // 1/sqrt(128)

// ---------------- scratch (device globals; no allocation allowed) ----------------
__device__ float g_nx  [TOK*Dz];
__device__ float g_f   [TOK*Dz];
__device__ float g_qkv [TOK*3*Dz];
__device__ float g_y   [TOK*Dz];
__device__ float g_h   [TOK*Dz];
__device__ float g_ffn [TOK*FFz];
// transposed weights (B operand stored [N,K] K-major)
__device__ float g_wqkvT[3*Dz*Dz];
__device__ float g_woT  [Dz*Dz];
__device__ float g_w1T  [FFz*Dz];
__device__ float g_w2T  [Dz*FFz];

// ======================= helpers =======================
__device__ __forceinline__ uint32_t smem_u32(const void* p) {
    uint32_t a;
    asm("{ .reg .u64 t; cvta.to.shared.u64 t, %1; cvt.u32.u64 %0, t; }" : "=r"(a) : "l"(p));
    return a;
}
#define CP_ASYNC16(smem, gptr) \
    asm volatile("cp.async.cg.shared.global [%0], [%1], 16;" :: "r"(smem), "l"(gptr))
#define CP_COMMIT()  asm volatile("cp.async.commit_group;" ::: "memory")
#define CP_WAIT0()   asm volatile("cp.async.wait_group 0;" ::: "memory")
#define CP_WAIT1()   asm volatile("cp.async.wait_group 1;" ::: "memory")
#define CP_WAIT2()   asm volatile("cp.async.wait_group 2;" ::: "memory")

__device__ __forceinline__ uint32_t f2tf32(float x) {
    uint32_t r;
    asm("cvt.rna.tf32.f32 %0, %1;" : "=r"(r) : "f"(x));
    return r;
}
__device__ __forceinline__ void mma_tf32(float& c0, float& c1, float& c2, float& c3,
                                         uint32_t a0, uint32_t a1, uint32_t a2, uint32_t a3,
                                         uint32_t b0, uint32_t b1) {
    asm volatile(
        "mma.sync.aligned.m16n8k8.row.col.f32.tf32.tf32.f32 "
        "{%0,%1,%2,%3}, {%4,%5,%6,%7}, {%8,%9}, {%0,%1,%2,%3};"
        : "+f"(c0), "+f"(c1), "+f"(c2), "+f"(c3)
        : "r"(a0), "r"(a1), "r"(a2), "r"(a3), "r"(b0), "r"(b1));
}

// ======================= weight transpose: W[Kd,Nd] -> Wt[Nd,Kd] =======================
__global__ void transpose_kernel(const float* __restrict__ W, float* __restrict__ Wt,
                                 int Kd, int Nd) {
    __shared__ float t[32][33];
    int n0 = blockIdx.x * 32, k0 = blockIdx.y * 32;
    #pragma unroll
    for (int i = threadIdx.y; i < 32; i += 8)
        t[i][threadIdx.x] = W[(size_t)(k0 + i) * Nd + n0 + threadIdx.x];
    __syncthreads();
    #pragma unroll
    for (int i = threadIdx.y; i < 32; i += 8)
        Wt[(size_t)(n0 + i) * Kd + k0 + threadIdx.x] = t[threadIdx.x][i];
}

// ======================= tf32 mma.sync GEMM =======================
// C[M,N] = A[M,K] @ Bt[N,K]^T  (+bias, +gelu?, +res?)
// CTA tile 128x128, BK=32, 8 warps each 64x32, 3-stage cp.async pipeline.
#define BM 128
#define BN 128
#define BK 32
#define APAD 4
#define ASTR (BK + APAD)                 // 36 floats = 144 B (16B aligned)
#define TILE_FLOATS (BM * ASTR)          // 4608
#define STAGE_FLOATS (2 * TILE_FLOATS)   // 9216
#define STAGES 3
#define SM_TOTAL (STAGES * STAGE_FLOATS * 4)   // 110592 bytes

__global__ __launch_bounds__(256, 2)
void tc_gemm_kernel(const float* __restrict__ A, const float* __restrict__ Bt,
                    const float* __restrict__ bias, const float* __restrict__ res,
                    float* __restrict__ C, int M, int N, int K, int do_gelu)
{
    extern __shared__ float smem[];
    const uint32_t sm0 = smem_u32(smem);
    const int tid  = threadIdx.x;
    const int wid  = tid >> 5;
    const int lane = tid & 31;
    const int gid  = lane >> 2;     // group id 0..7
    const int tig  = lane & 3;      // thread in group 0..3
    const int wm   = wid >> 2;      // 0..1  (64-row slab)
    const int wn   = wid & 3;       // 0..3  (32-col slab)
    const int row0 = blockIdx.y * BM;
    const int col0 = blockIdx.x * BN;

    float acc[4][4][4];
    #pragma unroll
    for (int mi = 0; mi < 4; mi++)
        #pragma unroll
        for (int ni = 0; ni < 4; ni++)
            #pragma unroll
            for (int e = 0; e < 4; e++) acc[mi][ni][e] = 0.f;

    const int niter = K >> 5;

    // loader: 2048 16B chunks per stage (1024 A + 1024 B), 8 per thread
    auto load_stage = [&](int buf, int iter) {
        const int k0 = iter << 5;
        const uint32_t sb = sm0 + (uint32_t)buf * (STAGE_FLOATS * 4);
        #pragma unroll
        for (int t = 0; t < 8; t++) {
            int c   = tid + t * 256;
            int isB = c >> 10;
            int cc  = c & 1023;
            int row = cc >> 3, col8 = cc & 7;
            const float* g = (isB ? (Bt + (size_t)(col0 + row) * K)
                                  : (A  + (size_t)(row0 + row) * K)) + k0 + col8 * 4;
            uint32_t s = sb + (uint32_t)((isB ? TILE_FLOATS : 0) + row * ASTR + col8 * 4) * 4;
            CP_ASYNC16(s, g);
        }
        CP_COMMIT();
    };

    // prologue
    if (0 < niter) { load_stage(0, 0); }
    if (1 < niter) { load_stage(1, 1); }

    for (int i = 0; i < niter; i++) {
        if (i + 2 < niter) load_stage((i + 2) % STAGES, i + 2);
        if (i + 2 < niter)      { CP_WAIT2(); }
        else if (i + 1 < niter) { CP_WAIT1(); }
        else                    { CP_WAIT0(); }
        __syncthreads();

        const float* sA = smem + (i % STAGES) * STAGE_FLOATS;
        const float* sB = sA + TILE_FLOATS;
        const float* pa = sA + (wm * 64 + gid) * ASTR + tig;
        const float* pb = sB + (wn * 32 + gid) * ASTR + tig;

        #pragma unroll
        for (int ks = 0; ks < 4; ks++) {
            const int ko = ks * 8;
            uint32_t bfr[4][2];
            #pragma unroll
            for (int ni = 0; ni < 4; ni++) {
                const float* p = pb + ni * 8 * ASTR + ko;
                bfr[ni][0] = f2tf32(p[0]);
                bfr[ni][1] = f2tf32(p[4]);
            }
            #pragma unroll
            for (int mi = 0; mi < 4; mi++) {
                const float* p = pa + mi * 16 * ASTR + ko;
                uint32_t a0 = f2tf32(p[0]);
                uint32_t a1 = f2tf32(p[8 * ASTR]);
                uint32_t a2 = f2tf32(p[4]);
                uint32_t a3 = f2tf32(p[8 * ASTR + 4]);
                #pragma unroll
                for (int ni = 0; ni < 4; ni++)
                    mma_tf32(acc[mi][ni][0], acc[mi][ni][1], acc[mi][ni][2], acc[mi][ni][3],
                             a0, a1, a2, a3, bfr[ni][0], bfr[ni][1]);
            }
        }
        __syncthreads();
    }

    // ---------------- epilogue ----------------
    #pragma unroll
    for (int mi = 0; mi < 4; mi++) {
        #pragma unroll
        for (int half = 0; half < 2; half++) {          // c0/c1 vs c2/c3 (row, row+8)
            const size_t r = (size_t)(row0 + wm * 64 + mi * 16 + gid + half * 8);
            #pragma unroll
            for (int ni = 0; ni < 4; ni++) {
                const int cc = col0 + wn * 32 + ni * 8 + tig * 2;
                float v0 = acc[mi][ni][half * 2 + 0] + bias[cc];
                float v1 = acc[mi][ni][half * 2 + 1] + bias[cc + 1];
                if (do_gelu) {
                    v0 = 0.5f * v0 * (1.f + erff(v0 * 0.70710678118654752f));
                    v1 = 0.5f * v1 * (1.f + erff(v1 * 0.70710678118654752f));
                }
                if (res) {
                    float2 rr = *(const float2*)&res[r * N + cc];
                    v0 += rr.x; v1 += rr.y;
                }
                *(float2*)&C[r * N + cc] = make_float2(v0, v1);
            }
        }
    }
}

// ---------------- fused double LayerNorm ----------------
__global__ void ln_kernel(const float* __restrict__ x,
                          const float* __restrict__ aw, const float* __restrict__ ab,
                          const float* __restrict__ fw, const float* __restrict__ fb,
                          float* __restrict__ nx, float* __restrict__ f)
{
    int row = blockIdx.x;
    int tid = threadIdx.x;
    const float4* xr = (const float4*)(x + (size_t)row * Dz);
    float4 a = xr[tid];
    float4 b = xr[tid + 256];
    float s  = a.x + a.y + a.z + a.w + b.x + b.y + b.z + b.w;
    float ss = a.x*a.x + a.y*a.y + a.z*a.z + a.w*a.w
             + b.x*b.x + b.y*b.y + b.z*b.z + b.w*b.w;
    #pragma unroll
    for (int o = 16; o; o >>= 1) {
        s  += __shfl_xor_sync(0xffffffffu, s,  o);
        ss += __shfl_xor_sync(0xffffffffu, ss, o);
    }
    __shared__ float r1[8], r2[8];
    __shared__ float mv[2];
    int wid = tid >> 5;
    if ((tid & 31) == 0) { r1[wid] = s; r2[wid] = ss; }
    __syncthreads();
    if (tid == 0) {
        float S = 0.f, SS = 0.f;
        #pragma unroll
        for (int i = 0; i < 8; i++) { S += r1[i]; SS += r2[i]; }
        float m   = S * (1.f / Dz);
        float var = SS * (1.f / Dz) - m * m;
        mv[0] = m;
        mv[1] = rsqrtf(var + EPSF);
    }
    __syncthreads();
    float m = mv[0], r = mv[1];

    float4* nxr = (float4*)(nx + (size_t)row * Dz);
    float4* fr  = (float4*)(f  + (size_t)row * Dz);
    const float4* aw4 = (const float4*)aw;  const float4* ab4 = (const float4*)ab;
    const float4* fw4 = (const float4*)fw;  const float4* fb4 = (const float4*)fb;
    #pragma unroll
    for (int e = 0; e < 2; e++) {
        int slot = tid + e * 256;
        float4 v = (e == 0) ? a : b;
        float4 w1 = aw4[slot], b1 = ab4[slot], w2 = fw4[slot], b2 = fb4[slot];
        float4 o1, o2;
        o1.x = (v.x - m) * r * w1.x + b1.x;  o2.x = (v.x - m) * r * w2.x + b2.x;
        o1.y = (v.y - m) * r * w1.y + b1.y;  o2.y = (v.y - m) * r * w2.y + b2.y;
        o1.z = (v.z - m) * r * w1.z + b1.z;  o2.z = (v.z - m) * r * w2.z + b2.z;
        o1.w = (v.w - m) * r * w1.w + b1.w;  o2.w = (v.w - m) * r * w2.w + b2.w;
        nxr[slot] = o1;
        fr[slot]  = o2;
    }
}

// ---------------- per-head RMS norm + RoPE + q scaling, in place ----------------
__global__ void qkrope_kernel(float* __restrict__ qkv, const float* __restrict__ fc,
                              const float* __restrict__ qn_w, const float* __restrict__ kn_w)
{
    int blk   = blockIdx.x;
    int token = blk >> 4;
    int h     = blk & 15;
    int s     = token & (Sz - 1);
    int sel   = threadIdx.x >> 7;
    int d     = threadIdx.x & 127;
    float* ptr = qkv + (size_t)token * (3 * Dz) + sel * Dz + h * HDz;
    float v = ptr[d];
    float ss = v * v;
    #pragma unroll
    for (int o = 16; o; o >>= 1) ss += __shfl_xor_sync(0xffffffffu, ss, o);
    __shared__ float red[8];
    __shared__ float rstd_s[2];
    int wid = threadIdx.x >> 5;
    if ((threadIdx.x & 31) == 0) red[wid] = ss;
    __syncthreads();
    if (d == 0) {
        float t = red[sel * 4] + red[sel * 4 + 1] + red[sel * 4 + 2] + red[sel * 4 + 3];
        rstd_s[sel] = rsqrtf(t * (1.f / HDz) + EPSF);
    }
    __syncthreads();
    float rstd = rstd_s[sel];
    float w = sel ? kn_w[d] : qn_w[d];
    float nv = v * rstd * w;
    if (d < RNz) {
        int j = d >> 1;
        float c  = fc[(s * 16 + j) * 2];
        float sn = fc[(s * 16 + j) * 2 + 1];
        float a = __shfl_sync(0xffffffffu, nv, j);
        float b = __shfl_sync(0xffffffffu, nv, j + 16);
        nv = (d & 1) ? (b * c + a * sn) : (a * c - b * sn);
    }
    if (sel == 0) nv *= SCALEF;
    ptr[d] = nv;
}

// ---------------- sliding-window flash attention: one warp per query ----------------
__global__ void attn_kernel(const float* __restrict__ qkv, float* __restrict__ y)
{
    int gw  = (blockIdx.x * blockDim.x + threadIdx.x) >> 5;
    int lane = threadIdx.x & 31;
    int qi = gw & (Sz - 1);
    int h  = (gw >> 11) & (Hz - 1);
    int b  = gw >> 15;

    const float* qrow = qkv + (size_t)(b * Sz + qi) * (3 * Dz) + h * HDz;
    float4 qv = *(const float4*)(qrow + lane * 4);

    int jstart = qi - (WINz - 1); if (jstart < 0) jstart = 0;
    float m = -1e30f, l = 0.f;
    float4 acc = make_float4(0.f, 0.f, 0.f, 0.f);

    for (int j = jstart; j <= qi; j++) {
        const float* base = qkv + (size_t)(b * Sz + j) * (3 * Dz) + h * HDz;
        float4 kv = *(const float4*)(base + Dz + lane * 4);
        float p = qv.x * kv.x + qv.y * kv.y + qv.z * kv.z + qv.w * kv.w;
        #pragma unroll
        for (int o = 16; o; o >>= 1) p += __shfl_xor_sync(0xffffffffu, p, o);
        float mn   = fmaxf(m, p);
        float corr = __expf(m - mn);
        float e    = __expf(p - mn);
        l = l * corr + e;
        m = mn;
        float4 vv = *(const float4*)(base + 2 * Dz + lane * 4);
        acc.x = acc.x * corr + e * vv.x;
        acc.y = acc.y * corr + e * vv.y;
        acc.z = acc.z * corr + e * vv.z;
        acc.w = acc.w * corr + e * vv.w;
    }
    float inv = 1.f / l;
    float4 o = make_float4(acc.x * inv, acc.y * inv, acc.z * inv, acc.w * inv);
    *(float4*)(y + (size_t)(b * Sz + qi) * Dz + h * HDz + lane * 4) = o;
}

// ---------------- launch ----------------
extern "C" void kernel_launch(void* const* d_in, const int* in_sizes, int n_in,
                              void* d_out, int out_size)
{
    const float* x      = (const float*)d_in[0];
    const float* fc     = (const float*)d_in[1];
    // d_in[2] = mask (implicit: causal sliding window of 256)
    const float* wqkv_w = (const float*)d_in[3];
    const float* wqkv_b = (const float*)d_in[4];
    const float* wo_w   = (const float*)d_in[5];
    const float* wo_b   = (const float*)d_in[6];
    const float* qn_w   = (const float*)d_in[7];
    const float* kn_w   = (const float*)d_in[8];
    const float* aln_w  = (const float*)d_in[9];
    const float* aln_b  = (const float*)d_in[10];
    const float* fln_w  = (const float*)d_in[11];
    const float* fln_b  = (const float*)d_in[12];
    const float* w1_w   = (const float*)d_in[13];
    const float* w1_b   = (const float*)d_in[14];
    const float* w2_w   = (const float*)d_in[15];
    const float* w2_b   = (const float*)d_in[16];
    float* out = (float*)d_out;

    float *nx, *f, *qkv, *y, *h, *ffn, *wqkvT, *woT, *w1T, *w2T;
    cudaGetSymbolAddress((void**)&nx,    g_nx);
    cudaGetSymbolAddress((void**)&f,     g_f);
    cudaGetSymbolAddress((void**)&qkv,   g_qkv);
    cudaGetSymbolAddress((void**)&y,     g_y);
    cudaGetSymbolAddress((void**)&h,     g_h);
    cudaGetSymbolAddress((void**)&ffn,   g_ffn);
    cudaGetSymbolAddress((void**)&wqkvT, g_wqkvT);
    cudaGetSymbolAddress((void**)&woT,   g_woT);
    cudaGetSymbolAddress((void**)&w1T,   g_w1T);
    cudaGetSymbolAddress((void**)&w2T,   g_w2T);

    static int smem_cfg = 0;
    if (!smem_cfg) {
        cudaFuncSetAttribute(tc_gemm_kernel,
                             cudaFuncAttributeMaxDynamicSharedMemorySize, SM_TOTAL);
        smem_cfg = 1;
    }

    // 0. weight transposes (W[K,N] -> Wt[N,K])
    transpose_kernel<<<dim3(3 * Dz / 32, Dz / 32), dim3(32, 8)>>>(wqkv_w, wqkvT, Dz, 3 * Dz);
    transpose_kernel<<<dim3(Dz / 32,     Dz / 32), dim3(32, 8)>>>(wo_w,   woT,   Dz, Dz);
    transpose_kernel<<<dim3(FFz / 32,    Dz / 32), dim3(32, 8)>>>(w1_w,   w1T,   Dz, FFz);
    transpose_kernel<<<dim3(Dz / 32,    FFz / 32), dim3(32, 8)>>>(w2_w,   w2T,   FFz, Dz);

    // 1. fused LN (attn + ffn branches share mean/var)
    ln_kernel<<<TOK, 256>>>(x, aln_w, aln_b, fln_w, fln_b, nx, f);

    // 2. qkv = nx @ wqkv + b
    tc_gemm_kernel<<<dim3(3 * Dz / BN, TOK / BM), 256, SM_TOTAL>>>(
        nx, wqkvT, wqkv_b, nullptr, qkv, TOK, 3 * Dz, Dz, 0);

    // 3. per-head rms norm + rope + scale fold
    qkrope_kernel<<<TOK * Hz, 256>>>(qkv, fc, qn_w, kn_w);

    // 4. windowed attention -> y
    attn_kernel<<<(Bz * Hz * Sz * 32) / 256, 256>>>(qkv, y);

    // 5. h = y @ wo + b + x
    tc_gemm_kernel<<<dim3(Dz / BN, TOK / BM), 256, SM_TOTAL>>>(
        y, woT, wo_b, x, h, TOK, Dz, Dz, 0);

    // 6. ffn = gelu_exact(f @ w1 + b1)
    tc_gemm_kernel<<<dim3(FFz / BN, TOK / BM), 256, SM_TOTAL>>>(
        f, w1T, w1_b, nullptr, ffn, TOK, FFz, Dz, 1);

    // 7. out = ffn @ w2 + b2 + h
    tc_gemm_kernel<<<dim3(Dz / BN, TOK / BM), 256, SM_TOTAL>>>(
        ffn, w2T, w2_b, h, out, TOK, Dz, FFz, 0);
}

// round 7
// speedup vs baseline: 3.4504x; 1.3526x over previous
#include <cuda_runtime.h>
#include <cuda_bf16.h>
#include <math.h>
#include <stdint.h>

// ---------------- problem constants ----------------
#define Bz   2
#define Sz   2048
#define Dz   2048
#define Hz   16
#define HDz  128
#define RNz  32
#define FFz  4096
#define WINz 256
#define TOK  (Bz*Sz)          // 4096 tokens
#define EPSF 1e-5f
#define SCALEF 0.08838834764831845f   // 1/sqrt(128)

// ---------------- scratch (device globals; no allocation allowed) ----------------
__device__ float g_nx  [TOK*Dz];
__device__ float g_f   [TOK*Dz];
__device__ float g_qkv [TOK*3*Dz];
__device__ float g_y   [TOK*Dz];
__device__ float g_h   [TOK*Dz];
__device__ float g_ffn [TOK*FFz];
// transposed weights (B operand stored [N,K] K-major)
__device__ float g_wqkvT[3*Dz*Dz];
__device__ float g_woT  [Dz*Dz];
__device__ float g_w1T  [FFz*Dz];
__device__ float g_w2T  [Dz*FFz];

// ======================= helpers =======================
__device__ __forceinline__ uint32_t smem_u32(const void* p) {
    uint32_t a;
    asm("{ .reg .u64 t; cvta.to.shared.u64 t, %1; cvt.u32.u64 %0, t; }" : "=r"(a) : "l"(p));
    return a;
}
#define CP_ASYNC16(smem, gptr) \
    asm volatile("cp.async.cg.shared.global [%0], [%1], 16;" :: "r"(smem), "l"(gptr))
#define CP_COMMIT()  asm volatile("cp.async.commit_group;" ::: "memory")
#define CP_WAIT0()   asm volatile("cp.async.wait_group 0;" ::: "memory")
#define CP_WAIT1()   asm volatile("cp.async.wait_group 1;" ::: "memory")
#define CP_WAIT2()   asm volatile("cp.async.wait_group 2;" ::: "memory")

__device__ __forceinline__ uint32_t f2tf32(float x) {
    uint32_t r;
    asm("cvt.rna.tf32.f32 %0, %1;" : "=r"(r) : "f"(x));
    return r;
}
__device__ __forceinline__ void mma_tf32(float& c0, float& c1, float& c2, float& c3,
                                         uint32_t a0, uint32_t a1, uint32_t a2, uint32_t a3,
                                         uint32_t b0, uint32_t b1) {
    asm volatile(
        "mma.sync.aligned.m16n8k8.row.col.f32.tf32.tf32.f32 "
        "{%0,%1,%2,%3}, {%4,%5,%6,%7}, {%8,%9}, {%0,%1,%2,%3};"
        : "+f"(c0), "+f"(c1), "+f"(c2), "+f"(c3)
        : "r"(a0), "r"(a1), "r"(a2), "r"(a3), "r"(b0), "r"(b1));
}

// ======================= weight transpose: W[Kd,Nd] -> Wt[Nd,Kd] =======================
__global__ void transpose_kernel(const float* __restrict__ W, float* __restrict__ Wt,
                                 int Kd, int Nd) {
    __shared__ float t[32][33];
    int n0 = blockIdx.x * 32, k0 = blockIdx.y * 32;
    #pragma unroll
    for (int i = threadIdx.y; i < 32; i += 8)
        t[i][threadIdx.x] = W[(size_t)(k0 + i) * Nd + n0 + threadIdx.x];
    __syncthreads();
    #pragma unroll
    for (int i = threadIdx.y; i < 32; i += 8)
        Wt[(size_t)(n0 + i) * Kd + k0 + threadIdx.x] = t[threadIdx.x][i];
}

// ======================= tf32 mma.sync GEMM =======================
#define BM 128
#define BN 128
#define BK 32
#define APAD 4
#define ASTR (BK + APAD)                 // 36 floats = 144 B
#define TILE_FLOATS (BM * ASTR)          // 4608
#define STAGE_FLOATS (2 * TILE_FLOATS)   // 9216
#define STAGES 3
#define SM_TOTAL (STAGES * STAGE_FLOATS * 4)   // 110592 bytes

__global__ __launch_bounds__(256, 2)
void tc_gemm_kernel(const float* __restrict__ A, const float* __restrict__ Bt,
                    const float* __restrict__ bias, const float* __restrict__ res,
                    float* __restrict__ C, int M, int N, int K, int do_gelu)
{
    extern __shared__ float smem[];
    const uint32_t sm0 = smem_u32(smem);
    const int tid  = threadIdx.x;
    const int wid  = tid >> 5;
    const int lane = tid & 31;
    const int gid  = lane >> 2;
    const int tig  = lane & 3;
    const int wm   = wid >> 2;
    const int wn   = wid & 3;
    const int row0 = blockIdx.y * BM;
    const int col0 = blockIdx.x * BN;

    float acc[4][4][4];
    #pragma unroll
    for (int mi = 0; mi < 4; mi++)
        #pragma unroll
        for (int ni = 0; ni < 4; ni++)
            #pragma unroll
            for (int e = 0; e < 4; e++) acc[mi][ni][e] = 0.f;

    const int niter = K >> 5;

    auto load_stage = [&](int buf, int iter) {
        const int k0 = iter << 5;
        const uint32_t sb = sm0 + (uint32_t)buf * (STAGE_FLOATS * 4);
        #pragma unroll
        for (int t = 0; t < 8; t++) {
            int c   = tid + t * 256;
            int isB = c >> 10;
            int cc  = c & 1023;
            int row = cc >> 3, col8 = cc & 7;
            const float* g = (isB ? (Bt + (size_t)(col0 + row) * K)
                                  : (A  + (size_t)(row0 + row) * K)) + k0 + col8 * 4;
            uint32_t s = sb + (uint32_t)((isB ? TILE_FLOATS : 0) + row * ASTR + col8 * 4) * 4;
            CP_ASYNC16(s, g);
        }
        CP_COMMIT();
    };

    if (0 < niter) { load_stage(0, 0); }
    if (1 < niter) { load_stage(1, 1); }

    for (int i = 0; i < niter; i++) {
        if (i + 2 < niter) load_stage((i + 2) % STAGES, i + 2);
        if (i + 2 < niter)      { CP_WAIT2(); }
        else if (i + 1 < niter) { CP_WAIT1(); }
        else                    { CP_WAIT0(); }
        __syncthreads();

        const float* sA = smem + (i % STAGES) * STAGE_FLOATS;
        const float* sB = sA + TILE_FLOATS;
        const float* pa = sA + (wm * 64 + gid) * ASTR + tig;
        const float* pb = sB + (wn * 32 + gid) * ASTR + tig;

        #pragma unroll
        for (int ks = 0; ks < 4; ks++) {
            const int ko = ks * 8;
            uint32_t bfr[4][2];
            #pragma unroll
            for (int ni = 0; ni < 4; ni++) {
                const float* p = pb + ni * 8 * ASTR + ko;
                bfr[ni][0] = f2tf32(p[0]);
                bfr[ni][1] = f2tf32(p[4]);
            }
            #pragma unroll
            for (int mi = 0; mi < 4; mi++) {
                const float* p = pa + mi * 16 * ASTR + ko;
                uint32_t a0 = f2tf32(p[0]);
                uint32_t a1 = f2tf32(p[8 * ASTR]);
                uint32_t a2 = f2tf32(p[4]);
                uint32_t a3 = f2tf32(p[8 * ASTR + 4]);
                #pragma unroll
                for (int ni = 0; ni < 4; ni++)
                    mma_tf32(acc[mi][ni][0], acc[mi][ni][1], acc[mi][ni][2], acc[mi][ni][3],
                             a0, a1, a2, a3, bfr[ni][0], bfr[ni][1]);
            }
        }
        __syncthreads();
    }

    #pragma unroll
    for (int mi = 0; mi < 4; mi++) {
        #pragma unroll
        for (int half = 0; half < 2; half++) {
            const size_t r = (size_t)(row0 + wm * 64 + mi * 16 + gid + half * 8);
            #pragma unroll
            for (int ni = 0; ni < 4; ni++) {
                const int cc = col0 + wn * 32 + ni * 8 + tig * 2;
                float v0 = acc[mi][ni][half * 2 + 0] + bias[cc];
                float v1 = acc[mi][ni][half * 2 + 1] + bias[cc + 1];
                if (do_gelu) {
                    v0 = 0.5f * v0 * (1.f + erff(v0 * 0.70710678118654752f));
                    v1 = 0.5f * v1 * (1.f + erff(v1 * 0.70710678118654752f));
                }
                if (res) {
                    float2 rr = *(const float2*)&res[r * N + cc];
                    v0 += rr.x; v1 += rr.y;
                }
                *(float2*)&C[r * N + cc] = make_float2(v0, v1);
            }
        }
    }
}

// ---------------- fused double LayerNorm ----------------
__global__ void ln_kernel(const float* __restrict__ x,
                          const float* __restrict__ aw, const float* __restrict__ ab,
                          const float* __restrict__ fw, const float* __restrict__ fb,
                          float* __restrict__ nx, float* __restrict__ f)
{
    int row = blockIdx.x;
    int tid = threadIdx.x;
    const float4* xr = (const float4*)(x + (size_t)row * Dz);
    float4 a = xr[tid];
    float4 b = xr[tid + 256];
    float s  = a.x + a.y + a.z + a.w + b.x + b.y + b.z + b.w;
    float ss = a.x*a.x + a.y*a.y + a.z*a.z + a.w*a.w
             + b.x*b.x + b.y*b.y + b.z*b.z + b.w*b.w;
    #pragma unroll
    for (int o = 16; o; o >>= 1) {
        s  += __shfl_xor_sync(0xffffffffu, s,  o);
        ss += __shfl_xor_sync(0xffffffffu, ss, o);
    }
    __shared__ float r1[8], r2[8];
    __shared__ float mv[2];
    int wid = tid >> 5;
    if ((tid & 31) == 0) { r1[wid] = s; r2[wid] = ss; }
    __syncthreads();
    if (tid == 0) {
        float S = 0.f, SS = 0.f;
        #pragma unroll
        for (int i = 0; i < 8; i++) { S += r1[i]; SS += r2[i]; }
        float m   = S * (1.f / Dz);
        float var = SS * (1.f / Dz) - m * m;
        mv[0] = m;
        mv[1] = rsqrtf(var + EPSF);
    }
    __syncthreads();
    float m = mv[0], r = mv[1];

    float4* nxr = (float4*)(nx + (size_t)row * Dz);
    float4* fr  = (float4*)(f  + (size_t)row * Dz);
    const float4* aw4 = (const float4*)aw;  const float4* ab4 = (const float4*)ab;
    const float4* fw4 = (const float4*)fw;  const float4* fb4 = (const float4*)fb;
    #pragma unroll
    for (int e = 0; e < 2; e++) {
        int slot = tid + e * 256;
        float4 v = (e == 0) ? a : b;
        float4 w1 = aw4[slot], b1 = ab4[slot], w2 = fw4[slot], b2 = fb4[slot];
        float4 o1, o2;
        o1.x = (v.x - m) * r * w1.x + b1.x;  o2.x = (v.x - m) * r * w2.x + b2.x;
        o1.y = (v.y - m) * r * w1.y + b1.y;  o2.y = (v.y - m) * r * w2.y + b2.y;
        o1.z = (v.z - m) * r * w1.z + b1.z;  o2.z = (v.z - m) * r * w2.z + b2.z;
        o1.w = (v.w - m) * r * w1.w + b1.w;  o2.w = (v.w - m) * r * w2.w + b2.w;
        nxr[slot] = o1;
        fr[slot]  = o2;
    }
}

// ---------------- per-head RMS norm + RoPE + q scaling, in place ----------------
__global__ void qkrope_kernel(float* __restrict__ qkv, const float* __restrict__ fc,
                              const float* __restrict__ qn_w, const float* __restrict__ kn_w)
{
    int blk   = blockIdx.x;
    int token = blk >> 4;
    int h     = blk & 15;
    int s     = token & (Sz - 1);
    int sel   = threadIdx.x >> 7;
    int d     = threadIdx.x & 127;
    float* ptr = qkv + (size_t)token * (3 * Dz) + sel * Dz + h * HDz;
    float v = ptr[d];
    float ss = v * v;
    #pragma unroll
    for (int o = 16; o; o >>= 1) ss += __shfl_xor_sync(0xffffffffu, ss, o);
    __shared__ float red[8];
    __shared__ float rstd_s[2];
    int wid = threadIdx.x >> 5;
    if ((threadIdx.x & 31) == 0) red[wid] = ss;
    __syncthreads();
    if (d == 0) {
        float t = red[sel * 4] + red[sel * 4 + 1] + red[sel * 4 + 2] + red[sel * 4 + 3];
        rstd_s[sel] = rsqrtf(t * (1.f / HDz) + EPSF);
    }
    __syncthreads();
    float rstd = rstd_s[sel];
    float w = sel ? kn_w[d] : qn_w[d];
    float nv = v * rstd * w;
    if (d < RNz) {
        int j = d >> 1;
        float c  = fc[(s * 16 + j) * 2];
        float sn = fc[(s * 16 + j) * 2 + 1];
        float a = __shfl_sync(0xffffffffu, nv, j);
        float b = __shfl_sync(0xffffffffu, nv, j + 16);
        nv = (d & 1) ? (b * c + a * sn) : (a * c - b * sn);
    }
    if (sel == 0) nv *= SCALEF;
    ptr[d] = nv;
}

// ======================= FA2-style windowed attention (tf32 mma) =======================
// CTA: 64 queries of one (b,h); 4 warps x 16 queries. Keys in 32-wide chunks,
// double-buffered cp.async into smem, converted to tf32 in place.
#define AT_CK 32
#define KSTR 132                        // 132 % 32 == 4 -> score-frag reads conflict-free
#define VSTR 136                        // 136 % 32 == 8 -> V-frag reads conflict-free
#define AT_K_OFF(buf) ((buf) * (AT_CK * KSTR))
#define AT_V_OFF(buf) (2 * AT_CK * KSTR + (buf) * (AT_CK * VSTR))
#define AT_SMEM_FLOATS (2 * AT_CK * KSTR + 2 * AT_CK * VSTR)   // 17152
#define AT_SMEM_BYTES  (AT_SMEM_FLOATS * 4)                     // 68608

__global__ __launch_bounds__(128, 2)
void attn_mma_kernel(const float* __restrict__ qkv, float* __restrict__ y)
{
    extern __shared__ float sm[];
    const uint32_t sm0 = smem_u32(sm);
    const int tid  = threadIdx.x;
    const int wi   = tid >> 5;
    const int lane = tid & 31;
    const int gid  = lane >> 2;
    const int tig  = lane & 3;
    const int qb0  = (blockIdx.x & 31) << 6;
    const int h    = (blockIdx.x >> 5) & 15;
    const int b    = blockIdx.x >> 9;
    const int qw   = qb0 + wi * 16;     // this warp's first query

    // ---- Q fragments (held in registers as tf32) ----
    uint32_t qf[16][4];
    {
        const float* q0 = qkv + (size_t)(b * Sz + qw + gid) * (3 * Dz) + h * HDz;
        const float* q1 = q0 + (size_t)8 * (3 * Dz);
        #pragma unroll
        for (int kg = 0; kg < 16; kg++) {
            qf[kg][0] = f2tf32(q0[kg * 8 + tig]);
            qf[kg][1] = f2tf32(q1[kg * 8 + tig]);
            qf[kg][2] = f2tf32(q0[kg * 8 + tig + 4]);
            qf[kg][3] = f2tf32(q1[kg * 8 + tig + 4]);
        }
    }

    float o[16][4];
    #pragma unroll
    for (int dt = 0; dt < 16; dt++)
        #pragma unroll
        for (int e = 0; e < 4; e++) o[dt][e] = 0.f;
    float m0 = -1e30f, m1 = -1e30f, l0 = 0.f, l1 = 0.f;

    int cs = qb0 - (WINz - 1); if (cs < 0) cs = 0;
    cs &= ~31;
    const int nc = ((qb0 + 63 - cs) >> 5) + 1;

    // chunk loader: 32 keys x 128 dims, K and V, 16 x cp.async per thread
    auto load_chunk = [&](int buf, int jc) {
        #pragma unroll
        for (int i = 0; i < 8; i++) {
            int fidx = i * 128 + tid;           // float4 index 0..1023
            int row = fidx >> 5, c4 = fidx & 31;
            const float* gk = qkv + (size_t)(b * Sz + jc + row) * (3 * Dz) + Dz + h * HDz + c4 * 4;
            CP_ASYNC16(sm0 + (uint32_t)(AT_K_OFF(buf) + row * KSTR + c4 * 4) * 4, gk);
        }
        #pragma unroll
        for (int i = 0; i < 8; i++) {
            int fidx = i * 128 + tid;
            int row = fidx >> 5, c4 = fidx & 31;
            const float* gv = qkv + (size_t)(b * Sz + jc + row) * (3 * Dz) + 2 * Dz + h * HDz + c4 * 4;
            CP_ASYNC16(sm0 + (uint32_t)(AT_V_OFF(buf) + row * VSTR + c4 * 4) * 4, gv);
        }
        CP_COMMIT();
    };

    load_chunk(0, cs);

    for (int c = 0; c < nc; c++) {
        const int jc  = cs + c * 32;
        const int buf = c & 1;
        if (c + 1 < nc) { load_chunk((c + 1) & 1, jc + 32); CP_WAIT1(); }
        else            { CP_WAIT0(); }
        __syncthreads();

        // in-place tf32 conversion of this thread's own cp.async slots
        #pragma unroll
        for (int i = 0; i < 8; i++) {
            int fidx = i * 128 + tid;
            int row = fidx >> 5, c4 = fidx & 31;
            float* pk = sm + AT_K_OFF(buf) + row * KSTR + c4 * 4;
            float4 v = *(float4*)pk;
            uint4 w; w.x = f2tf32(v.x); w.y = f2tf32(v.y); w.z = f2tf32(v.z); w.w = f2tf32(v.w);
            *(uint4*)pk = w;
            float* pv = sm + AT_V_OFF(buf) + row * VSTR + c4 * 4;
            v = *(float4*)pv;
            w.x = f2tf32(v.x); w.y = f2tf32(v.y); w.z = f2tf32(v.z); w.w = f2tf32(v.w);
            *(uint4*)pv = w;
        }
        __syncthreads();

        const bool act = (jc <= qw + 15) && (jc + 31 >= qw - (WINz - 1));
        if (act) {
            const uint32_t* Ks = (const uint32_t*)(sm + AT_K_OFF(buf));
            const uint32_t* Vs = (const uint32_t*)(sm + AT_V_OFF(buf));

            // ---- scores: S[16q x 32k] via 4 n-tiles x 16 k-dim groups ----
            float sc[4][4];
            #pragma unroll
            for (int ng = 0; ng < 4; ng++)
                #pragma unroll
                for (int e = 0; e < 4; e++) sc[ng][e] = 0.f;
            #pragma unroll
            for (int kg = 0; kg < 16; kg++) {
                #pragma unroll
                for (int ng = 0; ng < 4; ng++) {
                    const uint32_t* kp = Ks + (ng * 8 + gid) * KSTR + kg * 8 + tig;
                    mma_tf32(sc[ng][0], sc[ng][1], sc[ng][2], sc[ng][3],
                             qf[kg][0], qf[kg][1], qf[kg][2], qf[kg][3],
                             kp[0], kp[4]);
                }
            }

            // ---- online softmax ----
            const int q0r = qw + gid, q1r = qw + gid + 8;
            float smax0 = -1e30f, smax1 = -1e30f;
            #pragma unroll
            for (int ng = 0; ng < 4; ng++) {
                int j0 = jc + ng * 8 + tig * 2;
                smax0 = fmaxf(smax0, ((unsigned)(q0r - j0)     < 256u) ? sc[ng][0] : -1e30f);
                smax0 = fmaxf(smax0, ((unsigned)(q0r - j0 - 1) < 256u) ? sc[ng][1] : -1e30f);
                smax1 = fmaxf(smax1, ((unsigned)(q1r - j0)     < 256u) ? sc[ng][2] : -1e30f);
                smax1 = fmaxf(smax1, ((unsigned)(q1r - j0 - 1) < 256u) ? sc[ng][3] : -1e30f);
            }
            smax0 = fmaxf(smax0, __shfl_xor_sync(0xffffffffu, smax0, 1));
            smax0 = fmaxf(smax0, __shfl_xor_sync(0xffffffffu, smax0, 2));
            smax1 = fmaxf(smax1, __shfl_xor_sync(0xffffffffu, smax1, 1));
            smax1 = fmaxf(smax1, __shfl_xor_sync(0xffffffffu, smax1, 2));
            float m0n = fmaxf(m0, smax0), m1n = fmaxf(m1, smax1);
            float cr0 = __expf(m0 - m0n), cr1 = __expf(m1 - m1n);
            m0 = m0n; m1 = m1n;

            float ps0 = 0.f, ps1 = 0.f;
            #pragma unroll
            for (int ng = 0; ng < 4; ng++) {
                int j0 = jc + ng * 8 + tig * 2;
                float e;
                e = ((unsigned)(q0r - j0)     < 256u) ? __expf(sc[ng][0] - m0) : 0.f;
                sc[ng][0] = e; ps0 += e;
                e = ((unsigned)(q0r - j0 - 1) < 256u) ? __expf(sc[ng][1] - m0) : 0.f;
                sc[ng][1] = e; ps0 += e;
                e = ((unsigned)(q1r - j0)     < 256u) ? __expf(sc[ng][2] - m1) : 0.f;
                sc[ng][2] = e; ps1 += e;
                e = ((unsigned)(q1r - j0 - 1) < 256u) ? __expf(sc[ng][3] - m1) : 0.f;
                sc[ng][3] = e; ps1 += e;
            }
            ps0 += __shfl_xor_sync(0xffffffffu, ps0, 1);
            ps0 += __shfl_xor_sync(0xffffffffu, ps0, 2);
            ps1 += __shfl_xor_sync(0xffffffffu, ps1, 1);
            ps1 += __shfl_xor_sync(0xffffffffu, ps1, 2);
            l0 = l0 * cr0 + ps0;
            l1 = l1 * cr1 + ps1;

            // rescale output accumulators
            #pragma unroll
            for (int dt = 0; dt < 16; dt++) {
                o[dt][0] *= cr0; o[dt][1] *= cr0;
                o[dt][2] *= cr1; o[dt][3] *= cr1;
            }

            // ---- permute P from C-layout to A-fragment layout ----
            uint32_t af[4][4];
            const int src  = (lane & ~3) | (tig >> 1);
            const int src2 = src + 2;
            #pragma unroll
            for (int ng = 0; ng < 4; ng++) {
                float v0 = __shfl_sync(0xffffffffu, sc[ng][0], src);
                float v1 = __shfl_sync(0xffffffffu, sc[ng][1], src);
                float v2 = __shfl_sync(0xffffffffu, sc[ng][2], src);
                float v3 = __shfl_sync(0xffffffffu, sc[ng][3], src);
                float w0 = __shfl_sync(0xffffffffu, sc[ng][0], src2);
                float w1 = __shfl_sync(0xffffffffu, sc[ng][1], src2);
                float w2 = __shfl_sync(0xffffffffu, sc[ng][2], src2);
                float w3 = __shfl_sync(0xffffffffu, sc[ng][3], src2);
                af[ng][0] = f2tf32((tig & 1) ? v1 : v0);
                af[ng][1] = f2tf32((tig & 1) ? v3 : v2);
                af[ng][2] = f2tf32((tig & 1) ? w1 : w0);
                af[ng][3] = f2tf32((tig & 1) ? w3 : w2);
            }

            // ---- PV: out[16q x 128d] += P[16x32] @ V[32x128] ----
            #pragma unroll
            for (int dt = 0; dt < 16; dt++) {
                #pragma unroll
                for (int ng = 0; ng < 4; ng++) {
                    const uint32_t* vp = Vs + (ng * 8 + tig) * VSTR + dt * 8 + gid;
                    mma_tf32(o[dt][0], o[dt][1], o[dt][2], o[dt][3],
                             af[ng][0], af[ng][1], af[ng][2], af[ng][3],
                             vp[0], vp[4 * VSTR]);
                }
            }
        }
        __syncthreads();
    }

    // ---- write normalized output ----
    const float i0 = 1.f / l0, i1 = 1.f / l1;
    float* y0 = y + (size_t)(b * Sz + qw + gid) * Dz + h * HDz;
    float* y1 = y0 + (size_t)8 * Dz;
    #pragma unroll
    for (int dt = 0; dt < 16; dt++) {
        *(float2*)(y0 + dt * 8 + tig * 2) = make_float2(o[dt][0] * i0, o[dt][1] * i0);
        *(float2*)(y1 + dt * 8 + tig * 2) = make_float2(o[dt][2] * i1, o[dt][3] * i1);
    }
}

// ---------------- launch ----------------
extern "C" void kernel_launch(void* const* d_in, const int* in_sizes, int n_in,
                              void* d_out, int out_size)
{
    const float* x      = (const float*)d_in[0];
    const float* fc     = (const float*)d_in[1];
    // d_in[2] = mask (implicit: causal sliding window of 256)
    const float* wqkv_w = (const float*)d_in[3];
    const float* wqkv_b = (const float*)d_in[4];
    const float* wo_w   = (const float*)d_in[5];
    const float* wo_b   = (const float*)d_in[6];
    const float* qn_w   = (const float*)d_in[7];
    const float* kn_w   = (const float*)d_in[8];
    const float* aln_w  = (const float*)d_in[9];
    const float* aln_b  = (const float*)d_in[10];
    const float* fln_w  = (const float*)d_in[11];
    const float* fln_b  = (const float*)d_in[12];
    const float* w1_w   = (const float*)d_in[13];
    const float* w1_b   = (const float*)d_in[14];
    const float* w2_w   = (const float*)d_in[15];
    const float* w2_b   = (const float*)d_in[16];
    float* out = (float*)d_out;

    float *nx, *f, *qkv, *y, *h, *ffn, *wqkvT, *woT, *w1T, *w2T;
    cudaGetSymbolAddress((void**)&nx,    g_nx);
    cudaGetSymbolAddress((void**)&f,     g_f);
    cudaGetSymbolAddress((void**)&qkv,   g_qkv);
    cudaGetSymbolAddress((void**)&y,     g_y);
    cudaGetSymbolAddress((void**)&h,     g_h);
    cudaGetSymbolAddress((void**)&ffn,   g_ffn);
    cudaGetSymbolAddress((void**)&wqkvT, g_wqkvT);
    cudaGetSymbolAddress((void**)&woT,   g_woT);
    cudaGetSymbolAddress((void**)&w1T,   g_w1T);
    cudaGetSymbolAddress((void**)&w2T,   g_w2T);

    static int smem_cfg = 0;
    if (!smem_cfg) {
        cudaFuncSetAttribute(tc_gemm_kernel,
                             cudaFuncAttributeMaxDynamicSharedMemorySize, SM_TOTAL);
        cudaFuncSetAttribute(attn_mma_kernel,
                             cudaFuncAttributeMaxDynamicSharedMemorySize, AT_SMEM_BYTES);
        smem_cfg = 1;
    }

    // 0. weight transposes (W[K,N] -> Wt[N,K])
    transpose_kernel<<<dim3(3 * Dz / 32, Dz / 32), dim3(32, 8)>>>(wqkv_w, wqkvT, Dz, 3 * Dz);
    transpose_kernel<<<dim3(Dz / 32,     Dz / 32), dim3(32, 8)>>>(wo_w,   woT,   Dz, Dz);
    transpose_kernel<<<dim3(FFz / 32,    Dz / 32), dim3(32, 8)>>>(w1_w,   w1T,   Dz, FFz);
    transpose_kernel<<<dim3(Dz / 32,    FFz / 32), dim3(32, 8)>>>(w2_w,   w2T,   FFz, Dz);

    // 1. fused LN (attn + ffn branches share mean/var)
    ln_kernel<<<TOK, 256>>>(x, aln_w, aln_b, fln_w, fln_b, nx, f);

    // 2. qkv = nx @ wqkv + b
    tc_gemm_kernel<<<dim3(3 * Dz / BN, TOK / BM), 256, SM_TOTAL>>>(
        nx, wqkvT, wqkv_b, nullptr, qkv, TOK, 3 * Dz, Dz, 0);

    // 3. per-head rms norm + rope + scale fold
    qkrope_kernel<<<TOK * Hz, 256>>>(qkv, fc, qn_w, kn_w);

    // 4. windowed FA2 attention -> y
    attn_mma_kernel<<<Bz * Hz * (Sz / 64), 128, AT_SMEM_BYTES>>>(qkv, y);

    // 5. h = y @ wo + b + x
    tc_gemm_kernel<<<dim3(Dz / BN, TOK / BM), 256, SM_TOTAL>>>(
        y, woT, wo_b, x, h, TOK, Dz, Dz, 0);

    // 6. ffn = gelu_exact(f @ w1 + b1)
    tc_gemm_kernel<<<dim3(FFz / BN, TOK / BM), 256, SM_TOTAL>>>(
        f, w1T, w1_b, nullptr, ffn, TOK, FFz, Dz, 1);

    // 7. out = ffn @ w2 + b2 + h
    tc_gemm_kernel<<<dim3(Dz / BN, TOK / BM), 256, SM_TOTAL>>>(
        ffn, w2T, w2_b, h, out, TOK, Dz, FFz, 0);
}

// round 9
// speedup vs baseline: 3.6070x; 1.0454x over previous
#include <cuda_runtime.h>
#include <cuda_bf16.h>
#include <math.h>
#include <stdint.h>

// ---------------- problem constants ----------------
#define Bz   2
#define Sz   2048
#define Dz   2048
#define Hz   16
#define HDz  128
#define RNz  32
#define FFz  4096
#define WINz 256
#define TOK  (Bz*Sz)          // 4096 tokens
#define EPSF 1e-5f
#define SCALEF 0.08838834764831845f   // 1/sqrt(128)

// ---------------- scratch (device globals; no allocation allowed) ----------------
__device__ float g_nx  [TOK*Dz];       // tf32-rounded
__device__ float g_f   [TOK*Dz];       // tf32-rounded
__device__ float g_qkv [TOK*3*Dz];     // q,k,v tf32-rounded after qkrope
__device__ float g_y   [TOK*Dz];       // tf32-rounded
__device__ float g_h   [TOK*Dz];       // fp32 (residual stream)
__device__ float g_ffn [TOK*FFz];      // tf32-rounded
// transposed weights, tf32-rounded ([N,K] K-major)
__device__ float g_wqkvT[3*Dz*Dz];
__device__ float g_woT  [Dz*Dz];
__device__ float g_w1T  [FFz*Dz];
__device__ float g_w2T  [Dz*FFz];

// ======================= helpers =======================
__device__ __forceinline__ uint32_t smem_u32(const void* p) {
    uint32_t a;
    asm("{ .reg .u64 t; cvta.to.shared.u64 t, %1; cvt.u32.u64 %0, t; }" : "=r"(a) : "l"(p));
    return a;
}
#define CP_ASYNC16(smem, gptr) \
    asm volatile("cp.async.cg.shared.global [%0], [%1], 16;" :: "r"(smem), "l"(gptr))
#define CP_COMMIT()  asm volatile("cp.async.commit_group;" ::: "memory")
#define CP_WAIT0()   asm volatile("cp.async.wait_group 0;" ::: "memory")
#define CP_WAIT1()   asm volatile("cp.async.wait_group 1;" ::: "memory")
#define CP_WAIT2()   asm volatile("cp.async.wait_group 2;" ::: "memory")

__device__ __forceinline__ uint32_t f2tf32(float x) {
    uint32_t r;
    asm("cvt.rna.tf32.f32 %0, %1;" : "=r"(r) : "f"(x));
    return r;
}
__device__ __forceinline__ float tf32v(float x) {            // value rounded to tf32
    return __uint_as_float(f2tf32(x));
}
__device__ __forceinline__ void mma_tf32(float& c0, float& c1, float& c2, float& c3,
                                         uint32_t a0, uint32_t a1, uint32_t a2, uint32_t a3,
                                         uint32_t b0, uint32_t b1) {
    asm volatile(
        "mma.sync.aligned.m16n8k8.row.col.f32.tf32.tf32.f32 "
        "{%0,%1,%2,%3}, {%4,%5,%6,%7}, {%8,%9}, {%0,%1,%2,%3};"
        : "+f"(c0), "+f"(c1), "+f"(c2), "+f"(c3)
        : "r"(a0), "r"(a1), "r"(a2), "r"(a3), "r"(b0), "r"(b1));
}

// ======================= weight transpose (+tf32 round): W[Kd,Nd] -> Wt[Nd,Kd] =======================
__global__ void transpose_kernel(const float* __restrict__ W, float* __restrict__ Wt,
                                 int Kd, int Nd) {
    __shared__ float t[32][33];
    int n0 = blockIdx.x * 32, k0 = blockIdx.y * 32;
    #pragma unroll
    for (int i = threadIdx.y; i < 32; i += 8)
        t[i][threadIdx.x] = W[(size_t)(k0 + i) * Nd + n0 + threadIdx.x];
    __syncthreads();
    #pragma unroll
    for (int i = threadIdx.y; i < 32; i += 8)
        Wt[(size_t)(n0 + i) * Kd + k0 + threadIdx.x] = tf32v(t[threadIdx.x][i]);
}

// ======================= tf32 mma.sync GEMM (inputs pre-rounded to tf32) =======================
#define BM 128
#define BN 128
#define BK 32
#define APAD 4
#define ASTR (BK + APAD)                 // 36 floats = 144 B
#define TILE_FLOATS (BM * ASTR)          // 4608
#define STAGE_FLOATS (2 * TILE_FLOATS)   // 9216
#define STAGES 3
#define SM_TOTAL (STAGES * STAGE_FLOATS * 4)   // 110592 bytes

__global__ __launch_bounds__(256, 2)
void tc_gemm_kernel(const float* __restrict__ A, const float* __restrict__ Bt,
                    const float* __restrict__ bias, const float* __restrict__ res,
                    float* __restrict__ C, int M, int N, int K, int do_gelu, int cvt_out)
{
    extern __shared__ float smem[];
    const uint32_t sm0 = smem_u32(smem);
    const int tid  = threadIdx.x;
    const int wid  = tid >> 5;
    const int lane = tid & 31;
    const int gid  = lane >> 2;
    const int tig  = lane & 3;
    const int wm   = wid >> 2;
    const int wn   = wid & 3;
    const int row0 = blockIdx.y * BM;
    const int col0 = blockIdx.x * BN;

    float acc[4][4][4];
    #pragma unroll
    for (int mi = 0; mi < 4; mi++)
        #pragma unroll
        for (int ni = 0; ni < 4; ni++)
            #pragma unroll
            for (int e = 0; e < 4; e++) acc[mi][ni][e] = 0.f;

    const int niter = K >> 5;

    auto load_stage = [&](int buf, int iter) {
        const int k0 = iter << 5;
        const uint32_t sb = sm0 + (uint32_t)buf * (STAGE_FLOATS * 4);
        #pragma unroll
        for (int t = 0; t < 8; t++) {
            int c   = tid + t * 256;
            int isB = c >> 10;
            int cc  = c & 1023;
            int row = cc >> 3, col8 = cc & 7;
            const float* g = (isB ? (Bt + (size_t)(col0 + row) * K)
                                  : (A  + (size_t)(row0 + row) * K)) + k0 + col8 * 4;
            uint32_t s = sb + (uint32_t)((isB ? TILE_FLOATS : 0) + row * ASTR + col8 * 4) * 4;
            CP_ASYNC16(s, g);
        }
        CP_COMMIT();
    };

    if (0 < niter) { load_stage(0, 0); }
    if (1 < niter) { load_stage(1, 1); }

    for (int i = 0; i < niter; i++) {
        if (i + 2 < niter) load_stage((i + 2) % STAGES, i + 2);
        if (i + 2 < niter)      { CP_WAIT2(); }
        else if (i + 1 < niter) { CP_WAIT1(); }
        else                    { CP_WAIT0(); }
        __syncthreads();

        const uint32_t* sA = (const uint32_t*)(smem + (i % STAGES) * STAGE_FLOATS);
        const uint32_t* sB = sA + TILE_FLOATS;
        const uint32_t* pa = sA + (wm * 64 + gid) * ASTR + tig;
        const uint32_t* pb = sB + (wn * 32 + gid) * ASTR + tig;

        #pragma unroll
        for (int ks = 0; ks < 4; ks++) {
            const int ko = ks * 8;
            uint32_t bfr[4][2];
            #pragma unroll
            for (int ni = 0; ni < 4; ni++) {
                const uint32_t* p = pb + ni * 8 * ASTR + ko;
                bfr[ni][0] = p[0];
                bfr[ni][1] = p[4];
            }
            #pragma unroll
            for (int mi = 0; mi < 4; mi++) {
                const uint32_t* p = pa + mi * 16 * ASTR + ko;
                uint32_t a0 = p[0];
                uint32_t a1 = p[8 * ASTR];
                uint32_t a2 = p[4];
                uint32_t a3 = p[8 * ASTR + 4];
                #pragma unroll
                for (int ni = 0; ni < 4; ni++)
                    mma_tf32(acc[mi][ni][0], acc[mi][ni][1], acc[mi][ni][2], acc[mi][ni][3],
                             a0, a1, a2, a3, bfr[ni][0], bfr[ni][1]);
            }
        }
        __syncthreads();
    }

    #pragma unroll
    for (int mi = 0; mi < 4; mi++) {
        #pragma unroll
        for (int half = 0; half < 2; half++) {
            const size_t r = (size_t)(row0 + wm * 64 + mi * 16 + gid + half * 8);
            #pragma unroll
            for (int ni = 0; ni < 4; ni++) {
                const int cc = col0 + wn * 32 + ni * 8 + tig * 2;
                float v0 = acc[mi][ni][half * 2 + 0] + bias[cc];
                float v1 = acc[mi][ni][half * 2 + 1] + bias[cc + 1];
                if (do_gelu) {
                    v0 = 0.5f * v0 * (1.f + erff(v0 * 0.70710678118654752f));
                    v1 = 0.5f * v1 * (1.f + erff(v1 * 0.70710678118654752f));
                }
                if (res) {
                    float2 rr = *(const float2*)&res[r * N + cc];
                    v0 += rr.x; v1 += rr.y;
                }
                if (cvt_out) { v0 = tf32v(v0); v1 = tf32v(v1); }
                *(float2*)&C[r * N + cc] = make_float2(v0, v1);
            }
        }
    }
}

// ---------------- fused double LayerNorm (tf32-rounded outputs) ----------------
__global__ void ln_kernel(const float* __restrict__ x,
                          const float* __restrict__ aw, const float* __restrict__ ab,
                          const float* __restrict__ fw, const float* __restrict__ fb,
                          float* __restrict__ nx, float* __restrict__ f)
{
    int row = blockIdx.x;
    int tid = threadIdx.x;
    const float4* xr = (const float4*)(x + (size_t)row * Dz);
    float4 a = xr[tid];
    float4 b = xr[tid + 256];
    float s  = a.x + a.y + a.z + a.w + b.x + b.y + b.z + b.w;
    float ss = a.x*a.x + a.y*a.y + a.z*a.z + a.w*a.w
             + b.x*b.x + b.y*b.y + b.z*b.z + b.w*b.w;
    #pragma unroll
    for (int o = 16; o; o >>= 1) {
        s  += __shfl_xor_sync(0xffffffffu, s,  o);
        ss += __shfl_xor_sync(0xffffffffu, ss, o);
    }
    __shared__ float r1[8], r2[8];
    __shared__ float mv[2];
    int wid = tid >> 5;
    if ((tid & 31) == 0) { r1[wid] = s; r2[wid] = ss; }
    __syncthreads();
    if (tid == 0) {
        float S = 0.f, SS = 0.f;
        #pragma unroll
        for (int i = 0; i < 8; i++) { S += r1[i]; SS += r2[i]; }
        float m   = S * (1.f / Dz);
        float var = SS * (1.f / Dz) - m * m;
        mv[0] = m;
        mv[1] = rsqrtf(var + EPSF);
    }
    __syncthreads();
    float m = mv[0], r = mv[1];

    float4* nxr = (float4*)(nx + (size_t)row * Dz);
    float4* fr  = (float4*)(f  + (size_t)row * Dz);
    const float4* aw4 = (const float4*)aw;  const float4* ab4 = (const float4*)ab;
    const float4* fw4 = (const float4*)fw;  const float4* fb4 = (const float4*)fb;
    #pragma unroll
    for (int e = 0; e < 2; e++) {
        int slot = tid + e * 256;
        float4 v = (e == 0) ? a : b;
        float4 w1 = aw4[slot], b1 = ab4[slot], w2 = fw4[slot], b2 = fb4[slot];
        float4 o1, o2;
        o1.x = tf32v((v.x - m) * r * w1.x + b1.x);  o2.x = tf32v((v.x - m) * r * w2.x + b2.x);
        o1.y = tf32v((v.y - m) * r * w1.y + b1.y);  o2.y = tf32v((v.y - m) * r * w2.y + b2.y);
        o1.z = tf32v((v.z - m) * r * w1.z + b1.z);  o2.z = tf32v((v.z - m) * r * w2.z + b2.z);
        o1.w = tf32v((v.w - m) * r * w1.w + b1.w);  o2.w = tf32v((v.w - m) * r * w2.w + b2.w);
        nxr[slot] = o1;
        fr[slot]  = o2;
    }
}

// ---------------- per-head RMS norm + RoPE + q scaling + tf32 round (q,k,v), in place ----------------
// 384 threads: [0,128) q, [128,256) k, [256,384) v (v only tf32-rounded)
__global__ void qkrope_kernel(float* __restrict__ qkv, const float* __restrict__ fc,
                              const float* __restrict__ qn_w, const float* __restrict__ kn_w)
{
    int blk   = blockIdx.x;
    int token = blk >> 4;
    int h     = blk & 15;
    int s     = token & (Sz - 1);
    int sel   = threadIdx.x >> 7;       // 0=q, 1=k, 2=v
    int d     = threadIdx.x & 127;
    float* ptr = qkv + (size_t)token * (3 * Dz) + sel * Dz + h * HDz;
    float v = ptr[d];
    float ss = v * v;
    #pragma unroll
    for (int o = 16; o; o >>= 1) ss += __shfl_xor_sync(0xffffffffu, ss, o);
    __shared__ float red[12];
    __shared__ float rstd_s[2];
    int wid = threadIdx.x >> 5;
    if ((threadIdx.x & 31) == 0) red[wid] = ss;
    __syncthreads();
    if (d == 0 && sel < 2) {
        float t = red[sel * 4] + red[sel * 4 + 1] + red[sel * 4 + 2] + red[sel * 4 + 3];
        rstd_s[sel] = rsqrtf(t * (1.f / HDz) + EPSF);
    }
    __syncthreads();
    if (sel == 2) {                     // v: just tf32-round in place
        ptr[d] = tf32v(v);
        return;
    }
    float rstd = rstd_s[sel];
    float w = sel ? kn_w[d] : qn_w[d];
    float nv = v * rstd * w;
    if (d < RNz) {
        int j = d >> 1;
        float c  = fc[(s * 16 + j) * 2];
        float sn = fc[(s * 16 + j) * 2 + 1];
        float a = __shfl_sync(0xffffffffu, nv, j);
        float b = __shfl_sync(0xffffffffu, nv, j + 16);
        nv = (d & 1) ? (b * c + a * sn) : (a * c - b * sn);
    }
    if (sel == 0) nv *= SCALEF;
    ptr[d] = tf32v(nv);
}

// ======================= FA2-style windowed attention (tf32 mma, pre-rounded K/V) =======================
#define AT_CK 32
#define KSTR 132
#define VSTR 136
#define AT_K_OFF(buf) ((buf) * (AT_CK * KSTR))
#define AT_V_OFF(buf) (2 * AT_CK * KSTR + (buf) * (AT_CK * VSTR))
#define AT_SMEM_FLOATS (2 * AT_CK * KSTR + 2 * AT_CK * VSTR)   // 17152
#define AT_SMEM_BYTES  (AT_SMEM_FLOATS * 4)                     // 68608

__global__ __launch_bounds__(128, 2)
void attn_mma_kernel(const float* __restrict__ qkv, float* __restrict__ y)
{
    extern __shared__ float sm[];
    const uint32_t sm0 = smem_u32(sm);
    const int tid  = threadIdx.x;
    const int wi   = tid >> 5;
    const int lane = tid & 31;
    const int gid  = lane >> 2;
    const int tig  = lane & 3;
    const int qb0  = (blockIdx.x & 31) << 6;
    const int h    = (blockIdx.x >> 5) & 15;
    const int b    = blockIdx.x >> 9;
    const int qw   = qb0 + wi * 16;

    // ---- Q fragments (already tf32 bit patterns in gmem) ----
    uint32_t qf[16][4];
    {
        const float* q0 = qkv + (size_t)(b * Sz + qw + gid) * (3 * Dz) + h * HDz;
        const float* q1 = q0 + (size_t)8 * (3 * Dz);
        #pragma unroll
        for (int kg = 0; kg < 16; kg++) {
            qf[kg][0] = __float_as_uint(q0[kg * 8 + tig]);
            qf[kg][1] = __float_as_uint(q1[kg * 8 + tig]);
            qf[kg][2] = __float_as_uint(q0[kg * 8 + tig + 4]);
            qf[kg][3] = __float_as_uint(q1[kg * 8 + tig + 4]);
        }
    }

    float o[16][4];
    #pragma unroll
    for (int dt = 0; dt < 16; dt++)
        #pragma unroll
        for (int e = 0; e < 4; e++) o[dt][e] = 0.f;
    float m0 = -1e30f, m1 = -1e30f, l0 = 0.f, l1 = 0.f;

    int cs = qb0 - (WINz - 1); if (cs < 0) cs = 0;
    cs &= ~31;
    const int nc = ((qb0 + 63 - cs) >> 5) + 1;

    auto load_chunk = [&](int buf, int jc) {
        #pragma unroll
        for (int i = 0; i < 8; i++) {
            int fidx = i * 128 + tid;
            int row = fidx >> 5, c4 = fidx & 31;
            const float* gk = qkv + (size_t)(b * Sz + jc + row) * (3 * Dz) + Dz + h * HDz + c4 * 4;
            CP_ASYNC16(sm0 + (uint32_t)(AT_K_OFF(buf) + row * KSTR + c4 * 4) * 4, gk);
        }
        #pragma unroll
        for (int i = 0; i < 8; i++) {
            int fidx = i * 128 + tid;
            int row = fidx >> 5, c4 = fidx & 31;
            const float* gv = qkv + (size_t)(b * Sz + jc + row) * (3 * Dz) + 2 * Dz + h * HDz + c4 * 4;
            CP_ASYNC16(sm0 + (uint32_t)(AT_V_OFF(buf) + row * VSTR + c4 * 4) * 4, gv);
        }
        CP_COMMIT();
    };

    load_chunk(0, cs);

    for (int c = 0; c < nc; c++) {
        const int jc  = cs + c * 32;
        const int buf = c & 1;
        if (c + 1 < nc) { load_chunk((c + 1) & 1, jc + 32); CP_WAIT1(); }
        else            { CP_WAIT0(); }
        __syncthreads();

        const bool act = (jc <= qw + 15) && (jc + 31 >= qw - (WINz - 1));
        if (act) {
            const uint32_t* Ks = (const uint32_t*)(sm + AT_K_OFF(buf));
            const uint32_t* Vs = (const uint32_t*)(sm + AT_V_OFF(buf));

            // ---- scores ----
            float sc[4][4];
            #pragma unroll
            for (int ng = 0; ng < 4; ng++)
                #pragma unroll
                for (int e = 0; e < 4; e++) sc[ng][e] = 0.f;
            #pragma unroll
            for (int kg = 0; kg < 16; kg++) {
                #pragma unroll
                for (int ng = 0; ng < 4; ng++) {
                    const uint32_t* kp = Ks + (ng * 8 + gid) * KSTR + kg * 8 + tig;
                    mma_tf32(sc[ng][0], sc[ng][1], sc[ng][2], sc[ng][3],
                             qf[kg][0], qf[kg][1], qf[kg][2], qf[kg][3],
                             kp[0], kp[4]);
                }
            }

            // ---- online softmax ----
            const int q0r = qw + gid, q1r = qw + gid + 8;
            float smax0 = -1e30f, smax1 = -1e30f;
            #pragma unroll
            for (int ng = 0; ng < 4; ng++) {
                int j0 = jc + ng * 8 + tig * 2;
                smax0 = fmaxf(smax0, ((unsigned)(q0r - j0)     < 256u) ? sc[ng][0] : -1e30f);
                smax0 = fmaxf(smax0, ((unsigned)(q0r - j0 - 1) < 256u) ? sc[ng][1] : -1e30f);
                smax1 = fmaxf(smax1, ((unsigned)(q1r - j0)     < 256u) ? sc[ng][2] : -1e30f);
                smax1 = fmaxf(smax1, ((unsigned)(q1r - j0 - 1) < 256u) ? sc[ng][3] : -1e30f);
            }
            smax0 = fmaxf(smax0, __shfl_xor_sync(0xffffffffu, smax0, 1));
            smax0 = fmaxf(smax0, __shfl_xor_sync(0xffffffffu, smax0, 2));
            smax1 = fmaxf(smax1, __shfl_xor_sync(0xffffffffu, smax1, 1));
            smax1 = fmaxf(smax1, __shfl_xor_sync(0xffffffffu, smax1, 2));
            float m0n = fmaxf(m0, smax0), m1n = fmaxf(m1, smax1);
            float cr0 = __expf(m0 - m0n), cr1 = __expf(m1 - m1n);
            m0 = m0n; m1 = m1n;

            float ps0 = 0.f, ps1 = 0.f;
            #pragma unroll
            for (int ng = 0; ng < 4; ng++) {
                int j0 = jc + ng * 8 + tig * 2;
                float e;
                e = ((unsigned)(q0r - j0)     < 256u) ? __expf(sc[ng][0] - m0) : 0.f;
                sc[ng][0] = e; ps0 += e;
                e = ((unsigned)(q0r - j0 - 1) < 256u) ? __expf(sc[ng][1] - m0) : 0.f;
                sc[ng][1] = e; ps0 += e;
                e = ((unsigned)(q1r - j0)     < 256u) ? __expf(sc[ng][2] - m1) : 0.f;
                sc[ng][2] = e; ps1 += e;
                e = ((unsigned)(q1r - j0 - 1) < 256u) ? __expf(sc[ng][3] - m1) : 0.f;
                sc[ng][3] = e; ps1 += e;
            }
            ps0 += __shfl_xor_sync(0xffffffffu, ps0, 1);
            ps0 += __shfl_xor_sync(0xffffffffu, ps0, 2);
            ps1 += __shfl_xor_sync(0xffffffffu, ps1, 1);
            ps1 += __shfl_xor_sync(0xffffffffu, ps1, 2);
            l0 = l0 * cr0 + ps0;
            l1 = l1 * cr1 + ps1;

            #pragma unroll
            for (int dt = 0; dt < 16; dt++) {
                o[dt][0] *= cr0; o[dt][1] *= cr0;
                o[dt][2] *= cr1; o[dt][3] *= cr1;
            }

            // ---- permute P (C-layout -> A-fragment layout) ----
            uint32_t af[4][4];
            const int src  = (lane & ~3) | (tig >> 1);
            const int src2 = src + 2;
            #pragma unroll
            for (int ng = 0; ng < 4; ng++) {
                float v0 = __shfl_sync(0xffffffffu, sc[ng][0], src);
                float v1 = __shfl_sync(0xffffffffu, sc[ng][1], src);
                float v2 = __shfl_sync(0xffffffffu, sc[ng][2], src);
                float v3 = __shfl_sync(0xffffffffu, sc[ng][3], src);
                float w0 = __shfl_sync(0xffffffffu, sc[ng][0], src2);
                float w1 = __shfl_sync(0xffffffffu, sc[ng][1], src2);
                float w2 = __shfl_sync(0xffffffffu, sc[ng][2], src2);
                float w3 = __shfl_sync(0xffffffffu, sc[ng][3], src2);
                af[ng][0] = f2tf32((tig & 1) ? v1 : v0);
                af[ng][1] = f2tf32((tig & 1) ? v3 : v2);
                af[ng][2] = f2tf32((tig & 1) ? w1 : w0);
                af[ng][3] = f2tf32((tig & 1) ? w3 : w2);
            }

            // ---- PV ----
            #pragma unroll
            for (int dt = 0; dt < 16; dt++) {
                #pragma unroll
                for (int ng = 0; ng < 4; ng++) {
                    const uint32_t* vp = Vs + (ng * 8 + tig) * VSTR + dt * 8 + gid;
                    mma_tf32(o[dt][0], o[dt][1], o[dt][2], o[dt][3],
                             af[ng][0], af[ng][1], af[ng][2], af[ng][3],
                             vp[0], vp[4 * VSTR]);
                }
            }
        }
        __syncthreads();
    }

    // ---- write normalized output (tf32-rounded: consumed by Wo GEMM) ----
    const float i0 = 1.f / l0, i1 = 1.f / l1;
    float* y0 = y + (size_t)(b * Sz + qw + gid) * Dz + h * HDz;
    float* y1 = y0 + (size_t)8 * Dz;
    #pragma unroll
    for (int dt = 0; dt < 16; dt++) {
        *(float2*)(y0 + dt * 8 + tig * 2) = make_float2(tf32v(o[dt][0] * i0), tf32v(o[dt][1] * i0));
        *(float2*)(y1 + dt * 8 + tig * 2) = make_float2(tf32v(o[dt][2] * i1), tf32v(o[dt][3] * i1));
    }
}

// ---------------- launch ----------------
extern "C" void kernel_launch(void* const* d_in, const int* in_sizes, int n_in,
                              void* d_out, int out_size)
{
    const float* x      = (const float*)d_in[0];
    const float* fc     = (const float*)d_in[1];
    // d_in[2] = mask (implicit: causal sliding window of 256)
    const float* wqkv_w = (const float*)d_in[3];
    const float* wqkv_b = (const float*)d_in[4];
    const float* wo_w   = (const float*)d_in[5];
    const float* wo_b   = (const float*)d_in[6];
    const float* qn_w   = (const float*)d_in[7];
    const float* kn_w   = (const float*)d_in[8];
    const float* aln_w  = (const float*)d_in[9];
    const float* aln_b  = (const float*)d_in[10];
    const float* fln_w  = (const float*)d_in[11];
    const float* fln_b  = (const float*)d_in[12];
    const float* w1_w   = (const float*)d_in[13];
    const float* w1_b   = (const float*)d_in[14];
    const float* w2_w   = (const float*)d_in[15];
    const float* w2_b   = (const float*)d_in[16];
    float* out = (float*)d_out;

    float *nx, *f, *qkv, *y, *h, *ffn, *wqkvT, *woT, *w1T, *w2T;
    cudaGetSymbolAddress((void**)&nx,    g_nx);
    cudaGetSymbolAddress((void**)&f,     g_f);
    cudaGetSymbolAddress((void**)&qkv,   g_qkv);
    cudaGetSymbolAddress((void**)&y,     g_y);
    cudaGetSymbolAddress((void**)&h,     g_h);
    cudaGetSymbolAddress((void**)&ffn,   g_ffn);
    cudaGetSymbolAddress((void**)&wqkvT, g_wqkvT);
    cudaGetSymbolAddress((void**)&woT,   g_woT);
    cudaGetSymbolAddress((void**)&w1T,   g_w1T);
    cudaGetSymbolAddress((void**)&w2T,   g_w2T);

    static int smem_cfg = 0;
    if (!smem_cfg) {
        cudaFuncSetAttribute(tc_gemm_kernel,
                             cudaFuncAttributeMaxDynamicSharedMemorySize, SM_TOTAL);
        cudaFuncSetAttribute(attn_mma_kernel,
                             cudaFuncAttributeMaxDynamicSharedMemorySize, AT_SMEM_BYTES);
        smem_cfg = 1;
    }

    // 0. weight transposes + tf32 round (W[K,N] -> Wt[N,K])
    transpose_kernel<<<dim3(3 * Dz / 32, Dz / 32), dim3(32, 8)>>>(wqkv_w, wqkvT, Dz, 3 * Dz);
    transpose_kernel<<<dim3(Dz / 32,     Dz / 32), dim3(32, 8)>>>(wo_w,   woT,   Dz, Dz);
    transpose_kernel<<<dim3(FFz / 32,    Dz / 32), dim3(32, 8)>>>(w1_w,   w1T,   Dz, FFz);
    transpose_kernel<<<dim3(Dz / 32,    FFz / 32), dim3(32, 8)>>>(w2_w,   w2T,   FFz, Dz);

    // 1. fused LN (tf32-rounded outputs)
    ln_kernel<<<TOK, 256>>>(x, aln_w, aln_b, fln_w, fln_b, nx, f);

    // 2. qkv = nx @ wqkv + b
    tc_gemm_kernel<<<dim3(3 * Dz / BN, TOK / BM), 256, SM_TOTAL>>>(
        nx, wqkvT, wqkv_b, nullptr, qkv, TOK, 3 * Dz, Dz, 0, 0);

    // 3. per-head rms norm + rope + scale fold + tf32 round (q,k,v)
    qkrope_kernel<<<TOK * Hz, 384>>>(qkv, fc, qn_w, kn_w);

    // 4. windowed FA2 attention -> y (tf32-rounded)
    attn_mma_kernel<<<Bz * Hz * (Sz / 64), 128, AT_SMEM_BYTES>>>(qkv, y);

    // 5. h = y @ wo + b + x   (fp32 residual stream)
    tc_gemm_kernel<<<dim3(Dz / BN, TOK / BM), 256, SM_TOTAL>>>(
        y, woT, wo_b, x, h, TOK, Dz, Dz, 0, 0);

    // 6. ffn = gelu_exact(f @ w1 + b1)  (tf32-rounded: consumed by GEMM 7)
    tc_gemm_kernel<<<dim3(FFz / BN, TOK / BM), 256, SM_TOTAL>>>(
        f, w1T, w1_b, nullptr, ffn, TOK, FFz, Dz, 1, 1);

    // 7. out = ffn @ w2 + b2 + h  (full fp32 output)
    tc_gemm_kernel<<<dim3(Dz / BN, TOK / BM), 256, SM_TOTAL>>>(
        ffn, w2T, w2_b, h, out, TOK, Dz, FFz, 0, 0);
}

// round 10
// speedup vs baseline: 3.8443x; 1.0658x over previous
#include <cuda_runtime.h>
#include <cuda_bf16.h>
#include <math.h>
#include <stdint.h>

// ---------------- problem constants ----------------
#define Bz   2
#define Sz   2048
#define Dz   2048
#define Hz   16
#define HDz  128
#define RNz  32
#define FFz  4096
#define WINz 256
#define TOK  (Bz*Sz)          // 4096 tokens
#define EPSF 1e-5f
#define SCALEF 0.08838834764831845f   // 1/sqrt(128)

// ---------------- scratch (device globals; no allocation allowed) ----------------
__device__ float g_nx  [TOK*Dz];       // tf32-rounded
__device__ float g_f   [TOK*Dz];       // tf32-rounded
__device__ float g_qkv [TOK*3*Dz];     // q,k,v tf32-rounded after qkrope
__device__ float g_y   [TOK*Dz];       // tf32-rounded
__device__ float g_h   [TOK*Dz];       // fp32 (residual stream)
__device__ float g_ffn [TOK*FFz];      // tf32-rounded

// ======================= helpers =======================
__device__ __forceinline__ uint32_t smem_u32(const void* p) {
    uint32_t a;
    asm("{ .reg .u64 t; cvta.to.shared.u64 t, %1; cvt.u32.u64 %0, t; }" : "=r"(a) : "l"(p));
    return a;
}
#define CP_ASYNC16(smem, gptr) \
    asm volatile("cp.async.cg.shared.global [%0], [%1], 16;" :: "r"(smem), "l"(gptr))
#define CP_COMMIT()  asm volatile("cp.async.commit_group;" ::: "memory")
#define CP_WAIT0()   asm volatile("cp.async.wait_group 0;" ::: "memory")
#define CP_WAIT1()   asm volatile("cp.async.wait_group 1;" ::: "memory")
#define CP_WAIT2()   asm volatile("cp.async.wait_group 2;" ::: "memory")

__device__ __forceinline__ uint32_t f2tf32(float x) {
    uint32_t r;
    asm("cvt.rna.tf32.f32 %0, %1;" : "=r"(r) : "f"(x));
    return r;
}
__device__ __forceinline__ float tf32v(float x) {
    return __uint_as_float(f2tf32(x));
}
__device__ __forceinline__ void mma_tf32(float& c0, float& c1, float& c2, float& c3,
                                         uint32_t a0, uint32_t a1, uint32_t a2, uint32_t a3,
                                         uint32_t b0, uint32_t b1) {
    asm volatile(
        "mma.sync.aligned.m16n8k8.row.col.f32.tf32.tf32.f32 "
        "{%0,%1,%2,%3}, {%4,%5,%6,%7}, {%8,%9}, {%0,%1,%2,%3};"
        : "+f"(c0), "+f"(c1), "+f"(c2), "+f"(c3)
        : "r"(a0), "r"(a1), "r"(a2), "r"(a3), "r"(b0), "r"(b1));
}

// ======================= tf32 mma.sync GEMM v2 =======================
// C[M,N] = A[M,K] @ W[K,N]  (+bias, +gelu?, +res?)
// A pre-rounded to tf32; W raw fp32 (rounded at fragment load).
// CTA 128x128, 128 threads = 4 warps (2x2), warp tile 64x64, BK=32, 3-stage cp.async.
#define BM 128
#define BN 128
#define BK 32
#define ASTR 36                          // A smem row stride (bank perm: 4*gid+tig)
#define BSTR 136                         // B smem row stride (bank perm: 8*tig+gid)
#define A_FLOATS (BM * ASTR)             // 4608
#define B_FLOATS (BK * BSTR)             // 4352
#define STG_FLOATS (A_FLOATS + B_FLOATS) // 8960
#define STAGES 3
#define SM_TOTAL (STAGES * STG_FLOATS * 4)   // 107520 bytes

__global__ __launch_bounds__(128, 2)
void tc_gemm_kernel(const float* __restrict__ A, const float* __restrict__ W,
                    const float* __restrict__ bias, const float* __restrict__ res,
                    float* __restrict__ C, int M, int N, int K, int do_gelu, int cvt_out)
{
    extern __shared__ float smem[];
    const uint32_t sm0 = smem_u32(smem);
    const int tid  = threadIdx.x;
    const int wid  = tid >> 5;
    const int lane = tid & 31;
    const int gid  = lane >> 2;
    const int tig  = lane & 3;
    const int wm   = wid >> 1;          // 0..1: 64-row slab
    const int wn   = wid & 1;           // 0..1: 64-col slab
    const int row0 = blockIdx.y * BM;
    const int col0 = blockIdx.x * BN;

    float acc[4][8][4];
    #pragma unroll
    for (int mi = 0; mi < 4; mi++)
        #pragma unroll
        for (int ni = 0; ni < 8; ni++)
            #pragma unroll
            for (int e = 0; e < 4; e++) acc[mi][ni][e] = 0.f;

    const int niter = K >> 5;

    // loader: 2048 16B-chunks per stage (1024 A + 1024 B), 16 per thread
    auto load_stage = [&](int buf, int iter) {
        const int k0 = iter << 5;
        const uint32_t sb = sm0 + (uint32_t)buf * (STG_FLOATS * 4);
        #pragma unroll
        for (int t = 0; t < 16; t++) {
            int c = tid + t * 128;
            const float* g;
            uint32_t s;
            if (c < 1024) {                       // A: 128 rows x 8 float4
                int row = c >> 3, col8 = c & 7;
                g = A + (size_t)(row0 + row) * K + k0 + col8 * 4;
                s = sb + (uint32_t)(row * ASTR + col8 * 4) * 4;
            } else {                              // B: 32 k-rows x 32 float4 (N-contig)
                int cc = c - 1024;
                int row = cc >> 5, c4 = cc & 31;
                g = W + (size_t)(k0 + row) * N + col0 + c4 * 4;
                s = sb + (uint32_t)(A_FLOATS + row * BSTR + c4 * 4) * 4;
            }
            CP_ASYNC16(s, g);
        }
        CP_COMMIT();
    };

    if (0 < niter) { load_stage(0, 0); }
    if (1 < niter) { load_stage(1, 1); }

    for (int i = 0; i < niter; i++) {
        if (i + 2 < niter) load_stage((i + 2) % STAGES, i + 2);
        if (i + 2 < niter)      { CP_WAIT2(); }
        else if (i + 1 < niter) { CP_WAIT1(); }
        else                    { CP_WAIT0(); }
        __syncthreads();

        const uint32_t* sA = (const uint32_t*)(smem + (i % STAGES) * STG_FLOATS);
        const float*    sB = (const float*)(sA + A_FLOATS);
        const uint32_t* pa = sA + (wm * 64 + gid) * ASTR + tig;
        const float*    pb = sB + tig * BSTR + wn * 64 + gid;

        #pragma unroll
        for (int ks = 0; ks < 4; ks++) {
            const int ko = ks * 8;
            uint32_t bfr[8][2];
            #pragma unroll
            for (int ni = 0; ni < 8; ni++) {
                const float* p = pb + ko * BSTR + ni * 8;
                bfr[ni][0] = f2tf32(p[0]);
                bfr[ni][1] = f2tf32(p[4 * BSTR]);
            }
            #pragma unroll
            for (int mi = 0; mi < 4; mi++) {
                const uint32_t* p = pa + mi * 16 * ASTR + ko;
                uint32_t a0 = p[0];
                uint32_t a1 = p[8 * ASTR];
                uint32_t a2 = p[4];
                uint32_t a3 = p[8 * ASTR + 4];
                #pragma unroll
                for (int ni = 0; ni < 8; ni++)
                    mma_tf32(acc[mi][ni][0], acc[mi][ni][1], acc[mi][ni][2], acc[mi][ni][3],
                             a0, a1, a2, a3, bfr[ni][0], bfr[ni][1]);
            }
        }
        __syncthreads();
    }

    // ---------------- epilogue ----------------
    #pragma unroll
    for (int mi = 0; mi < 4; mi++) {
        #pragma unroll
        for (int half = 0; half < 2; half++) {
            const size_t r = (size_t)(row0 + wm * 64 + mi * 16 + gid + half * 8);
            #pragma unroll
            for (int ni = 0; ni < 8; ni++) {
                const int cc = col0 + wn * 64 + ni * 8 + tig * 2;
                float v0 = acc[mi][ni][half * 2 + 0] + bias[cc];
                float v1 = acc[mi][ni][half * 2 + 1] + bias[cc + 1];
                if (do_gelu) {
                    v0 = 0.5f * v0 * (1.f + erff(v0 * 0.70710678118654752f));
                    v1 = 0.5f * v1 * (1.f + erff(v1 * 0.70710678118654752f));
                }
                if (res) {
                    float2 rr = *(const float2*)&res[r * N + cc];
                    v0 += rr.x; v1 += rr.y;
                }
                if (cvt_out) { v0 = tf32v(v0); v1 = tf32v(v1); }
                *(float2*)&C[r * N + cc] = make_float2(v0, v1);
            }
        }
    }
}

// ---------------- fused double LayerNorm (tf32-rounded outputs) ----------------
__global__ void ln_kernel(const float* __restrict__ x,
                          const float* __restrict__ aw, const float* __restrict__ ab,
                          const float* __restrict__ fw, const float* __restrict__ fb,
                          float* __restrict__ nx, float* __restrict__ f)
{
    int row = blockIdx.x;
    int tid = threadIdx.x;
    const float4* xr = (const float4*)(x + (size_t)row * Dz);
    float4 a = xr[tid];
    float4 b = xr[tid + 256];
    float s  = a.x + a.y + a.z + a.w + b.x + b.y + b.z + b.w;
    float ss = a.x*a.x + a.y*a.y + a.z*a.z + a.w*a.w
             + b.x*b.x + b.y*b.y + b.z*b.z + b.w*b.w;
    #pragma unroll
    for (int o = 16; o; o >>= 1) {
        s  += __shfl_xor_sync(0xffffffffu, s,  o);
        ss += __shfl_xor_sync(0xffffffffu, ss, o);
    }
    __shared__ float r1[8], r2[8];
    __shared__ float mv[2];
    int wid = tid >> 5;
    if ((tid & 31) == 0) { r1[wid] = s; r2[wid] = ss; }
    __syncthreads();
    if (tid == 0) {
        float S = 0.f, SS = 0.f;
        #pragma unroll
        for (int i = 0; i < 8; i++) { S += r1[i]; SS += r2[i]; }
        float m   = S * (1.f / Dz);
        float var = SS * (1.f / Dz) - m * m;
        mv[0] = m;
        mv[1] = rsqrtf(var + EPSF);
    }
    __syncthreads();
    float m = mv[0], r = mv[1];

    float4* nxr = (float4*)(nx + (size_t)row * Dz);
    float4* fr  = (float4*)(f  + (size_t)row * Dz);
    const float4* aw4 = (const float4*)aw;  const float4* ab4 = (const float4*)ab;
    const float4* fw4 = (const float4*)fw;  const float4* fb4 = (const float4*)fb;
    #pragma unroll
    for (int e = 0; e < 2; e++) {
        int slot = tid + e * 256;
        float4 v = (e == 0) ? a : b;
        float4 w1 = aw4[slot], b1 = ab4[slot], w2 = fw4[slot], b2 = fb4[slot];
        float4 o1, o2;
        o1.x = tf32v((v.x - m) * r * w1.x + b1.x);  o2.x = tf32v((v.x - m) * r * w2.x + b2.x);
        o1.y = tf32v((v.y - m) * r * w1.y + b1.y);  o2.y = tf32v((v.y - m) * r * w2.y + b2.y);
        o1.z = tf32v((v.z - m) * r * w1.z + b1.z);  o2.z = tf32v((v.z - m) * r * w2.z + b2.z);
        o1.w = tf32v((v.w - m) * r * w1.w + b1.w);  o2.w = tf32v((v.w - m) * r * w2.w + b2.w);
        nxr[slot] = o1;
        fr[slot]  = o2;
    }
}

// ---------------- per-head RMS norm + RoPE + q scaling + tf32 round (q,k,v), in place ----------------
__global__ void qkrope_kernel(float* __restrict__ qkv, const float* __restrict__ fc,
                              const float* __restrict__ qn_w, const float* __restrict__ kn_w)
{
    int blk   = blockIdx.x;
    int token = blk >> 4;
    int h     = blk & 15;
    int s     = token & (Sz - 1);
    int sel   = threadIdx.x >> 7;       // 0=q, 1=k, 2=v
    int d     = threadIdx.x & 127;
    float* ptr = qkv + (size_t)token * (3 * Dz) + sel * Dz + h * HDz;
    float v = ptr[d];
    float ss = v * v;
    #pragma unroll
    for (int o = 16; o; o >>= 1) ss += __shfl_xor_sync(0xffffffffu, ss, o);
    __shared__ float red[12];
    __shared__ float rstd_s[2];
    int wid = threadIdx.x >> 5;
    if ((threadIdx.x & 31) == 0) red[wid] = ss;
    __syncthreads();
    if (d == 0 && sel < 2) {
        float t = red[sel * 4] + red[sel * 4 + 1] + red[sel * 4 + 2] + red[sel * 4 + 3];
        rstd_s[sel] = rsqrtf(t * (1.f / HDz) + EPSF);
    }
    __syncthreads();
    if (sel == 2) {                     // v: just tf32-round in place
        ptr[d] = tf32v(v);
        return;
    }
    float rstd = rstd_s[sel];
    float w = sel ? kn_w[d] : qn_w[d];
    float nv = v * rstd * w;
    if (d < RNz) {
        int j = d >> 1;
        float c  = fc[(s * 16 + j) * 2];
        float sn = fc[(s * 16 + j) * 2 + 1];
        float a = __shfl_sync(0xffffffffu, nv, j);
        float b = __shfl_sync(0xffffffffu, nv, j + 16);
        nv = (d & 1) ? (b * c + a * sn) : (a * c - b * sn);
    }
    if (sel == 0) nv *= SCALEF;
    ptr[d] = tf32v(nv);
}

// ======================= FA2-style windowed attention (tf32 mma, pre-rounded K/V) =======================
#define AT_CK 32
#define KSTR 132
#define VSTR 136
#define AT_K_OFF(buf) ((buf) * (AT_CK * KSTR))
#define AT_V_OFF(buf) (2 * AT_CK * KSTR + (buf) * (AT_CK * VSTR))
#define AT_SMEM_FLOATS (2 * AT_CK * KSTR + 2 * AT_CK * VSTR)   // 17152
#define AT_SMEM_BYTES  (AT_SMEM_FLOATS * 4)                     // 68608

__global__ __launch_bounds__(128, 2)
void attn_mma_kernel(const float* __restrict__ qkv, float* __restrict__ y)
{
    extern __shared__ float sm[];
    const uint32_t sm0 = smem_u32(sm);
    const int tid  = threadIdx.x;
    const int wi   = tid >> 5;
    const int lane = tid & 31;
    const int gid  = lane >> 2;
    const int tig  = lane & 3;
    const int qb0  = (blockIdx.x & 31) << 6;
    const int h    = (blockIdx.x >> 5) & 15;
    const int b    = blockIdx.x >> 9;
    const int qw   = qb0 + wi * 16;

    uint32_t qf[16][4];
    {
        const float* q0 = qkv + (size_t)(b * Sz + qw + gid) * (3 * Dz) + h * HDz;
        const float* q1 = q0 + (size_t)8 * (3 * Dz);
        #pragma unroll
        for (int kg = 0; kg < 16; kg++) {
            qf[kg][0] = __float_as_uint(q0[kg * 8 + tig]);
            qf[kg][1] = __float_as_uint(q1[kg * 8 + tig]);
            qf[kg][2] = __float_as_uint(q0[kg * 8 + tig + 4]);
            qf[kg][3] = __float_as_uint(q1[kg * 8 + tig + 4]);
        }
    }

    float o[16][4];
    #pragma unroll
    for (int dt = 0; dt < 16; dt++)
        #pragma unroll
        for (int e = 0; e < 4; e++) o[dt][e] = 0.f;
    float m0 = -1e30f, m1 = -1e30f, l0 = 0.f, l1 = 0.f;

    int cs = qb0 - (WINz - 1); if (cs < 0) cs = 0;
    cs &= ~31;
    const int nc = ((qb0 + 63 - cs) >> 5) + 1;

    auto load_chunk = [&](int buf, int jc) {
        #pragma unroll
        for (int i = 0; i < 8; i++) {
            int fidx = i * 128 + tid;
            int row = fidx >> 5, c4 = fidx & 31;
            const float* gk = qkv + (size_t)(b * Sz + jc + row) * (3 * Dz) + Dz + h * HDz + c4 * 4;
            CP_ASYNC16(sm0 + (uint32_t)(AT_K_OFF(buf) + row * KSTR + c4 * 4) * 4, gk);
        }
        #pragma unroll
        for (int i = 0; i < 8; i++) {
            int fidx = i * 128 + tid;
            int row = fidx >> 5, c4 = fidx & 31;
            const float* gv = qkv + (size_t)(b * Sz + jc + row) * (3 * Dz) + 2 * Dz + h * HDz + c4 * 4;
            CP_ASYNC16(sm0 + (uint32_t)(AT_V_OFF(buf) + row * VSTR + c4 * 4) * 4, gv);
        }
        CP_COMMIT();
    };

    load_chunk(0, cs);

    for (int c = 0; c < nc; c++) {
        const int jc  = cs + c * 32;
        const int buf = c & 1;
        if (c + 1 < nc) { load_chunk((c + 1) & 1, jc + 32); CP_WAIT1(); }
        else            { CP_WAIT0(); }
        __syncthreads();

        const bool act = (jc <= qw + 15) && (jc + 31 >= qw - (WINz - 1));
        if (act) {
            const uint32_t* Ks = (const uint32_t*)(sm + AT_K_OFF(buf));
            const uint32_t* Vs = (const uint32_t*)(sm + AT_V_OFF(buf));

            float sc[4][4];
            #pragma unroll
            for (int ng = 0; ng < 4; ng++)
                #pragma unroll
                for (int e = 0; e < 4; e++) sc[ng][e] = 0.f;
            #pragma unroll
            for (int kg = 0; kg < 16; kg++) {
                #pragma unroll
                for (int ng = 0; ng < 4; ng++) {
                    const uint32_t* kp = Ks + (ng * 8 + gid) * KSTR + kg * 8 + tig;
                    mma_tf32(sc[ng][0], sc[ng][1], sc[ng][2], sc[ng][3],
                             qf[kg][0], qf[kg][1], qf[kg][2], qf[kg][3],
                             kp[0], kp[4]);
                }
            }

            const int q0r = qw + gid, q1r = qw + gid + 8;
            float smax0 = -1e30f, smax1 = -1e30f;
            #pragma unroll
            for (int ng = 0; ng < 4; ng++) {
                int j0 = jc + ng * 8 + tig * 2;
                smax0 = fmaxf(smax0, ((unsigned)(q0r - j0)     < 256u) ? sc[ng][0] : -1e30f);
                smax0 = fmaxf(smax0, ((unsigned)(q0r - j0 - 1) < 256u) ? sc[ng][1] : -1e30f);
                smax1 = fmaxf(smax1, ((unsigned)(q1r - j0)     < 256u) ? sc[ng][2] : -1e30f);
                smax1 = fmaxf(smax1, ((unsigned)(q1r - j0 - 1) < 256u) ? sc[ng][3] : -1e30f);
            }
            smax0 = fmaxf(smax0, __shfl_xor_sync(0xffffffffu, smax0, 1));
            smax0 = fmaxf(smax0, __shfl_xor_sync(0xffffffffu, smax0, 2));
            smax1 = fmaxf(smax1, __shfl_xor_sync(0xffffffffu, smax1, 1));
            smax1 = fmaxf(smax1, __shfl_xor_sync(0xffffffffu, smax1, 2));
            float m0n = fmaxf(m0, smax0), m1n = fmaxf(m1, smax1);
            float cr0 = __expf(m0 - m0n), cr1 = __expf(m1 - m1n);
            m0 = m0n; m1 = m1n;

            float ps0 = 0.f, ps1 = 0.f;
            #pragma unroll
            for (int ng = 0; ng < 4; ng++) {
                int j0 = jc + ng * 8 + tig * 2;
                float e;
                e = ((unsigned)(q0r - j0)     < 256u) ? __expf(sc[ng][0] - m0) : 0.f;
                sc[ng][0] = e; ps0 += e;
                e = ((unsigned)(q0r - j0 - 1) < 256u) ? __expf(sc[ng][1] - m0) : 0.f;
                sc[ng][1] = e; ps0 += e;
                e = ((unsigned)(q1r - j0)     < 256u) ? __expf(sc[ng][2] - m1) : 0.f;
                sc[ng][2] = e; ps1 += e;
                e = ((unsigned)(q1r - j0 - 1) < 256u) ? __expf(sc[ng][3] - m1) : 0.f;
                sc[ng][3] = e; ps1 += e;
            }
            ps0 += __shfl_xor_sync(0xffffffffu, ps0, 1);
            ps0 += __shfl_xor_sync(0xffffffffu, ps0, 2);
            ps1 += __shfl_xor_sync(0xffffffffu, ps1, 1);
            ps1 += __shfl_xor_sync(0xffffffffu, ps1, 2);
            l0 = l0 * cr0 + ps0;
            l1 = l1 * cr1 + ps1;

            #pragma unroll
            for (int dt = 0; dt < 16; dt++) {
                o[dt][0] *= cr0; o[dt][1] *= cr0;
                o[dt][2] *= cr1; o[dt][3] *= cr1;
            }

            uint32_t af[4][4];
            const int src  = (lane & ~3) | (tig >> 1);
            const int src2 = src + 2;
            #pragma unroll
            for (int ng = 0; ng < 4; ng++) {
                float v0 = __shfl_sync(0xffffffffu, sc[ng][0], src);
                float v1 = __shfl_sync(0xffffffffu, sc[ng][1], src);
                float v2 = __shfl_sync(0xffffffffu, sc[ng][2], src);
                float v3 = __shfl_sync(0xffffffffu, sc[ng][3], src);
                float w0 = __shfl_sync(0xffffffffu, sc[ng][0], src2);
                float w1 = __shfl_sync(0xffffffffu, sc[ng][1], src2);
                float w2 = __shfl_sync(0xffffffffu, sc[ng][2], src2);
                float w3 = __shfl_sync(0xffffffffu, sc[ng][3], src2);
                af[ng][0] = f2tf32((tig & 1) ? v1 : v0);
                af[ng][1] = f2tf32((tig & 1) ? v3 : v2);
                af[ng][2] = f2tf32((tig & 1) ? w1 : w0);
                af[ng][3] = f2tf32((tig & 1) ? w3 : w2);
            }

            #pragma unroll
            for (int dt = 0; dt < 16; dt++) {
                #pragma unroll
                for (int ng = 0; ng < 4; ng++) {
                    const uint32_t* vp = Vs + (ng * 8 + tig) * VSTR + dt * 8 + gid;
                    mma_tf32(o[dt][0], o[dt][1], o[dt][2], o[dt][3],
                             af[ng][0], af[ng][1], af[ng][2], af[ng][3],
                             vp[0], vp[4 * VSTR]);
                }
            }
        }
        __syncthreads();
    }

    const float i0 = 1.f / l0, i1 = 1.f / l1;
    float* y0 = y + (size_t)(b * Sz + qw + gid) * Dz + h * HDz;
    float* y1 = y0 + (size_t)8 * Dz;
    #pragma unroll
    for (int dt = 0; dt < 16; dt++) {
        *(float2*)(y0 + dt * 8 + tig * 2) = make_float2(tf32v(o[dt][0] * i0), tf32v(o[dt][1] * i0));
        *(float2*)(y1 + dt * 8 + tig * 2) = make_float2(tf32v(o[dt][2] * i1), tf32v(o[dt][3] * i1));
    }
}

// ---------------- launch ----------------
extern "C" void kernel_launch(void* const* d_in, const int* in_sizes, int n_in,
                              void* d_out, int out_size)
{
    const float* x      = (const float*)d_in[0];
    const float* fc     = (const float*)d_in[1];
    // d_in[2] = mask (implicit: causal sliding window of 256)
    const float* wqkv_w = (const float*)d_in[3];
    const float* wqkv_b = (const float*)d_in[4];
    const float* wo_w   = (const float*)d_in[5];
    const float* wo_b   = (const float*)d_in[6];
    const float* qn_w   = (const float*)d_in[7];
    const float* kn_w   = (const float*)d_in[8];
    const float* aln_w  = (const float*)d_in[9];
    const float* aln_b  = (const float*)d_in[10];
    const float* fln_w  = (const float*)d_in[11];
    const float* fln_b  = (const float*)d_in[12];
    const float* w1_w   = (const float*)d_in[13];
    const float* w1_b   = (const float*)d_in[14];
    const float* w2_w   = (const float*)d_in[15];
    const float* w2_b   = (const float*)d_in[16];
    float* out = (float*)d_out;

    float *nx, *f, *qkv, *y, *h, *ffn;
    cudaGetSymbolAddress((void**)&nx,  g_nx);
    cudaGetSymbolAddress((void**)&f,   g_f);
    cudaGetSymbolAddress((void**)&qkv, g_qkv);
    cudaGetSymbolAddress((void**)&y,   g_y);
    cudaGetSymbolAddress((void**)&h,   g_h);
    cudaGetSymbolAddress((void**)&ffn, g_ffn);

    static int smem_cfg = 0;
    if (!smem_cfg) {
        cudaFuncSetAttribute(tc_gemm_kernel,
                             cudaFuncAttributeMaxDynamicSharedMemorySize, SM_TOTAL);
        cudaFuncSetAttribute(attn_mma_kernel,
                             cudaFuncAttributeMaxDynamicSharedMemorySize, AT_SMEM_BYTES);
        smem_cfg = 1;
    }

    // 1. fused LN (tf32-rounded outputs)
    ln_kernel<<<TOK, 256>>>(x, aln_w, aln_b, fln_w, fln_b, nx, f);

    // 2. qkv = nx @ wqkv + b   (weights consumed in natural [K,N] layout)
    tc_gemm_kernel<<<dim3(3 * Dz / BN, TOK / BM), 128, SM_TOTAL>>>(
        nx, wqkv_w, wqkv_b, nullptr, qkv, TOK, 3 * Dz, Dz, 0, 0);

    // 3. per-head rms norm + rope + scale fold + tf32 round (q,k,v)
    qkrope_kernel<<<TOK * Hz, 384>>>(qkv, fc, qn_w, kn_w);

    // 4. windowed FA2 attention -> y (tf32-rounded)
    attn_mma_kernel<<<Bz * Hz * (Sz / 64), 128, AT_SMEM_BYTES>>>(qkv, y);

    // 5. h = y @ wo + b + x   (fp32 residual stream)
    tc_gemm_kernel<<<dim3(Dz / BN, TOK / BM), 128, SM_TOTAL>>>(
        y, wo_w, wo_b, x, h, TOK, Dz, Dz, 0, 0);

    // 6. ffn = gelu_exact(f @ w1 + b1)  (tf32-rounded: consumed by GEMM 7)
    tc_gemm_kernel<<<dim3(FFz / BN, TOK / BM), 128, SM_TOTAL>>>(
        f, w1_w, w1_b, nullptr, ffn, TOK, FFz, Dz, 1, 1);

    // 7. out = ffn @ w2 + b2 + h  (full fp32 output)
    tc_gemm_kernel<<<dim3(Dz / BN, TOK / BM), 128, SM_TOTAL>>>(
        ffn, w2_w, w2_b, h, out, TOK, Dz, FFz, 0, 0);
}

// round 11
// speedup vs baseline: 5.5169x; 1.4351x over previous
#include <cuda_runtime.h>
#include <cuda_fp16.h>
#include <cuda_bf16.h>
#include <math.h>
#include <stdint.h>

// ---------------- problem constants ----------------
#define Bz   2
#define Sz   2048
#define Dz   2048
#define Hz   16
#define HDz  128
#define RNz  32
#define FFz  4096
#define WINz 256
#define TOK  (Bz*Sz)          // 4096 tokens
#define EPSF 1e-5f
#define SCALEF 0.08838834764831845f   // 1/sqrt(128)

// ---------------- scratch (device globals; no allocation allowed) ----------------
__device__ __half  g_nx  [TOK*Dz];      // fp16 LN output (attn branch)
__device__ __half  g_f   [TOK*Dz];      // fp16 LN output (ffn branch)
__device__ float   g_qkv [TOK*3*Dz];    // fp32; q,k,v tf32-rounded after qkrope
__device__ __half  g_y   [TOK*Dz];      // fp16 attention output
__device__ float   g_h   [TOK*Dz];      // fp32 residual stream
__device__ __half  g_ffn [TOK*FFz];     // fp16 gelu(f@w1+b1)
// fp16 weights, k-pair-interleaved: Wh[kp][n] = half2(W[2kp][n], W[2kp+1][n])
__device__ __half2 g_wqkvH[(Dz/2)*3*Dz];
__device__ __half2 g_woH  [(Dz/2)*Dz];
__device__ __half2 g_w1H  [(Dz/2)*FFz];
__device__ __half2 g_w2H  [(FFz/2)*Dz];

// ======================= helpers =======================
__device__ __forceinline__ uint32_t smem_u32(const void* p) {
    uint32_t a;
    asm("{ .reg .u64 t; cvta.to.shared.u64 t, %1; cvt.u32.u64 %0, t; }" : "=r"(a) : "l"(p));
    return a;
}
#define CP_ASYNC16(smem, gptr) \
    asm volatile("cp.async.cg.shared.global [%0], [%1], 16;" :: "r"(smem), "l"(gptr))
#define CP_COMMIT()  asm volatile("cp.async.commit_group;" ::: "memory")
#define CP_WAIT0()   asm volatile("cp.async.wait_group 0;" ::: "memory")
#define CP_WAIT1()   asm volatile("cp.async.wait_group 1;" ::: "memory")
#define CP_WAIT2()   asm volatile("cp.async.wait_group 2;" ::: "memory")

__device__ __forceinline__ uint32_t f2tf32(float x) {
    uint32_t r;
    asm("cvt.rna.tf32.f32 %0, %1;" : "=r"(r) : "f"(x));
    return r;
}
__device__ __forceinline__ float tf32v(float x) {
    return __uint_as_float(f2tf32(x));
}
// tf32 mma (attention only)
__device__ __forceinline__ void mma_tf32(float& c0, float& c1, float& c2, float& c3,
                                         uint32_t a0, uint32_t a1, uint32_t a2, uint32_t a3,
                                         uint32_t b0, uint32_t b1) {
    asm volatile(
        "mma.sync.aligned.m16n8k8.row.col.f32.tf32.tf32.f32 "
        "{%0,%1,%2,%3}, {%4,%5,%6,%7}, {%8,%9}, {%0,%1,%2,%3};"
        : "+f"(c0), "+f"(c1), "+f"(c2), "+f"(c3)
        : "r"(a0), "r"(a1), "r"(a2), "r"(a3), "r"(b0), "r"(b1));
}
// fp16 mma (GEMMs)
__device__ __forceinline__ void mma_f16(float& c0, float& c1, float& c2, float& c3,
                                        uint32_t a0, uint32_t a1, uint32_t a2, uint32_t a3,
                                        uint32_t b0, uint32_t b1) {
    asm volatile(
        "mma.sync.aligned.m16n8k16.row.col.f32.f16.f16.f32 "
        "{%0,%1,%2,%3}, {%4,%5,%6,%7}, {%8,%9}, {%0,%1,%2,%3};"
        : "+f"(c0), "+f"(c1), "+f"(c2), "+f"(c3)
        : "r"(a0), "r"(a1), "r"(a2), "r"(a3), "r"(b0), "r"(b1));
}

// ======================= weight fp16 pack: W[K,N] fp32 -> Wh[K/2,N] half2 =======================
__global__ void wconv_kernel(const float* __restrict__ W, __half2* __restrict__ Wh, int N) {
    int n  = blockIdx.x * 256 + threadIdx.x;
    int kp = blockIdx.y;
    float lo = W[(size_t)(2 * kp)     * N + n];
    float hi = W[(size_t)(2 * kp + 1) * N + n];
    Wh[(size_t)kp * N + n] = __floats2half2_rn(lo, hi);
}

// ======================= fp16 mma.sync GEMM =======================
// C[M,N] = A[M,K] @ W[K,N]  (+bias fp32, +gelu?, +res fp32?, out fp32 or fp16)
// A fp16 [M,K]; W pre-packed half2 [K/2,N].
// CTA 128x128, 128 threads = 4 warps (2x2), warp tile 64x64, BK=32, 3-stage cp.async.
#define BM 128
#define BN 128
#define BK 32
#define AE 20                            // A row stride, half2 entries (80 B, bank perm 20*gid+tig)
#define BE 132                           // B row stride, half2 entries (528 B, bank perm 4*tig+gid)
#define A_ENT (BM * AE)                  // 2560
#define B_ENT (16 * BE)                  // 2112
#define STG_ENT (A_ENT + B_ENT)          // 4672 entries = 18688 B
#define STAGES 3
#define SM_TOTAL (STAGES * STG_ENT * 4)  // 56064 bytes

__global__ __launch_bounds__(128, 2)
void tc_gemm_kernel(const __half* __restrict__ A, const __half2* __restrict__ Wh,
                    const float* __restrict__ bias, const float* __restrict__ res,
                    void* __restrict__ Cv, int M, int N, int K, int do_gelu, int out_half)
{
    extern __shared__ uint32_t smem[];
    const uint32_t sm0 = smem_u32(smem);
    const int tid  = threadIdx.x;
    const int wid  = tid >> 5;
    const int lane = tid & 31;
    const int gid  = lane >> 2;
    const int tig  = lane & 3;
    const int wm   = wid >> 1;          // 0..1: 64-row slab
    const int wn   = wid & 1;           // 0..1: 64-col slab
    const int row0 = blockIdx.y * BM;
    const int col0 = blockIdx.x * BN;

    float acc[4][8][4];
    #pragma unroll
    for (int mi = 0; mi < 4; mi++)
        #pragma unroll
        for (int ni = 0; ni < 8; ni++)
            #pragma unroll
            for (int e = 0; e < 4; e++) acc[mi][ni][e] = 0.f;

    const int niter = K >> 5;

    // loader: 1024 16B-chunks per stage (512 A + 512 B), 8 per thread
    auto load_stage = [&](int buf, int iter) {
        const int k0  = iter << 5;      // halves
        const int kp0 = iter << 4;      // half2 k-pair rows
        const uint32_t sb = sm0 + (uint32_t)buf * (STG_ENT * 4);
        #pragma unroll
        for (int t = 0; t < 8; t++) {
            int c = tid + t * 128;
            const void* g;
            uint32_t s;
            if (c < 512) {                        // A: 128 rows x 4 chunks (32 halves/row)
                int row = c >> 2, ch = c & 3;
                g = A + (size_t)(row0 + row) * K + k0 + ch * 8;
                s = sb + (uint32_t)(row * 80 + ch * 16);
            } else {                              // B: 16 kp-rows x 32 chunks (128 half2/row)
                int cc = c - 512;
                int row = cc >> 5, c4 = cc & 31;
                g = Wh + (size_t)(kp0 + row) * N + col0 + c4 * 4;
                s = sb + (uint32_t)(A_ENT * 4 + row * 528 + c4 * 16);
            }
            CP_ASYNC16(s, g);
        }
        CP_COMMIT();
    };

    if (0 < niter) { load_stage(0, 0); }
    if (1 < niter) { load_stage(1, 1); }

    for (int i = 0; i < niter; i++) {
        if (i + 2 < niter) load_stage((i + 2) % STAGES, i + 2);
        if (i + 2 < niter)      { CP_WAIT2(); }
        else if (i + 1 < niter) { CP_WAIT1(); }
        else                    { CP_WAIT0(); }
        __syncthreads();

        const uint32_t* sA = smem + (i % STAGES) * STG_ENT;
        const uint32_t* sB = sA + A_ENT;
        const uint32_t* pa = sA + (wm * 64 + gid) * AE + tig;
        const uint32_t* pb = sB + tig * BE + wn * 64 + gid;

        #pragma unroll
        for (int s = 0; s < 2; s++) {           // two k16 steps per BK=32
            uint32_t bfr[8][2];
            #pragma unroll
            for (int ni = 0; ni < 8; ni++) {
                bfr[ni][0] = pb[(s * 8)     * BE + ni * 8];
                bfr[ni][1] = pb[(s * 8 + 4) * BE + ni * 8];
            }
            #pragma unroll
            for (int mi = 0; mi < 4; mi++) {
                const uint32_t* p = pa + mi * 16 * AE + s * 8;
                uint32_t a0 = p[0];
                uint32_t a1 = p[8 * AE];
                uint32_t a2 = p[4];
                uint32_t a3 = p[8 * AE + 4];
                #pragma unroll
                for (int ni = 0; ni < 8; ni++)
                    mma_f16(acc[mi][ni][0], acc[mi][ni][1], acc[mi][ni][2], acc[mi][ni][3],
                            a0, a1, a2, a3, bfr[ni][0], bfr[ni][1]);
            }
        }
        __syncthreads();
    }

    // ---------------- epilogue ----------------
    #pragma unroll
    for (int mi = 0; mi < 4; mi++) {
        #pragma unroll
        for (int half = 0; half < 2; half++) {
            const size_t r = (size_t)(row0 + wm * 64 + mi * 16 + gid + half * 8);
            #pragma unroll
            for (int ni = 0; ni < 8; ni++) {
                const int cc = col0 + wn * 64 + ni * 8 + tig * 2;
                float v0 = acc[mi][ni][half * 2 + 0] + bias[cc];
                float v1 = acc[mi][ni][half * 2 + 1] + bias[cc + 1];
                if (do_gelu) {
                    v0 = 0.5f * v0 * (1.f + erff(v0 * 0.70710678118654752f));
                    v1 = 0.5f * v1 * (1.f + erff(v1 * 0.70710678118654752f));
                }
                if (res) {
                    float2 rr = *(const float2*)&res[r * N + cc];
                    v0 += rr.x; v1 += rr.y;
                }
                if (out_half) {
                    *(__half2*)((__half*)Cv + r * N + cc) = __floats2half2_rn(v0, v1);
                } else {
                    *(float2*)((float*)Cv + r * N + cc) = make_float2(v0, v1);
                }
            }
        }
    }
}

// ---------------- fused double LayerNorm (fp16 outputs) ----------------
__global__ void ln_kernel(const float* __restrict__ x,
                          const float* __restrict__ aw, const float* __restrict__ ab,
                          const float* __restrict__ fw, const float* __restrict__ fb,
                          __half* __restrict__ nx, __half* __restrict__ f)
{
    int row = blockIdx.x;
    int tid = threadIdx.x;
    const float4* xr = (const float4*)(x + (size_t)row * Dz);
    float4 a = xr[tid];
    float4 b = xr[tid + 256];
    float s  = a.x + a.y + a.z + a.w + b.x + b.y + b.z + b.w;
    float ss = a.x*a.x + a.y*a.y + a.z*a.z + a.w*a.w
             + b.x*b.x + b.y*b.y + b.z*b.z + b.w*b.w;
    #pragma unroll
    for (int o = 16; o; o >>= 1) {
        s  += __shfl_xor_sync(0xffffffffu, s,  o);
        ss += __shfl_xor_sync(0xffffffffu, ss, o);
    }
    __shared__ float r1[8], r2[8];
    __shared__ float mv[2];
    int wid = tid >> 5;
    if ((tid & 31) == 0) { r1[wid] = s; r2[wid] = ss; }
    __syncthreads();
    if (tid == 0) {
        float S = 0.f, SS = 0.f;
        #pragma unroll
        for (int i = 0; i < 8; i++) { S += r1[i]; SS += r2[i]; }
        float m   = S * (1.f / Dz);
        float var = SS * (1.f / Dz) - m * m;
        mv[0] = m;
        mv[1] = rsqrtf(var + EPSF);
    }
    __syncthreads();
    float m = mv[0], r = mv[1];

    __half* nxr = nx + (size_t)row * Dz;
    __half* fr  = f  + (size_t)row * Dz;
    const float4* aw4 = (const float4*)aw;  const float4* ab4 = (const float4*)ab;
    const float4* fw4 = (const float4*)fw;  const float4* fb4 = (const float4*)fb;
    #pragma unroll
    for (int e = 0; e < 2; e++) {
        int slot = tid + e * 256;
        float4 v = (e == 0) ? a : b;
        float4 w1 = aw4[slot], b1 = ab4[slot], w2 = fw4[slot], b2 = fb4[slot];
        __half2 h0 = __floats2half2_rn((v.x - m) * r * w1.x + b1.x, (v.y - m) * r * w1.y + b1.y);
        __half2 h1 = __floats2half2_rn((v.z - m) * r * w1.z + b1.z, (v.w - m) * r * w1.w + b1.w);
        __half2 g0 = __floats2half2_rn((v.x - m) * r * w2.x + b2.x, (v.y - m) * r * w2.y + b2.y);
        __half2 g1 = __floats2half2_rn((v.z - m) * r * w2.z + b2.z, (v.w - m) * r * w2.w + b2.w);
        *(__half2*)(nxr + slot * 4)     = h0;
        *(__half2*)(nxr + slot * 4 + 2) = h1;
        *(__half2*)(fr  + slot * 4)     = g0;
        *(__half2*)(fr  + slot * 4 + 2) = g1;
    }
}

// ---------------- per-head RMS norm + RoPE + q scaling + tf32 round (q,k,v), fp32 in place ----------------
__global__ void qkrope_kernel(float* __restrict__ qkv, const float* __restrict__ fc,
                              const float* __restrict__ qn_w, const float* __restrict__ kn_w)
{
    int blk   = blockIdx.x;
    int token = blk >> 4;
    int h     = blk & 15;
    int s     = token & (Sz - 1);
    int sel   = threadIdx.x >> 7;       // 0=q, 1=k, 2=v
    int d     = threadIdx.x & 127;
    float* ptr = qkv + (size_t)token * (3 * Dz) + sel * Dz + h * HDz;
    float v = ptr[d];
    float ss = v * v;
    #pragma unroll
    for (int o = 16; o; o >>= 1) ss += __shfl_xor_sync(0xffffffffu, ss, o);
    __shared__ float red[12];
    __shared__ float rstd_s[2];
    int wid = threadIdx.x >> 5;
    if ((threadIdx.x & 31) == 0) red[wid] = ss;
    __syncthreads();
    if (d == 0 && sel < 2) {
        float t = red[sel * 4] + red[sel * 4 + 1] + red[sel * 4 + 2] + red[sel * 4 + 3];
        rstd_s[sel] = rsqrtf(t * (1.f / HDz) + EPSF);
    }
    __syncthreads();
    if (sel == 2) {                     // v: tf32-round in place
        ptr[d] = tf32v(v);
        return;
    }
    float rstd = rstd_s[sel];
    float w = sel ? kn_w[d] : qn_w[d];
    float nv = v * rstd * w;
    if (d < RNz) {
        int j = d >> 1;
        float c  = fc[(s * 16 + j) * 2];
        float sn = fc[(s * 16 + j) * 2 + 1];
        float a = __shfl_sync(0xffffffffu, nv, j);
        float b = __shfl_sync(0xffffffffu, nv, j + 16);
        nv = (d & 1) ? (b * c + a * sn) : (a * c - b * sn);
    }
    if (sel == 0) nv *= SCALEF;
    ptr[d] = tf32v(nv);
}

// ======================= FA2-style windowed attention (tf32 mma, fp32 qkv, fp16 y out) =======================
#define AT_CK 32
#define KSTR 132
#define VSTR 136
#define AT_K_OFF(buf) ((buf) * (AT_CK * KSTR))
#define AT_V_OFF(buf) (2 * AT_CK * KSTR + (buf) * (AT_CK * VSTR))
#define AT_SMEM_FLOATS (2 * AT_CK * KSTR + 2 * AT_CK * VSTR)   // 17152
#define AT_SMEM_BYTES  (AT_SMEM_FLOATS * 4)                     // 68608

__global__ __launch_bounds__(128, 2)
void attn_mma_kernel(const float* __restrict__ qkv, __half* __restrict__ y)
{
    extern __shared__ float sm[];
    const uint32_t sm0 = smem_u32(sm);
    const int tid  = threadIdx.x;
    const int wi   = tid >> 5;
    const int lane = tid & 31;
    const int gid  = lane >> 2;
    const int tig  = lane & 3;
    const int qb0  = (blockIdx.x & 31) << 6;
    const int h    = (blockIdx.x >> 5) & 15;
    const int b    = blockIdx.x >> 9;
    const int qw   = qb0 + wi * 16;

    uint32_t qf[16][4];
    {
        const float* q0 = qkv + (size_t)(b * Sz + qw + gid) * (3 * Dz) + h * HDz;
        const float* q1 = q0 + (size_t)8 * (3 * Dz);
        #pragma unroll
        for (int kg = 0; kg < 16; kg++) {
            qf[kg][0] = __float_as_uint(q0[kg * 8 + tig]);
            qf[kg][1] = __float_as_uint(q1[kg * 8 + tig]);
            qf[kg][2] = __float_as_uint(q0[kg * 8 + tig + 4]);
            qf[kg][3] = __float_as_uint(q1[kg * 8 + tig + 4]);
        }
    }

    float o[16][4];
    #pragma unroll
    for (int dt = 0; dt < 16; dt++)
        #pragma unroll
        for (int e = 0; e < 4; e++) o[dt][e] = 0.f;
    float m0 = -1e30f, m1 = -1e30f, l0 = 0.f, l1 = 0.f;

    int cs = qb0 - (WINz - 1); if (cs < 0) cs = 0;
    cs &= ~31;
    const int nc = ((qb0 + 63 - cs) >> 5) + 1;

    auto load_chunk = [&](int buf, int jc) {
        #pragma unroll
        for (int i = 0; i < 8; i++) {
            int fidx = i * 128 + tid;
            int row = fidx >> 5, c4 = fidx & 31;
            const float* gk = qkv + (size_t)(b * Sz + jc + row) * (3 * Dz) + Dz + h * HDz + c4 * 4;
            CP_ASYNC16(sm0 + (uint32_t)(AT_K_OFF(buf) + row * KSTR + c4 * 4) * 4, gk);
        }
        #pragma unroll
        for (int i = 0; i < 8; i++) {
            int fidx = i * 128 + tid;
            int row = fidx >> 5, c4 = fidx & 31;
            const float* gv = qkv + (size_t)(b * Sz + jc + row) * (3 * Dz) + 2 * Dz + h * HDz + c4 * 4;
            CP_ASYNC16(sm0 + (uint32_t)(AT_V_OFF(buf) + row * VSTR + c4 * 4) * 4, gv);
        }
        CP_COMMIT();
    };

    load_chunk(0, cs);

    for (int c = 0; c < nc; c++) {
        const int jc  = cs + c * 32;
        const int buf = c & 1;
        if (c + 1 < nc) { load_chunk((c + 1) & 1, jc + 32); CP_WAIT1(); }
        else            { CP_WAIT0(); }
        __syncthreads();

        const bool act = (jc <= qw + 15) && (jc + 31 >= qw - (WINz - 1));
        if (act) {
            const uint32_t* Ks = (const uint32_t*)(sm + AT_K_OFF(buf));
            const uint32_t* Vs = (const uint32_t*)(sm + AT_V_OFF(buf));

            float sc[4][4];
            #pragma unroll
            for (int ng = 0; ng < 4; ng++)
                #pragma unroll
                for (int e = 0; e < 4; e++) sc[ng][e] = 0.f;
            #pragma unroll
            for (int kg = 0; kg < 16; kg++) {
                #pragma unroll
                for (int ng = 0; ng < 4; ng++) {
                    const uint32_t* kp = Ks + (ng * 8 + gid) * KSTR + kg * 8 + tig;
                    mma_tf32(sc[ng][0], sc[ng][1], sc[ng][2], sc[ng][3],
                             qf[kg][0], qf[kg][1], qf[kg][2], qf[kg][3],
                             kp[0], kp[4]);
                }
            }

            const int q0r = qw + gid, q1r = qw + gid + 8;
            float smax0 = -1e30f, smax1 = -1e30f;
            #pragma unroll
            for (int ng = 0; ng < 4; ng++) {
                int j0 = jc + ng * 8 + tig * 2;
                smax0 = fmaxf(smax0, ((unsigned)(q0r - j0)     < 256u) ? sc[ng][0] : -1e30f);
                smax0 = fmaxf(smax0, ((unsigned)(q0r - j0 - 1) < 256u) ? sc[ng][1] : -1e30f);
                smax1 = fmaxf(smax1, ((unsigned)(q1r - j0)     < 256u) ? sc[ng][2] : -1e30f);
                smax1 = fmaxf(smax1, ((unsigned)(q1r - j0 - 1) < 256u) ? sc[ng][3] : -1e30f);
            }
            smax0 = fmaxf(smax0, __shfl_xor_sync(0xffffffffu, smax0, 1));
            smax0 = fmaxf(smax0, __shfl_xor_sync(0xffffffffu, smax0, 2));
            smax1 = fmaxf(smax1, __shfl_xor_sync(0xffffffffu, smax1, 1));
            smax1 = fmaxf(smax1, __shfl_xor_sync(0xffffffffu, smax1, 2));
            float m0n = fmaxf(m0, smax0), m1n = fmaxf(m1, smax1);
            float cr0 = __expf(m0 - m0n), cr1 = __expf(m1 - m1n);
            m0 = m0n; m1 = m1n;

            float ps0 = 0.f, ps1 = 0.f;
            #pragma unroll
            for (int ng = 0; ng < 4; ng++) {
                int j0 = jc + ng * 8 + tig * 2;
                float e;
                e = ((unsigned)(q0r - j0)     < 256u) ? __expf(sc[ng][0] - m0) : 0.f;
                sc[ng][0] = e; ps0 += e;
                e = ((unsigned)(q0r - j0 - 1) < 256u) ? __expf(sc[ng][1] - m0) : 0.f;
                sc[ng][1] = e; ps0 += e;
                e = ((unsigned)(q1r - j0)     < 256u) ? __expf(sc[ng][2] - m1) : 0.f;
                sc[ng][2] = e; ps1 += e;
                e = ((unsigned)(q1r - j0 - 1) < 256u) ? __expf(sc[ng][3] - m1) : 0.f;
                sc[ng][3] = e; ps1 += e;
            }
            ps0 += __shfl_xor_sync(0xffffffffu, ps0, 1);
            ps0 += __shfl_xor_sync(0xffffffffu, ps0, 2);
            ps1 += __shfl_xor_sync(0xffffffffu, ps1, 1);
            ps1 += __shfl_xor_sync(0xffffffffu, ps1, 2);
            l0 = l0 * cr0 + ps0;
            l1 = l1 * cr1 + ps1;

            #pragma unroll
            for (int dt = 0; dt < 16; dt++) {
                o[dt][0] *= cr0; o[dt][1] *= cr0;
                o[dt][2] *= cr1; o[dt][3] *= cr1;
            }

            uint32_t af[4][4];
            const int src  = (lane & ~3) | (tig >> 1);
            const int src2 = src + 2;
            #pragma unroll
            for (int ng = 0; ng < 4; ng++) {
                float v0 = __shfl_sync(0xffffffffu, sc[ng][0], src);
                float v1 = __shfl_sync(0xffffffffu, sc[ng][1], src);
                float v2 = __shfl_sync(0xffffffffu, sc[ng][2], src);
                float v3 = __shfl_sync(0xffffffffu, sc[ng][3], src);
                float w0 = __shfl_sync(0xffffffffu, sc[ng][0], src2);
                float w1 = __shfl_sync(0xffffffffu, sc[ng][1], src2);
                float w2 = __shfl_sync(0xffffffffu, sc[ng][2], src2);
                float w3 = __shfl_sync(0xffffffffu, sc[ng][3], src2);
                af[ng][0] = f2tf32((tig & 1) ? v1 : v0);
                af[ng][1] = f2tf32((tig & 1) ? v3 : v2);
                af[ng][2] = f2tf32((tig & 1) ? w1 : w0);
                af[ng][3] = f2tf32((tig & 1) ? w3 : w2);
            }

            #pragma unroll
            for (int dt = 0; dt < 16; dt++) {
                #pragma unroll
                for (int ng = 0; ng < 4; ng++) {
                    const uint32_t* vp = Vs + (ng * 8 + tig) * VSTR + dt * 8 + gid;
                    mma_tf32(o[dt][0], o[dt][1], o[dt][2], o[dt][3],
                             af[ng][0], af[ng][1], af[ng][2], af[ng][3],
                             vp[0], vp[4 * VSTR]);
                }
            }
        }
        __syncthreads();
    }

    // ---- write normalized output as fp16 (A operand of Wo GEMM) ----
    const float i0 = 1.f / l0, i1 = 1.f / l1;
    __half* y0 = y + (size_t)(b * Sz + qw + gid) * Dz + h * HDz;
    __half* y1 = y0 + (size_t)8 * Dz;
    #pragma unroll
    for (int dt = 0; dt < 16; dt++) {
        *(__half2*)(y0 + dt * 8 + tig * 2) = __floats2half2_rn(o[dt][0] * i0, o[dt][1] * i0);
        *(__half2*)(y1 + dt * 8 + tig * 2) = __floats2half2_rn(o[dt][2] * i1, o[dt][3] * i1);
    }
}

// ---------------- launch ----------------
extern "C" void kernel_launch(void* const* d_in, const int* in_sizes, int n_in,
                              void* d_out, int out_size)
{
    const float* x      = (const float*)d_in[0];
    const float* fc     = (const float*)d_in[1];
    // d_in[2] = mask (implicit: causal sliding window of 256)
    const float* wqkv_w = (const float*)d_in[3];
    const float* wqkv_b = (const float*)d_in[4];
    const float* wo_w   = (const float*)d_in[5];
    const float* wo_b   = (const float*)d_in[6];
    const float* qn_w   = (const float*)d_in[7];
    const float* kn_w   = (const float*)d_in[8];
    const float* aln_w  = (const float*)d_in[9];
    const float* aln_b  = (const float*)d_in[10];
    const float* fln_w  = (const float*)d_in[11];
    const float* fln_b  = (const float*)d_in[12];
    const float* w1_w   = (const float*)d_in[13];
    const float* w1_b   = (const float*)d_in[14];
    const float* w2_w   = (const float*)d_in[15];
    const float* w2_b   = (const float*)d_in[16];
    float* out = (float*)d_out;

    __half *nx, *f, *y, *ffn;
    float *qkv, *h;
    __half2 *wqkvH, *woH, *w1H, *w2H;
    cudaGetSymbolAddress((void**)&nx,    g_nx);
    cudaGetSymbolAddress((void**)&f,     g_f);
    cudaGetSymbolAddress((void**)&qkv,   g_qkv);
    cudaGetSymbolAddress((void**)&y,     g_y);
    cudaGetSymbolAddress((void**)&h,     g_h);
    cudaGetSymbolAddress((void**)&ffn,   g_ffn);
    cudaGetSymbolAddress((void**)&wqkvH, g_wqkvH);
    cudaGetSymbolAddress((void**)&woH,   g_woH);
    cudaGetSymbolAddress((void**)&w1H,   g_w1H);
    cudaGetSymbolAddress((void**)&w2H,   g_w2H);

    static int smem_cfg = 0;
    if (!smem_cfg) {
        cudaFuncSetAttribute(tc_gemm_kernel,
                             cudaFuncAttributeMaxDynamicSharedMemorySize, SM_TOTAL);
        cudaFuncSetAttribute(attn_mma_kernel,
                             cudaFuncAttributeMaxDynamicSharedMemorySize, AT_SMEM_BYTES);
        smem_cfg = 1;
    }

    // 0. weight fp16 pack (k-pair interleaved)
    wconv_kernel<<<dim3(3 * Dz / 256, Dz / 2), 256>>>(wqkv_w, wqkvH, 3 * Dz);
    wconv_kernel<<<dim3(Dz / 256,     Dz / 2), 256>>>(wo_w,   woH,   Dz);
    wconv_kernel<<<dim3(FFz / 256,    Dz / 2), 256>>>(w1_w,   w1H,   FFz);
    wconv_kernel<<<dim3(Dz / 256,    FFz / 2), 256>>>(w2_w,   w2H,   Dz);

    // 1. fused LN (fp16 outputs)
    ln_kernel<<<TOK, 256>>>(x, aln_w, aln_b, fln_w, fln_b, nx, f);

    // 2. qkv = nx @ wqkv + b  (fp32 out)
    tc_gemm_kernel<<<dim3(3 * Dz / BN, TOK / BM), 128, SM_TOTAL>>>(
        nx, wqkvH, wqkv_b, nullptr, qkv, TOK, 3 * Dz, Dz, 0, 0);

    // 3. per-head rms norm + rope + scale fold + tf32 round
    qkrope_kernel<<<TOK * Hz, 384>>>(qkv, fc, qn_w, kn_w);

    // 4. windowed FA2 attention -> y (fp16)
    attn_mma_kernel<<<Bz * Hz * (Sz / 64), 128, AT_SMEM_BYTES>>>(qkv, y);

    // 5. h = y @ wo + b + x   (fp32 residual stream)
    tc_gemm_kernel<<<dim3(Dz / BN, TOK / BM), 128, SM_TOTAL>>>(
        y, woH, wo_b, x, h, TOK, Dz, Dz, 0, 0);

    // 6. ffn = gelu_exact(f @ w1 + b1)  (fp16 out)
    tc_gemm_kernel<<<dim3(FFz / BN, TOK / BM), 128, SM_TOTAL>>>(
        f, w1H, w1_b, nullptr, ffn, TOK, FFz, Dz, 1, 1);

    // 7. out = ffn @ w2 + b2 + h  (fp32 output)
    tc_gemm_kernel<<<dim3(Dz / BN, TOK / BM), 128, SM_TOTAL>>>(
        ffn, w2H, w2_b, h, out, TOK, Dz, FFz, 0, 0);
}

// round 12
// speedup vs baseline: 5.8026x; 1.0518x over previous
#include <cuda_runtime.h>
#include <cuda_fp16.h>
#include <cuda_bf16.h>
#include <math.h>
#include <stdint.h>

// ---------------- problem constants ----------------
#define Bz   2
#define Sz   2048
#define Dz   2048
#define Hz   16
#define HDz  128
#define RNz  32
#define FFz  4096
#define WINz 256
#define TOK  (Bz*Sz)          // 4096 tokens
#define EPSF 1e-5f
#define SCALEF 0.08838834764831845f   // 1/sqrt(128)

// ---------------- scratch (device globals; no allocation allowed) ----------------
__device__ __half  g_nx  [TOK*Dz];      // fp16 LN output (attn branch)
__device__ __half  g_f   [TOK*Dz];      // fp16 LN output (ffn branch)
__device__ float   g_qkv [TOK*3*Dz];    // fp32; q,k,v tf32-rounded after qkrope
__device__ __half  g_y   [TOK*Dz];      // fp16 attention output
__device__ float   g_h   [TOK*Dz];      // fp32 residual stream
__device__ __half  g_ffn [TOK*FFz];     // fp16 gelu(f@w1+b1)
// fp16 weights, k-pair-interleaved: Wh[kp][n] = half2(W[2kp][n], W[2kp+1][n])
__device__ __half2 g_wqkvH[(Dz/2)*3*Dz];
__device__ __half2 g_woH  [(Dz/2)*Dz];
__device__ __half2 g_w1H  [(Dz/2)*FFz];
__device__ __half2 g_w2H  [(FFz/2)*Dz];

// ======================= helpers =======================
__device__ __forceinline__ uint32_t smem_u32(const void* p) {
    uint32_t a;
    asm("{ .reg .u64 t; cvta.to.shared.u64 t, %1; cvt.u32.u64 %0, t; }" : "=r"(a) : "l"(p));
    return a;
}
#define CP_ASYNC16(smem, gptr) \
    asm volatile("cp.async.cg.shared.global [%0], [%1], 16;" :: "r"(smem), "l"(gptr))
#define CP_COMMIT()  asm volatile("cp.async.commit_group;" ::: "memory")
#define CP_WAIT0()   asm volatile("cp.async.wait_group 0;" ::: "memory")
#define CP_WAIT1()   asm volatile("cp.async.wait_group 1;" ::: "memory")
#define CP_WAIT2()   asm volatile("cp.async.wait_group 2;" ::: "memory")

__device__ __forceinline__ uint32_t f2tf32(float x) {
    uint32_t r;
    asm("cvt.rna.tf32.f32 %0, %1;" : "=r"(r) : "f"(x));
    return r;
}
__device__ __forceinline__ float tf32v(float x) {
    return __uint_as_float(f2tf32(x));
}
// tf32 mma (attention only)
__device__ __forceinline__ void mma_tf32(float& c0, float& c1, float& c2, float& c3,
                                         uint32_t a0, uint32_t a1, uint32_t a2, uint32_t a3,
                                         uint32_t b0, uint32_t b1) {
    asm volatile(
        "mma.sync.aligned.m16n8k8.row.col.f32.tf32.tf32.f32 "
        "{%0,%1,%2,%3}, {%4,%5,%6,%7}, {%8,%9}, {%0,%1,%2,%3};"
        : "+f"(c0), "+f"(c1), "+f"(c2), "+f"(c3)
        : "r"(a0), "r"(a1), "r"(a2), "r"(a3), "r"(b0), "r"(b1));
}
// fp16 mma (GEMMs)
__device__ __forceinline__ void mma_f16(float& c0, float& c1, float& c2, float& c3,
                                        uint32_t a0, uint32_t a1, uint32_t a2, uint32_t a3,
                                        uint32_t b0, uint32_t b1) {
    asm volatile(
        "mma.sync.aligned.m16n8k16.row.col.f32.f16.f16.f32 "
        "{%0,%1,%2,%3}, {%4,%5,%6,%7}, {%8,%9}, {%0,%1,%2,%3};"
        : "+f"(c0), "+f"(c1), "+f"(c2), "+f"(c3)
        : "r"(a0), "r"(a1), "r"(a2), "r"(a3), "r"(b0), "r"(b1));
}

// ======================= weight fp16 pack: W[K,N] fp32 -> Wh[K/2,N] half2 =======================
__global__ void wconv_kernel(const float* __restrict__ W, __half2* __restrict__ Wh, int N) {
    int n  = blockIdx.x * 256 + threadIdx.x;
    int kp = blockIdx.y;
    float lo = W[(size_t)(2 * kp)     * N + n];
    float hi = W[(size_t)(2 * kp + 1) * N + n];
    Wh[(size_t)kp * N + n] = __floats2half2_rn(lo, hi);
}

// ======================= fp16 mma.sync GEMM =======================
// C[M,N] = A[M,K] @ W[K,N]  (+bias fp32, +gelu?, +res fp32?, out fp32 or fp16)
// A fp16 [M,K]; W pre-packed half2 [K/2,N].
// CTA 128x128, 128 threads = 4 warps (2x2), warp tile 64x64, BK=32, 3-stage cp.async.
#define BM 128
#define BN 128
#define BK 32
#define AE 20                            // A row stride, half2 entries (80 B, bank perm 20*gid+tig)
#define BE 132                           // B row stride, half2 entries (528 B, bank perm 4*tig+gid)
#define A_ENT (BM * AE)                  // 2560
#define B_ENT (16 * BE)                  // 2112
#define STG_ENT (A_ENT + B_ENT)          // 4672 entries = 18688 B
#define STAGES 3
#define SM_TOTAL (STAGES * STG_ENT * 4)  // 56064 bytes

__global__ __launch_bounds__(128, 2)
void tc_gemm_kernel(const __half* __restrict__ A, const __half2* __restrict__ Wh,
                    const float* __restrict__ bias, const float* __restrict__ res,
                    void* __restrict__ Cv, int M, int N, int K, int do_gelu, int out_half)
{
    extern __shared__ uint32_t smem[];
    const uint32_t sm0 = smem_u32(smem);
    const int tid  = threadIdx.x;
    const int wid  = tid >> 5;
    const int lane = tid & 31;
    const int gid  = lane >> 2;
    const int tig  = lane & 3;
    const int wm   = wid >> 1;          // 0..1: 64-row slab
    const int wn   = wid & 1;           // 0..1: 64-col slab
    const int row0 = blockIdx.y * BM;
    const int col0 = blockIdx.x * BN;

    float acc[4][8][4];
    #pragma unroll
    for (int mi = 0; mi < 4; mi++)
        #pragma unroll
        for (int ni = 0; ni < 8; ni++)
            #pragma unroll
            for (int e = 0; e < 4; e++) acc[mi][ni][e] = 0.f;

    const int niter = K >> 5;

    // loader: 1024 16B-chunks per stage (512 A + 512 B), 8 per thread
    auto load_stage = [&](int buf, int iter) {
        const int k0  = iter << 5;      // halves
        const int kp0 = iter << 4;      // half2 k-pair rows
        const uint32_t sb = sm0 + (uint32_t)buf * (STG_ENT * 4);
        #pragma unroll
        for (int t = 0; t < 8; t++) {
            int c = tid + t * 128;
            const void* g;
            uint32_t s;
            if (c < 512) {                        // A: 128 rows x 4 chunks (32 halves/row)
                int row = c >> 2, ch = c & 3;
                g = A + (size_t)(row0 + row) * K + k0 + ch * 8;
                s = sb + (uint32_t)(row * 80 + ch * 16);
            } else {                              // B: 16 kp-rows x 32 chunks (128 half2/row)
                int cc = c - 512;
                int row = cc >> 5, c4 = cc & 31;
                g = Wh + (size_t)(kp0 + row) * N + col0 + c4 * 4;
                s = sb + (uint32_t)(A_ENT * 4 + row * 528 + c4 * 16);
            }
            CP_ASYNC16(s, g);
        }
        CP_COMMIT();
    };

    if (0 < niter) { load_stage(0, 0); }
    if (1 < niter) { load_stage(1, 1); }

    for (int i = 0; i < niter; i++) {
        if (i + 2 < niter) load_stage((i + 2) % STAGES, i + 2);
        if (i + 2 < niter)      { CP_WAIT2(); }
        else if (i + 1 < niter) { CP_WAIT1(); }
        else                    { CP_WAIT0(); }
        __syncthreads();

        const uint32_t* sA = smem + (i % STAGES) * STG_ENT;
        const uint32_t* sB = sA + A_ENT;
        const uint32_t* pa = sA + (wm * 64 + gid) * AE + tig;
        const uint32_t* pb = sB + tig * BE + wn * 64 + gid;

        #pragma unroll
        for (int s = 0; s < 2; s++) {           // two k16 steps per BK=32
            uint32_t bfr[8][2];
            #pragma unroll
            for (int ni = 0; ni < 8; ni++) {
                bfr[ni][0] = pb[(s * 8)     * BE + ni * 8];
                bfr[ni][1] = pb[(s * 8 + 4) * BE + ni * 8];
            }
            #pragma unroll
            for (int mi = 0; mi < 4; mi++) {
                const uint32_t* p = pa + mi * 16 * AE + s * 8;
                uint32_t a0 = p[0];
                uint32_t a1 = p[8 * AE];
                uint32_t a2 = p[4];
                uint32_t a3 = p[8 * AE + 4];
                #pragma unroll
                for (int ni = 0; ni < 8; ni++)
                    mma_f16(acc[mi][ni][0], acc[mi][ni][1], acc[mi][ni][2], acc[mi][ni][3],
                            a0, a1, a2, a3, bfr[ni][0], bfr[ni][1]);
            }
        }
        __syncthreads();
    }

    // ---------------- epilogue ----------------
    #pragma unroll
    for (int mi = 0; mi < 4; mi++) {
        #pragma unroll
        for (int half = 0; half < 2; half++) {
            const size_t r = (size_t)(row0 + wm * 64 + mi * 16 + gid + half * 8);
            #pragma unroll
            for (int ni = 0; ni < 8; ni++) {
                const int cc = col0 + wn * 64 + ni * 8 + tig * 2;
                float v0 = acc[mi][ni][half * 2 + 0] + bias[cc];
                float v1 = acc[mi][ni][half * 2 + 1] + bias[cc + 1];
                if (do_gelu) {
                    v0 = 0.5f * v0 * (1.f + erff(v0 * 0.70710678118654752f));
                    v1 = 0.5f * v1 * (1.f + erff(v1 * 0.70710678118654752f));
                }
                if (res) {
                    float2 rr = *(const float2*)&res[r * N + cc];
                    v0 += rr.x; v1 += rr.y;
                }
                if (out_half) {
                    *(__half2*)((__half*)Cv + r * N + cc) = __floats2half2_rn(v0, v1);
                } else {
                    *(float2*)((float*)Cv + r * N + cc) = make_float2(v0, v1);
                }
            }
        }
    }
}

// ---------------- fused double LayerNorm (fp16 outputs) ----------------
__global__ void ln_kernel(const float* __restrict__ x,
                          const float* __restrict__ aw, const float* __restrict__ ab,
                          const float* __restrict__ fw, const float* __restrict__ fb,
                          __half* __restrict__ nx, __half* __restrict__ f)
{
    int row = blockIdx.x;
    int tid = threadIdx.x;
    const float4* xr = (const float4*)(x + (size_t)row * Dz);
    float4 a = xr[tid];
    float4 b = xr[tid + 256];
    float s  = a.x + a.y + a.z + a.w + b.x + b.y + b.z + b.w;
    float ss = a.x*a.x + a.y*a.y + a.z*a.z + a.w*a.w
             + b.x*b.x + b.y*b.y + b.z*b.z + b.w*b.w;
    #pragma unroll
    for (int o = 16; o; o >>= 1) {
        s  += __shfl_xor_sync(0xffffffffu, s,  o);
        ss += __shfl_xor_sync(0xffffffffu, ss, o);
    }
    __shared__ float r1[8], r2[8];
    __shared__ float mv[2];
    int wid = tid >> 5;
    if ((tid & 31) == 0) { r1[wid] = s; r2[wid] = ss; }
    __syncthreads();
    if (tid == 0) {
        float S = 0.f, SS = 0.f;
        #pragma unroll
        for (int i = 0; i < 8; i++) { S += r1[i]; SS += r2[i]; }
        float m   = S * (1.f / Dz);
        float var = SS * (1.f / Dz) - m * m;
        mv[0] = m;
        mv[1] = rsqrtf(var + EPSF);
    }
    __syncthreads();
    float m = mv[0], r = mv[1];

    __half* nxr = nx + (size_t)row * Dz;
    __half* fr  = f  + (size_t)row * Dz;
    const float4* aw4 = (const float4*)aw;  const float4* ab4 = (const float4*)ab;
    const float4* fw4 = (const float4*)fw;  const float4* fb4 = (const float4*)fb;
    #pragma unroll
    for (int e = 0; e < 2; e++) {
        int slot = tid + e * 256;
        float4 v = (e == 0) ? a : b;
        float4 w1 = aw4[slot], b1 = ab4[slot], w2 = fw4[slot], b2 = fb4[slot];
        __half2 h0 = __floats2half2_rn((v.x - m) * r * w1.x + b1.x, (v.y - m) * r * w1.y + b1.y);
        __half2 h1 = __floats2half2_rn((v.z - m) * r * w1.z + b1.z, (v.w - m) * r * w1.w + b1.w);
        __half2 g0 = __floats2half2_rn((v.x - m) * r * w2.x + b2.x, (v.y - m) * r * w2.y + b2.y);
        __half2 g1 = __floats2half2_rn((v.z - m) * r * w2.z + b2.z, (v.w - m) * r * w2.w + b2.w);
        *(__half2*)(nxr + slot * 4)     = h0;
        *(__half2*)(nxr + slot * 4 + 2) = h1;
        *(__half2*)(fr  + slot * 4)     = g0;
        *(__half2*)(fr  + slot * 4 + 2) = g1;
    }
}

// ---------------- per-head RMS norm + RoPE + q scaling + tf32 round (q,k,v), fp32 in place ----------------
__global__ void qkrope_kernel(float* __restrict__ qkv, const float* __restrict__ fc,
                              const float* __restrict__ qn_w, const float* __restrict__ kn_w)
{
    int blk   = blockIdx.x;
    int token = blk >> 4;
    int h     = blk & 15;
    int s     = token & (Sz - 1);
    int sel   = threadIdx.x >> 7;       // 0=q, 1=k, 2=v
    int d     = threadIdx.x & 127;
    float* ptr = qkv + (size_t)token * (3 * Dz) + sel * Dz + h * HDz;
    float v = ptr[d];
    float ss = v * v;
    #pragma unroll
    for (int o = 16; o; o >>= 1) ss += __shfl_xor_sync(0xffffffffu, ss, o);
    __shared__ float red[12];
    __shared__ float rstd_s[2];
    int wid = threadIdx.x >> 5;
    if ((threadIdx.x & 31) == 0) red[wid] = ss;
    __syncthreads();
    if (d == 0 && sel < 2) {
        float t = red[sel * 4] + red[sel * 4 + 1] + red[sel * 4 + 2] + red[sel * 4 + 3];
        rstd_s[sel] = rsqrtf(t * (1.f / HDz) + EPSF);
    }
    __syncthreads();
    if (sel == 2) {                     // v: tf32-round in place
        ptr[d] = tf32v(v);
        return;
    }
    float rstd = rstd_s[sel];
    float w = sel ? kn_w[d] : qn_w[d];
    float nv = v * rstd * w;
    if (d < RNz) {
        int j = d >> 1;
        float c  = fc[(s * 16 + j) * 2];
        float sn = fc[(s * 16 + j) * 2 + 1];
        float a = __shfl_sync(0xffffffffu, nv, j);
        float b = __shfl_sync(0xffffffffu, nv, j + 16);
        nv = (d & 1) ? (b * c + a * sn) : (a * c - b * sn);
    }
    if (sel == 0) nv *= SCALEF;
    ptr[d] = tf32v(nv);
}

// ======================= FA2-style windowed attention (tf32 mma, fp32 qkv, fp16 y out) =======================
#define AT_CK 32
#define KSTR 132
#define VSTR 136
#define AT_K_OFF(buf) ((buf) * (AT_CK * KSTR))
#define AT_V_OFF(buf) (2 * AT_CK * KSTR + (buf) * (AT_CK * VSTR))
#define AT_SMEM_FLOATS (2 * AT_CK * KSTR + 2 * AT_CK * VSTR)   // 17152
#define AT_SMEM_BYTES  (AT_SMEM_FLOATS * 4)                     // 68608

__global__ __launch_bounds__(128, 2)
void attn_mma_kernel(const float* __restrict__ qkv, __half* __restrict__ y)
{
    extern __shared__ float sm[];
    const uint32_t sm0 = smem_u32(sm);
    const int tid  = threadIdx.x;
    const int wi   = tid >> 5;
    const int lane = tid & 31;
    const int gid  = lane >> 2;
    const int tig  = lane & 3;
    const int qb0  = (blockIdx.x & 31) << 6;
    const int h    = (blockIdx.x >> 5) & 15;
    const int b    = blockIdx.x >> 9;
    const int qw   = qb0 + wi * 16;

    uint32_t qf[16][4];
    {
        const float* q0 = qkv + (size_t)(b * Sz + qw + gid) * (3 * Dz) + h * HDz;
        const float* q1 = q0 + (size_t)8 * (3 * Dz);
        #pragma unroll
        for (int kg = 0; kg < 16; kg++) {
            qf[kg][0] = __float_as_uint(q0[kg * 8 + tig]);
            qf[kg][1] = __float_as_uint(q1[kg * 8 + tig]);
            qf[kg][2] = __float_as_uint(q0[kg * 8 + tig + 4]);
            qf[kg][3] = __float_as_uint(q1[kg * 8 + tig + 4]);
        }
    }

    float o[16][4];
    #pragma unroll
    for (int dt = 0; dt < 16; dt++)
        #pragma unroll
        for (int e = 0; e < 4; e++) o[dt][e] = 0.f;
    float m0 = -1e30f, m1 = -1e30f, l0 = 0.f, l1 = 0.f;

    int cs = qb0 - (WINz - 1); if (cs < 0) cs = 0;
    cs &= ~31;
    const int nc = ((qb0 + 63 - cs) >> 5) + 1;

    auto load_chunk = [&](int buf, int jc) {
        #pragma unroll
        for (int i = 0; i < 8; i++) {
            int fidx = i * 128 + tid;
            int row = fidx >> 5, c4 = fidx & 31;
            const float* gk = qkv + (size_t)(b * Sz + jc + row) * (3 * Dz) + Dz + h * HDz + c4 * 4;
            CP_ASYNC16(sm0 + (uint32_t)(AT_K_OFF(buf) + row * KSTR + c4 * 4) * 4, gk);
        }
        #pragma unroll
        for (int i = 0; i < 8; i++) {
            int fidx = i * 128 + tid;
            int row = fidx >> 5, c4 = fidx & 31;
            const float* gv = qkv + (size_t)(b * Sz + jc + row) * (3 * Dz) + 2 * Dz + h * HDz + c4 * 4;
            CP_ASYNC16(sm0 + (uint32_t)(AT_V_OFF(buf) + row * VSTR + c4 * 4) * 4, gv);
        }
        CP_COMMIT();
    };

    load_chunk(0, cs);

    for (int c = 0; c < nc; c++) {
        const int jc  = cs + c * 32;
        const int buf = c & 1;
        if (c + 1 < nc) { load_chunk((c + 1) & 1, jc + 32); CP_WAIT1(); }
        else            { CP_WAIT0(); }
        __syncthreads();

        const bool act = (jc <= qw + 15) && (jc + 31 >= qw - (WINz - 1));
        if (act) {
            const uint32_t* Ks = (const uint32_t*)(sm + AT_K_OFF(buf));
            const uint32_t* Vs = (const uint32_t*)(sm + AT_V_OFF(buf));

            float sc[4][4];
            #pragma unroll
            for (int ng = 0; ng < 4; ng++)
                #pragma unroll
                for (int e = 0; e < 4; e++) sc[ng][e] = 0.f;
            #pragma unroll
            for (int kg = 0; kg < 16; kg++) {
                #pragma unroll
                for (int ng = 0; ng < 4; ng++) {
                    const uint32_t* kp = Ks + (ng * 8 + gid) * KSTR + kg * 8 + tig;
                    mma_tf32(sc[ng][0], sc[ng][1], sc[ng][2], sc[ng][3],
                             qf[kg][0], qf[kg][1], qf[kg][2], qf[kg][3],
                             kp[0], kp[4]);
                }
            }

            const int q0r = qw + gid, q1r = qw + gid + 8;
            float smax0 = -1e30f, smax1 = -1e30f;
            #pragma unroll
            for (int ng = 0; ng < 4; ng++) {
                int j0 = jc + ng * 8 + tig * 2;
                smax0 = fmaxf(smax0, ((unsigned)(q0r - j0)     < 256u) ? sc[ng][0] : -1e30f);
                smax0 = fmaxf(smax0, ((unsigned)(q0r - j0 - 1) < 256u) ? sc[ng][1] : -1e30f);
                smax1 = fmaxf(smax1, ((unsigned)(q1r - j0)     < 256u) ? sc[ng][2] : -1e30f);
                smax1 = fmaxf(smax1, ((unsigned)(q1r - j0 - 1) < 256u) ? sc[ng][3] : -1e30f);
            }
            smax0 = fmaxf(smax0, __shfl_xor_sync(0xffffffffu, smax0, 1));
            smax0 = fmaxf(smax0, __shfl_xor_sync(0xffffffffu, smax0, 2));
            smax1 = fmaxf(smax1, __shfl_xor_sync(0xffffffffu, smax1, 1));
            smax1 = fmaxf(smax1, __shfl_xor_sync(0xffffffffu, smax1, 2));
            float m0n = fmaxf(m0, smax0), m1n = fmaxf(m1, smax1);
            float cr0 = __expf(m0 - m0n), cr1 = __expf(m1 - m1n);
            m0 = m0n; m1 = m1n;

            float ps0 = 0.f, ps1 = 0.f;
            #pragma unroll
            for (int ng = 0; ng < 4; ng++) {
                int j0 = jc + ng * 8 + tig * 2;
                float e;
                e = ((unsigned)(q0r - j0)     < 256u) ? __expf(sc[ng][0] - m0) : 0.f;
                sc[ng][0] = e; ps0 += e;
                e = ((unsigned)(q0r - j0 - 1) < 256u) ? __expf(sc[ng][1] - m0) : 0.f;
                sc[ng][1] = e; ps0 += e;
                e = ((unsigned)(q1r - j0)     < 256u) ? __expf(sc[ng][2] - m1) : 0.f;
                sc[ng][2] = e; ps1 += e;
                e = ((unsigned)(q1r - j0 - 1) < 256u) ? __expf(sc[ng][3] - m1) : 0.f;
                sc[ng][3] = e; ps1 += e;
            }
            ps0 += __shfl_xor_sync(0xffffffffu, ps0, 1);
            ps0 += __shfl_xor_sync(0xffffffffu, ps0, 2);
            ps1 += __shfl_xor_sync(0xffffffffu, ps1, 1);
            ps1 += __shfl_xor_sync(0xffffffffu, ps1, 2);
            l0 = l0 * cr0 + ps0;
            l1 = l1 * cr1 + ps1;

            #pragma unroll
            for (int dt = 0; dt < 16; dt++) {
                o[dt][0] *= cr0; o[dt][1] *= cr0;
                o[dt][2] *= cr1; o[dt][3] *= cr1;
            }

            uint32_t af[4][4];
            const int src  = (lane & ~3) | (tig >> 1);
            const int src2 = src + 2;
            #pragma unroll
            for (int ng = 0; ng < 4; ng++) {
                float v0 = __shfl_sync(0xffffffffu, sc[ng][0], src);
                float v1 = __shfl_sync(0xffffffffu, sc[ng][1], src);
                float v2 = __shfl_sync(0xffffffffu, sc[ng][2], src);
                float v3 = __shfl_sync(0xffffffffu, sc[ng][3], src);
                float w0 = __shfl_sync(0xffffffffu, sc[ng][0], src2);
                float w1 = __shfl_sync(0xffffffffu, sc[ng][1], src2);
                float w2 = __shfl_sync(0xffffffffu, sc[ng][2], src2);
                float w3 = __shfl_sync(0xffffffffu, sc[ng][3], src2);
                af[ng][0] = f2tf32((tig & 1) ? v1 : v0);
                af[ng][1] = f2tf32((tig & 1) ? v3 : v2);
                af[ng][2] = f2tf32((tig & 1) ? w1 : w0);
                af[ng][3] = f2tf32((tig & 1) ? w3 : w2);
            }

            #pragma unroll
            for (int dt = 0; dt < 16; dt++) {
                #pragma unroll
                for (int ng = 0; ng < 4; ng++) {
                    const uint32_t* vp = Vs + (ng * 8 + tig) * VSTR + dt * 8 + gid;
                    mma_tf32(o[dt][0], o[dt][1], o[dt][2], o[dt][3],
                             af[ng][0], af[ng][1], af[ng][2], af[ng][3],
                             vp[0], vp[4 * VSTR]);
                }
            }
        }
        __syncthreads();
    }

    // ---- write normalized output as fp16 (A operand of Wo GEMM) ----
    const float i0 = 1.f / l0, i1 = 1.f / l1;
    __half* y0 = y + (size_t)(b * Sz + qw + gid) * Dz + h * HDz;
    __half* y1 = y0 + (size_t)8 * Dz;
    #pragma unroll
    for (int dt = 0; dt < 16; dt++) {
        *(__half2*)(y0 + dt * 8 + tig * 2) = __floats2half2_rn(o[dt][0] * i0, o[dt][1] * i0);
        *(__half2*)(y1 + dt * 8 + tig * 2) = __floats2half2_rn(o[dt][2] * i1, o[dt][3] * i1);
    }
}

// ---------------- launch ----------------
extern "C" void kernel_launch(void* const* d_in, const int* in_sizes, int n_in,
                              void* d_out, int out_size)
{
    const float* x      = (const float*)d_in[0];
    const float* fc     = (const float*)d_in[1];
    // d_in[2] = mask (implicit: causal sliding window of 256)
    const float* wqkv_w = (const float*)d_in[3];
    const float* wqkv_b = (const float*)d_in[4];
    const float* wo_w   = (const float*)d_in[5];
    const float* wo_b   = (const float*)d_in[6];
    const float* qn_w   = (const float*)d_in[7];
    const float* kn_w   = (const float*)d_in[8];
    const float* aln_w  = (const float*)d_in[9];
    const float* aln_b  = (const float*)d_in[10];
    const float* fln_w  = (const float*)d_in[11];
    const float* fln_b  = (const float*)d_in[12];
    const float* w1_w   = (const float*)d_in[13];
    const float* w1_b   = (const float*)d_in[14];
    const float* w2_w   = (const float*)d_in[15];
    const float* w2_b   = (const float*)d_in[16];
    float* out = (float*)d_out;

    __half *nx, *f, *y, *ffn;
    float *qkv, *h;
    __half2 *wqkvH, *woH, *w1H, *w2H;
    cudaGetSymbolAddress((void**)&nx,    g_nx);
    cudaGetSymbolAddress((void**)&f,     g_f);
    cudaGetSymbolAddress((void**)&qkv,   g_qkv);
    cudaGetSymbolAddress((void**)&y,     g_y);
    cudaGetSymbolAddress((void**)&h,     g_h);
    cudaGetSymbolAddress((void**)&ffn,   g_ffn);
    cudaGetSymbolAddress((void**)&wqkvH, g_wqkvH);
    cudaGetSymbolAddress((void**)&woH,   g_woH);
    cudaGetSymbolAddress((void**)&w1H,   g_w1H);
    cudaGetSymbolAddress((void**)&w2H,   g_w2H);

    static int init_done = 0;
    static cudaStream_t s2;
    static cudaEvent_t ev0, ev1;
    if (!init_done) {
        cudaFuncSetAttribute(tc_gemm_kernel,
                             cudaFuncAttributeMaxDynamicSharedMemorySize, SM_TOTAL);
        cudaFuncSetAttribute(attn_mma_kernel,
                             cudaFuncAttributeMaxDynamicSharedMemorySize, AT_SMEM_BYTES);
        cudaStreamCreateWithFlags(&s2, cudaStreamNonBlocking);
        cudaEventCreateWithFlags(&ev0, cudaEventDisableTiming);
        cudaEventCreateWithFlags(&ev1, cudaEventDisableTiming);
        init_done = 1;
    }

    // ---- stream 0 (capture origin): prerequisites of both branches ----
    wconv_kernel<<<dim3(3 * Dz / 256, Dz / 2), 256>>>(wqkv_w, wqkvH, 3 * Dz);
    wconv_kernel<<<dim3(Dz / 256,     Dz / 2), 256>>>(wo_w,   woH,   Dz);
    ln_kernel<<<TOK, 256>>>(x, aln_w, aln_b, fln_w, fln_b, nx, f);
    cudaEventRecord(ev0, 0);

    // ---- stream s2: FFN branch (independent of attention chain) ----
    cudaStreamWaitEvent(s2, ev0, 0);
    wconv_kernel<<<dim3(FFz / 256, Dz / 2), 256, 0, s2>>>(w1_w, w1H, FFz);
    wconv_kernel<<<dim3(Dz / 256, FFz / 2), 256, 0, s2>>>(w2_w, w2H, Dz);
    tc_gemm_kernel<<<dim3(FFz / BN, TOK / BM), 128, SM_TOTAL, s2>>>(
        f, w1H, w1_b, nullptr, ffn, TOK, FFz, Dz, 1, 1);
    cudaEventRecord(ev1, s2);

    // ---- stream 0: attention chain ----
    tc_gemm_kernel<<<dim3(3 * Dz / BN, TOK / BM), 128, SM_TOTAL>>>(
        nx, wqkvH, wqkv_b, nullptr, qkv, TOK, 3 * Dz, Dz, 0, 0);
    qkrope_kernel<<<TOK * Hz, 384>>>(qkv, fc, qn_w, kn_w);
    attn_mma_kernel<<<Bz * Hz * (Sz / 64), 128, AT_SMEM_BYTES>>>(qkv, y);
    tc_gemm_kernel<<<dim3(Dz / BN, TOK / BM), 128, SM_TOTAL>>>(
        y, woH, wo_b, x, h, TOK, Dz, Dz, 0, 0);

    // ---- join: FFN2 needs ffn (s2) + h (stream 0) ----
    cudaStreamWaitEvent(0, ev1, 0);
    tc_gemm_kernel<<<dim3(Dz / BN, TOK / BM), 128, SM_TOTAL>>>(
        ffn, w2H, w2_b, h, out, TOK, Dz, FFz, 0, 0);
}

// round 13
// speedup vs baseline: 6.0239x; 1.0381x over previous
#include <cuda_runtime.h>
#include <cuda_fp16.h>
#include <cuda_bf16.h>
#include <math.h>
#include <stdint.h>

// ---------------- problem constants ----------------
#define Bz   2
#define Sz   2048
#define Dz   2048
#define Hz   16
#define HDz  128
#define RNz  32
#define FFz  4096
#define WINz 256
#define TOK  (Bz*Sz)          // 4096 tokens
#define EPSF 1e-5f
#define SCALEF 0.08838834764831845f   // 1/sqrt(128)

// ---------------- scratch (device globals; no allocation allowed) ----------------
__device__ __half  g_nx  [TOK*Dz];      // fp16 LN output (attn branch)
__device__ __half  g_f   [TOK*Dz];      // fp16 LN output (ffn branch)
__device__ float   g_qkv [TOK*3*Dz];    // fp32; q,k,v tf32-rounded after qkrope
__device__ __half  g_y   [TOK*Dz];      // fp16 attention output
__device__ float   g_h   [TOK*Dz];      // fp32 residual stream (x + attn_out)
__device__ __half  g_ffn [TOK*FFz];     // fp16 gelu(f@w1+b1)
__device__ float   g_ffo [TOK*Dz];      // fp32 ffn tower output (pre-residual)
// fp16 weights, k-pair-interleaved: Wh[kp][n] = half2(W[2kp][n], W[2kp+1][n])
__device__ __half2 g_wqkvH[(Dz/2)*3*Dz];
__device__ __half2 g_woH  [(Dz/2)*Dz];
__device__ __half2 g_w1H  [(Dz/2)*FFz];
__device__ __half2 g_w2H  [(FFz/2)*Dz];

// ======================= helpers =======================
__device__ __forceinline__ uint32_t smem_u32(const void* p) {
    uint32_t a;
    asm("{ .reg .u64 t; cvta.to.shared.u64 t, %1; cvt.u32.u64 %0, t; }" : "=r"(a) : "l"(p));
    return a;
}
#define CP_ASYNC16(smem, gptr) \
    asm volatile("cp.async.cg.shared.global [%0], [%1], 16;" :: "r"(smem), "l"(gptr))
#define CP_COMMIT()  asm volatile("cp.async.commit_group;" ::: "memory")
#define CP_WAIT0()   asm volatile("cp.async.wait_group 0;" ::: "memory")
#define CP_WAIT1()   asm volatile("cp.async.wait_group 1;" ::: "memory")
#define CP_WAIT2()   asm volatile("cp.async.wait_group 2;" ::: "memory")

__device__ __forceinline__ uint32_t f2tf32(float x) {
    uint32_t r;
    asm("cvt.rna.tf32.f32 %0, %1;" : "=r"(r) : "f"(x));
    return r;
}
__device__ __forceinline__ float tf32v(float x) {
    return __uint_as_float(f2tf32(x));
}
// tf32 mma (attention only)
__device__ __forceinline__ void mma_tf32(float& c0, float& c1, float& c2, float& c3,
                                         uint32_t a0, uint32_t a1, uint32_t a2, uint32_t a3,
                                         uint32_t b0, uint32_t b1) {
    asm volatile(
        "mma.sync.aligned.m16n8k8.row.col.f32.tf32.tf32.f32 "
        "{%0,%1,%2,%3}, {%4,%5,%6,%7}, {%8,%9}, {%0,%1,%2,%3};"
        : "+f"(c0), "+f"(c1), "+f"(c2), "+f"(c3)
        : "r"(a0), "r"(a1), "r"(a2), "r"(a3), "r"(b0), "r"(b1));
}
// fp16 mma (GEMMs)
__device__ __forceinline__ void mma_f16(float& c0, float& c1, float& c2, float& c3,
                                        uint32_t a0, uint32_t a1, uint32_t a2, uint32_t a3,
                                        uint32_t b0, uint32_t b1) {
    asm volatile(
        "mma.sync.aligned.m16n8k16.row.col.f32.f16.f16.f32 "
        "{%0,%1,%2,%3}, {%4,%5,%6,%7}, {%8,%9}, {%0,%1,%2,%3};"
        : "+f"(c0), "+f"(c1), "+f"(c2), "+f"(c3)
        : "r"(a0), "r"(a1), "r"(a2), "r"(a3), "r"(b0), "r"(b1));
}

// ======================= weight fp16 pack: W[K,N] fp32 -> Wh[K/2,N] half2 =======================
__global__ void wconv_kernel(const float* __restrict__ W, __half2* __restrict__ Wh, int N) {
    int n  = blockIdx.x * 256 + threadIdx.x;
    int kp = blockIdx.y;
    float lo = W[(size_t)(2 * kp)     * N + n];
    float hi = W[(size_t)(2 * kp + 1) * N + n];
    Wh[(size_t)kp * N + n] = __floats2half2_rn(lo, hi);
}

// ======================= final residual join: out = a + b =======================
__global__ void add_kernel(const float* __restrict__ a, const float* __restrict__ b,
                           float* __restrict__ o) {
    int i = blockIdx.x * 256 + threadIdx.x;
    float4 va = ((const float4*)a)[i];
    float4 vb = ((const float4*)b)[i];
    ((float4*)o)[i] = make_float4(va.x + vb.x, va.y + vb.y, va.z + vb.z, va.w + vb.w);
}

// ======================= fp16 mma.sync GEMM =======================
// C[M,N] = A[M,K] @ W[K,N]  (+bias fp32, +gelu?, +res fp32?, out fp32 or fp16)
// A fp16 [M,K]; W pre-packed half2 [K/2,N].
// CTA 128x128, 128 threads = 4 warps (2x2), warp tile 64x64, BK=32, 3-stage cp.async.
#define BM 128
#define BN 128
#define BK 32
#define AE 20                            // A row stride, half2 entries (80 B, bank perm 20*gid+tig)
#define BE 132                           // B row stride, half2 entries (528 B, bank perm 4*tig+gid)
#define A_ENT (BM * AE)                  // 2560
#define B_ENT (16 * BE)                  // 2112
#define STG_ENT (A_ENT + B_ENT)          // 4672 entries = 18688 B
#define STAGES 3
#define SM_TOTAL (STAGES * STG_ENT * 4)  // 56064 bytes

__global__ __launch_bounds__(128, 2)
void tc_gemm_kernel(const __half* __restrict__ A, const __half2* __restrict__ Wh,
                    const float* __restrict__ bias, const float* __restrict__ res,
                    void* __restrict__ Cv, int M, int N, int K, int do_gelu, int out_half)
{
    extern __shared__ uint32_t smem[];
    const uint32_t sm0 = smem_u32(smem);
    const int tid  = threadIdx.x;
    const int wid  = tid >> 5;
    const int lane = tid & 31;
    const int gid  = lane >> 2;
    const int tig  = lane & 3;
    const int wm   = wid >> 1;          // 0..1: 64-row slab
    const int wn   = wid & 1;           // 0..1: 64-col slab
    const int row0 = blockIdx.y * BM;
    const int col0 = blockIdx.x * BN;

    float acc[4][8][4];
    #pragma unroll
    for (int mi = 0; mi < 4; mi++)
        #pragma unroll
        for (int ni = 0; ni < 8; ni++)
            #pragma unroll
            for (int e = 0; e < 4; e++) acc[mi][ni][e] = 0.f;

    const int niter = K >> 5;

    // loader: 1024 16B-chunks per stage (512 A + 512 B), 8 per thread
    auto load_stage = [&](int buf, int iter) {
        const int k0  = iter << 5;      // halves
        const int kp0 = iter << 4;      // half2 k-pair rows
        const uint32_t sb = sm0 + (uint32_t)buf * (STG_ENT * 4);
        #pragma unroll
        for (int t = 0; t < 8; t++) {
            int c = tid + t * 128;
            const void* g;
            uint32_t s;
            if (c < 512) {                        // A: 128 rows x 4 chunks (32 halves/row)
                int row = c >> 2, ch = c & 3;
                g = A + (size_t)(row0 + row) * K + k0 + ch * 8;
                s = sb + (uint32_t)(row * 80 + ch * 16);
            } else {                              // B: 16 kp-rows x 32 chunks (128 half2/row)
                int cc = c - 512;
                int row = cc >> 5, c4 = cc & 31;
                g = Wh + (size_t)(kp0 + row) * N + col0 + c4 * 4;
                s = sb + (uint32_t)(A_ENT * 4 + row * 528 + c4 * 16);
            }
            CP_ASYNC16(s, g);
        }
        CP_COMMIT();
    };

    if (0 < niter) { load_stage(0, 0); }
    if (1 < niter) { load_stage(1, 1); }

    for (int i = 0; i < niter; i++) {
        if (i + 2 < niter) load_stage((i + 2) % STAGES, i + 2);
        if (i + 2 < niter)      { CP_WAIT2(); }
        else if (i + 1 < niter) { CP_WAIT1(); }
        else                    { CP_WAIT0(); }
        __syncthreads();

        const uint32_t* sA = smem + (i % STAGES) * STG_ENT;
        const uint32_t* sB = sA + A_ENT;
        const uint32_t* pa = sA + (wm * 64 + gid) * AE + tig;
        const uint32_t* pb = sB + tig * BE + wn * 64 + gid;

        #pragma unroll
        for (int s = 0; s < 2; s++) {           // two k16 steps per BK=32
            uint32_t bfr[8][2];
            #pragma unroll
            for (int ni = 0; ni < 8; ni++) {
                bfr[ni][0] = pb[(s * 8)     * BE + ni * 8];
                bfr[ni][1] = pb[(s * 8 + 4) * BE + ni * 8];
            }
            #pragma unroll
            for (int mi = 0; mi < 4; mi++) {
                const uint32_t* p = pa + mi * 16 * AE + s * 8;
                uint32_t a0 = p[0];
                uint32_t a1 = p[8 * AE];
                uint32_t a2 = p[4];
                uint32_t a3 = p[8 * AE + 4];
                #pragma unroll
                for (int ni = 0; ni < 8; ni++)
                    mma_f16(acc[mi][ni][0], acc[mi][ni][1], acc[mi][ni][2], acc[mi][ni][3],
                            a0, a1, a2, a3, bfr[ni][0], bfr[ni][1]);
            }
        }
        __syncthreads();
    }

    // ---------------- epilogue ----------------
    #pragma unroll
    for (int mi = 0; mi < 4; mi++) {
        #pragma unroll
        for (int half = 0; half < 2; half++) {
            const size_t r = (size_t)(row0 + wm * 64 + mi * 16 + gid + half * 8);
            #pragma unroll
            for (int ni = 0; ni < 8; ni++) {
                const int cc = col0 + wn * 64 + ni * 8 + tig * 2;
                float v0 = acc[mi][ni][half * 2 + 0] + bias[cc];
                float v1 = acc[mi][ni][half * 2 + 1] + bias[cc + 1];
                if (do_gelu) {
                    v0 = 0.5f * v0 * (1.f + erff(v0 * 0.70710678118654752f));
                    v1 = 0.5f * v1 * (1.f + erff(v1 * 0.70710678118654752f));
                }
                if (res) {
                    float2 rr = *(const float2*)&res[r * N + cc];
                    v0 += rr.x; v1 += rr.y;
                }
                if (out_half) {
                    *(__half2*)((__half*)Cv + r * N + cc) = __floats2half2_rn(v0, v1);
                } else {
                    *(float2*)((float*)Cv + r * N + cc) = make_float2(v0, v1);
                }
            }
        }
    }
}

// ---------------- fused double LayerNorm (fp16 outputs) ----------------
__global__ void ln_kernel(const float* __restrict__ x,
                          const float* __restrict__ aw, const float* __restrict__ ab,
                          const float* __restrict__ fw, const float* __restrict__ fb,
                          __half* __restrict__ nx, __half* __restrict__ f)
{
    int row = blockIdx.x;
    int tid = threadIdx.x;
    const float4* xr = (const float4*)(x + (size_t)row * Dz);
    float4 a = xr[tid];
    float4 b = xr[tid + 256];
    float s  = a.x + a.y + a.z + a.w + b.x + b.y + b.z + b.w;
    float ss = a.x*a.x + a.y*a.y + a.z*a.z + a.w*a.w
             + b.x*b.x + b.y*b.y + b.z*b.z + b.w*b.w;
    #pragma unroll
    for (int o = 16; o; o >>= 1) {
        s  += __shfl_xor_sync(0xffffffffu, s,  o);
        ss += __shfl_xor_sync(0xffffffffu, ss, o);
    }
    __shared__ float r1[8], r2[8];
    __shared__ float mv[2];
    int wid = tid >> 5;
    if ((tid & 31) == 0) { r1[wid] = s; r2[wid] = ss; }
    __syncthreads();
    if (tid == 0) {
        float S = 0.f, SS = 0.f;
        #pragma unroll
        for (int i = 0; i < 8; i++) { S += r1[i]; SS += r2[i]; }
        float m   = S * (1.f / Dz);
        float var = SS * (1.f / Dz) - m * m;
        mv[0] = m;
        mv[1] = rsqrtf(var + EPSF);
    }
    __syncthreads();
    float m = mv[0], r = mv[1];

    __half* nxr = nx + (size_t)row * Dz;
    __half* fr  = f  + (size_t)row * Dz;
    const float4* aw4 = (const float4*)aw;  const float4* ab4 = (const float4*)ab;
    const float4* fw4 = (const float4*)fw;  const float4* fb4 = (const float4*)fb;
    #pragma unroll
    for (int e = 0; e < 2; e++) {
        int slot = tid + e * 256;
        float4 v = (e == 0) ? a : b;
        float4 w1 = aw4[slot], b1 = ab4[slot], w2 = fw4[slot], b2 = fb4[slot];
        __half2 h0 = __floats2half2_rn((v.x - m) * r * w1.x + b1.x, (v.y - m) * r * w1.y + b1.y);
        __half2 h1 = __floats2half2_rn((v.z - m) * r * w1.z + b1.z, (v.w - m) * r * w1.w + b1.w);
        __half2 g0 = __floats2half2_rn((v.x - m) * r * w2.x + b2.x, (v.y - m) * r * w2.y + b2.y);
        __half2 g1 = __floats2half2_rn((v.z - m) * r * w2.z + b2.z, (v.w - m) * r * w2.w + b2.w);
        *(__half2*)(nxr + slot * 4)     = h0;
        *(__half2*)(nxr + slot * 4 + 2) = h1;
        *(__half2*)(fr  + slot * 4)     = g0;
        *(__half2*)(fr  + slot * 4 + 2) = g1;
    }
}

// ---------------- per-head RMS norm + RoPE + q scaling + tf32 round (q,k,v), fp32 in place ----------------
__global__ void qkrope_kernel(float* __restrict__ qkv, const float* __restrict__ fc,
                              const float* __restrict__ qn_w, const float* __restrict__ kn_w)
{
    int blk   = blockIdx.x;
    int token = blk >> 4;
    int h     = blk & 15;
    int s     = token & (Sz - 1);
    int sel   = threadIdx.x >> 7;       // 0=q, 1=k, 2=v
    int d     = threadIdx.x & 127;
    float* ptr = qkv + (size_t)token * (3 * Dz) + sel * Dz + h * HDz;
    float v = ptr[d];
    float ss = v * v;
    #pragma unroll
    for (int o = 16; o; o >>= 1) ss += __shfl_xor_sync(0xffffffffu, ss, o);
    __shared__ float red[12];
    __shared__ float rstd_s[2];
    int wid = threadIdx.x >> 5;
    if ((threadIdx.x & 31) == 0) red[wid] = ss;
    __syncthreads();
    if (d == 0 && sel < 2) {
        float t = red[sel * 4] + red[sel * 4 + 1] + red[sel * 4 + 2] + red[sel * 4 + 3];
        rstd_s[sel] = rsqrtf(t * (1.f / HDz) + EPSF);
    }
    __syncthreads();
    if (sel == 2) {                     // v: tf32-round in place
        ptr[d] = tf32v(v);
        return;
    }
    float rstd = rstd_s[sel];
    float w = sel ? kn_w[d] : qn_w[d];
    float nv = v * rstd * w;
    if (d < RNz) {
        int j = d >> 1;
        float c  = fc[(s * 16 + j) * 2];
        float sn = fc[(s * 16 + j) * 2 + 1];
        float a = __shfl_sync(0xffffffffu, nv, j);
        float b = __shfl_sync(0xffffffffu, nv, j + 16);
        nv = (d & 1) ? (b * c + a * sn) : (a * c - b * sn);
    }
    if (sel == 0) nv *= SCALEF;
    ptr[d] = tf32v(nv);
}

// ======================= FA2-style windowed attention (tf32 mma, fp32 qkv, fp16 y out) =======================
#define AT_CK 32
#define KSTR 132
#define VSTR 136
#define AT_K_OFF(buf) ((buf) * (AT_CK * KSTR))
#define AT_V_OFF(buf) (2 * AT_CK * KSTR + (buf) * (AT_CK * VSTR))
#define AT_SMEM_FLOATS (2 * AT_CK * KSTR + 2 * AT_CK * VSTR)   // 17152
#define AT_SMEM_BYTES  (AT_SMEM_FLOATS * 4)                     // 68608

__global__ __launch_bounds__(128, 2)
void attn_mma_kernel(const float* __restrict__ qkv, __half* __restrict__ y)
{
    extern __shared__ float sm[];
    const uint32_t sm0 = smem_u32(sm);
    const int tid  = threadIdx.x;
    const int wi   = tid >> 5;
    const int lane = tid & 31;
    const int gid  = lane >> 2;
    const int tig  = lane & 3;
    const int qb0  = (blockIdx.x & 31) << 6;
    const int h    = (blockIdx.x >> 5) & 15;
    const int b    = blockIdx.x >> 9;
    const int qw   = qb0 + wi * 16;

    uint32_t qf[16][4];
    {
        const float* q0 = qkv + (size_t)(b * Sz + qw + gid) * (3 * Dz) + h * HDz;
        const float* q1 = q0 + (size_t)8 * (3 * Dz);
        #pragma unroll
        for (int kg = 0; kg < 16; kg++) {
            qf[kg][0] = __float_as_uint(q0[kg * 8 + tig]);
            qf[kg][1] = __float_as_uint(q1[kg * 8 + tig]);
            qf[kg][2] = __float_as_uint(q0[kg * 8 + tig + 4]);
            qf[kg][3] = __float_as_uint(q1[kg * 8 + tig + 4]);
        }
    }

    float o[16][4];
    #pragma unroll
    for (int dt = 0; dt < 16; dt++)
        #pragma unroll
        for (int e = 0; e < 4; e++) o[dt][e] = 0.f;
    float m0 = -1e30f, m1 = -1e30f, l0 = 0.f, l1 = 0.f;

    int cs = qb0 - (WINz - 1); if (cs < 0) cs = 0;
    cs &= ~31;
    const int nc = ((qb0 + 63 - cs) >> 5) + 1;

    auto load_chunk = [&](int buf, int jc) {
        #pragma unroll
        for (int i = 0; i < 8; i++) {
            int fidx = i * 128 + tid;
            int row = fidx >> 5, c4 = fidx & 31;
            const float* gk = qkv + (size_t)(b * Sz + jc + row) * (3 * Dz) + Dz + h * HDz + c4 * 4;
            CP_ASYNC16(sm0 + (uint32_t)(AT_K_OFF(buf) + row * KSTR + c4 * 4) * 4, gk);
        }
        #pragma unroll
        for (int i = 0; i < 8; i++) {
            int fidx = i * 128 + tid;
            int row = fidx >> 5, c4 = fidx & 31;
            const float* gv = qkv + (size_t)(b * Sz + jc + row) * (3 * Dz) + 2 * Dz + h * HDz + c4 * 4;
            CP_ASYNC16(sm0 + (uint32_t)(AT_V_OFF(buf) + row * VSTR + c4 * 4) * 4, gv);
        }
        CP_COMMIT();
    };

    load_chunk(0, cs);

    for (int c = 0; c < nc; c++) {
        const int jc  = cs + c * 32;
        const int buf = c & 1;
        if (c + 1 < nc) { load_chunk((c + 1) & 1, jc + 32); CP_WAIT1(); }
        else            { CP_WAIT0(); }
        __syncthreads();

        const bool act = (jc <= qw + 15) && (jc + 31 >= qw - (WINz - 1));
        if (act) {
            const uint32_t* Ks = (const uint32_t*)(sm + AT_K_OFF(buf));
            const uint32_t* Vs = (const uint32_t*)(sm + AT_V_OFF(buf));

            float sc[4][4];
            #pragma unroll
            for (int ng = 0; ng < 4; ng++)
                #pragma unroll
                for (int e = 0; e < 4; e++) sc[ng][e] = 0.f;
            #pragma unroll
            for (int kg = 0; kg < 16; kg++) {
                #pragma unroll
                for (int ng = 0; ng < 4; ng++) {
                    const uint32_t* kp = Ks + (ng * 8 + gid) * KSTR + kg * 8 + tig;
                    mma_tf32(sc[ng][0], sc[ng][1], sc[ng][2], sc[ng][3],
                             qf[kg][0], qf[kg][1], qf[kg][2], qf[kg][3],
                             kp[0], kp[4]);
                }
            }

            const int q0r = qw + gid, q1r = qw + gid + 8;
            float smax0 = -1e30f, smax1 = -1e30f;
            #pragma unroll
            for (int ng = 0; ng < 4; ng++) {
                int j0 = jc + ng * 8 + tig * 2;
                smax0 = fmaxf(smax0, ((unsigned)(q0r - j0)     < 256u) ? sc[ng][0] : -1e30f);
                smax0 = fmaxf(smax0, ((unsigned)(q0r - j0 - 1) < 256u) ? sc[ng][1] : -1e30f);
                smax1 = fmaxf(smax1, ((unsigned)(q1r - j0)     < 256u) ? sc[ng][2] : -1e30f);
                smax1 = fmaxf(smax1, ((unsigned)(q1r - j0 - 1) < 256u) ? sc[ng][3] : -1e30f);
            }
            smax0 = fmaxf(smax0, __shfl_xor_sync(0xffffffffu, smax0, 1));
            smax0 = fmaxf(smax0, __shfl_xor_sync(0xffffffffu, smax0, 2));
            smax1 = fmaxf(smax1, __shfl_xor_sync(0xffffffffu, smax1, 1));
            smax1 = fmaxf(smax1, __shfl_xor_sync(0xffffffffu, smax1, 2));
            float m0n = fmaxf(m0, smax0), m1n = fmaxf(m1, smax1);
            float cr0 = __expf(m0 - m0n), cr1 = __expf(m1 - m1n);
            m0 = m0n; m1 = m1n;

            float ps0 = 0.f, ps1 = 0.f;
            #pragma unroll
            for (int ng = 0; ng < 4; ng++) {
                int j0 = jc + ng * 8 + tig * 2;
                float e;
                e = ((unsigned)(q0r - j0)     < 256u) ? __expf(sc[ng][0] - m0) : 0.f;
                sc[ng][0] = e; ps0 += e;
                e = ((unsigned)(q0r - j0 - 1) < 256u) ? __expf(sc[ng][1] - m0) : 0.f;
                sc[ng][1] = e; ps0 += e;
                e = ((unsigned)(q1r - j0)     < 256u) ? __expf(sc[ng][2] - m1) : 0.f;
                sc[ng][2] = e; ps1 += e;
                e = ((unsigned)(q1r - j0 - 1) < 256u) ? __expf(sc[ng][3] - m1) : 0.f;
                sc[ng][3] = e; ps1 += e;
            }
            ps0 += __shfl_xor_sync(0xffffffffu, ps0, 1);
            ps0 += __shfl_xor_sync(0xffffffffu, ps0, 2);
            ps1 += __shfl_xor_sync(0xffffffffu, ps1, 1);
            ps1 += __shfl_xor_sync(0xffffffffu, ps1, 2);
            l0 = l0 * cr0 + ps0;
            l1 = l1 * cr1 + ps1;

            #pragma unroll
            for (int dt = 0; dt < 16; dt++) {
                o[dt][0] *= cr0; o[dt][1] *= cr0;
                o[dt][2] *= cr1; o[dt][3] *= cr1;
            }

            uint32_t af[4][4];
            const int src  = (lane & ~3) | (tig >> 1);
            const int src2 = src + 2;
            #pragma unroll
            for (int ng = 0; ng < 4; ng++) {
                float v0 = __shfl_sync(0xffffffffu, sc[ng][0], src);
                float v1 = __shfl_sync(0xffffffffu, sc[ng][1], src);
                float v2 = __shfl_sync(0xffffffffu, sc[ng][2], src);
                float v3 = __shfl_sync(0xffffffffu, sc[ng][3], src);
                float w0 = __shfl_sync(0xffffffffu, sc[ng][0], src2);
                float w1 = __shfl_sync(0xffffffffu, sc[ng][1], src2);
                float w2 = __shfl_sync(0xffffffffu, sc[ng][2], src2);
                float w3 = __shfl_sync(0xffffffffu, sc[ng][3], src2);
                af[ng][0] = f2tf32((tig & 1) ? v1 : v0);
                af[ng][1] = f2tf32((tig & 1) ? v3 : v2);
                af[ng][2] = f2tf32((tig & 1) ? w1 : w0);
                af[ng][3] = f2tf32((tig & 1) ? w3 : w2);
            }

            #pragma unroll
            for (int dt = 0; dt < 16; dt++) {
                #pragma unroll
                for (int ng = 0; ng < 4; ng++) {
                    const uint32_t* vp = Vs + (ng * 8 + tig) * VSTR + dt * 8 + gid;
                    mma_tf32(o[dt][0], o[dt][1], o[dt][2], o[dt][3],
                             af[ng][0], af[ng][1], af[ng][2], af[ng][3],
                             vp[0], vp[4 * VSTR]);
                }
            }
        }
        __syncthreads();
    }

    // ---- write normalized output as fp16 (A operand of Wo GEMM) ----
    const float i0 = 1.f / l0, i1 = 1.f / l1;
    __half* y0 = y + (size_t)(b * Sz + qw + gid) * Dz + h * HDz;
    __half* y1 = y0 + (size_t)8 * Dz;
    #pragma unroll
    for (int dt = 0; dt < 16; dt++) {
        *(__half2*)(y0 + dt * 8 + tig * 2) = __floats2half2_rn(o[dt][0] * i0, o[dt][1] * i0);
        *(__half2*)(y1 + dt * 8 + tig * 2) = __floats2half2_rn(o[dt][2] * i1, o[dt][3] * i1);
    }
}

// ---------------- launch ----------------
extern "C" void kernel_launch(void* const* d_in, const int* in_sizes, int n_in,
                              void* d_out, int out_size)
{
    const float* x      = (const float*)d_in[0];
    const float* fc     = (const float*)d_in[1];
    // d_in[2] = mask (implicit: causal sliding window of 256)
    const float* wqkv_w = (const float*)d_in[3];
    const float* wqkv_b = (const float*)d_in[4];
    const float* wo_w   = (const float*)d_in[5];
    const float* wo_b   = (const float*)d_in[6];
    const float* qn_w   = (const float*)d_in[7];
    const float* kn_w   = (const float*)d_in[8];
    const float* aln_w  = (const float*)d_in[9];
    const float* aln_b  = (const float*)d_in[10];
    const float* fln_w  = (const float*)d_in[11];
    const float* fln_b  = (const float*)d_in[12];
    const float* w1_w   = (const float*)d_in[13];
    const float* w1_b   = (const float*)d_in[14];
    const float* w2_w   = (const float*)d_in[15];
    const float* w2_b   = (const float*)d_in[16];
    float* out = (float*)d_out;

    __half *nx, *f, *y, *ffn;
    float *qkv, *h, *ffo;
    __half2 *wqkvH, *woH, *w1H, *w2H;
    cudaGetSymbolAddress((void**)&nx,    g_nx);
    cudaGetSymbolAddress((void**)&f,     g_f);
    cudaGetSymbolAddress((void**)&qkv,   g_qkv);
    cudaGetSymbolAddress((void**)&y,     g_y);
    cudaGetSymbolAddress((void**)&h,     g_h);
    cudaGetSymbolAddress((void**)&ffn,   g_ffn);
    cudaGetSymbolAddress((void**)&ffo,   g_ffo);
    cudaGetSymbolAddress((void**)&wqkvH, g_wqkvH);
    cudaGetSymbolAddress((void**)&woH,   g_woH);
    cudaGetSymbolAddress((void**)&w1H,   g_w1H);
    cudaGetSymbolAddress((void**)&w2H,   g_w2H);

    static int init_done = 0;
    static cudaStream_t s2;
    static cudaEvent_t ev0, ev1;
    if (!init_done) {
        cudaFuncSetAttribute(tc_gemm_kernel,
                             cudaFuncAttributeMaxDynamicSharedMemorySize, SM_TOTAL);
        cudaFuncSetAttribute(attn_mma_kernel,
                             cudaFuncAttributeMaxDynamicSharedMemorySize, AT_SMEM_BYTES);
        cudaStreamCreateWithFlags(&s2, cudaStreamNonBlocking);
        cudaEventCreateWithFlags(&ev0, cudaEventDisableTiming);
        cudaEventCreateWithFlags(&ev1, cudaEventDisableTiming);
        init_done = 1;
    }

    // ---- stream 0 (capture origin): prerequisites of both branches ----
    wconv_kernel<<<dim3(3 * Dz / 256, Dz / 2), 256>>>(wqkv_w, wqkvH, 3 * Dz);
    wconv_kernel<<<dim3(Dz / 256,     Dz / 2), 256>>>(wo_w,   woH,   Dz);
    ln_kernel<<<TOK, 256>>>(x, aln_w, aln_b, fln_w, fln_b, nx, f);
    cudaEventRecord(ev0, 0);

    // ---- stream s2: the ENTIRE FFN tower (independent of attention chain) ----
    cudaStreamWaitEvent(s2, ev0, 0);
    wconv_kernel<<<dim3(FFz / 256, Dz / 2), 256, 0, s2>>>(w1_w, w1H, FFz);
    wconv_kernel<<<dim3(Dz / 256, FFz / 2), 256, 0, s2>>>(w2_w, w2H, Dz);
    tc_gemm_kernel<<<dim3(FFz / BN, TOK / BM), 128, SM_TOTAL, s2>>>(
        f, w1H, w1_b, nullptr, ffn, TOK, FFz, Dz, 1, 1);
    tc_gemm_kernel<<<dim3(Dz / BN, TOK / BM), 128, SM_TOTAL, s2>>>(
        ffn, w2H, w2_b, nullptr, ffo, TOK, Dz, FFz, 0, 0);
    cudaEventRecord(ev1, s2);

    // ---- stream 0: attention chain ----
    tc_gemm_kernel<<<dim3(3 * Dz / BN, TOK / BM), 128, SM_TOTAL>>>(
        nx, wqkvH, wqkv_b, nullptr, qkv, TOK, 3 * Dz, Dz, 0, 0);
    qkrope_kernel<<<TOK * Hz, 384>>>(qkv, fc, qn_w, kn_w);
    attn_mma_kernel<<<Bz * Hz * (Sz / 64), 128, AT_SMEM_BYTES>>>(qkv, y);
    tc_gemm_kernel<<<dim3(Dz / BN, TOK / BM), 128, SM_TOTAL>>>(
        y, woH, wo_b, x, h, TOK, Dz, Dz, 0, 0);

    // ---- join: out = h + ffo ----
    cudaStreamWaitEvent(0, ev1, 0);
    add_kernel<<<(TOK * Dz / 4) / 256, 256>>>(h, ffo, out);
}

// round 15
// speedup vs baseline: 6.2351x; 1.0351x over previous
#include <cuda_runtime.h>
#include <cuda_fp16.h>
#include <cuda_bf16.h>
#include <math.h>
#include <stdint.h>

// ---------------- problem constants ----------------
#define Bz   2
#define Sz   2048
#define Dz   2048
#define Hz   16
#define HDz  128
#define RNz  32
#define FFz  4096
#define WINz 256
#define TOK  (Bz*Sz)          // 4096 tokens
#define EPSF 1e-5f
#define SCALEF 0.08838834764831845f   // 1/sqrt(128)

// ---------------- scratch (device globals; no allocation allowed) ----------------
__device__ __half  g_nx  [TOK*Dz];      // fp16 LN output (attn branch)
__device__ __half  g_f   [TOK*Dz];      // fp16 LN output (ffn branch)
__device__ float   g_qkv [TOK*3*Dz];    // fp32; q,k tf32-rounded after qkrope; v raw
__device__ __half  g_y   [TOK*Dz];      // fp16 attention output
__device__ float   g_h   [TOK*Dz];      // fp32 residual stream (x + attn_out)
__device__ __half  g_ffn [TOK*FFz];     // fp16 gelu(f@w1+b1)
__device__ float   g_ffo [TOK*Dz];      // fp32 ffn tower output (pre-residual)
// fp16 weights, k-pair-interleaved: Wh[kp][n] = half2(W[2kp][n], W[2kp+1][n])
__device__ __half2 g_wqkvH[(Dz/2)*3*Dz];
__device__ __half2 g_woH  [(Dz/2)*Dz];
__device__ __half2 g_w1H  [(Dz/2)*FFz];
__device__ __half2 g_w2H  [(FFz/2)*Dz];

// ======================= helpers =======================
__device__ __forceinline__ uint32_t smem_u32(const void* p) {
    uint32_t a;
    asm("{ .reg .u64 t; cvta.to.shared.u64 t, %1; cvt.u32.u64 %0, t; }" : "=r"(a) : "l"(p));
    return a;
}
#define CP_ASYNC16(smem, gptr) \
    asm volatile("cp.async.cg.shared.global [%0], [%1], 16;" :: "r"(smem), "l"(gptr))
#define CP_COMMIT()  asm volatile("cp.async.commit_group;" ::: "memory")
#define CP_WAIT0()   asm volatile("cp.async.wait_group 0;" ::: "memory")
#define CP_WAIT1()   asm volatile("cp.async.wait_group 1;" ::: "memory")
#define CP_WAIT2()   asm volatile("cp.async.wait_group 2;" ::: "memory")

__device__ __forceinline__ uint32_t f2tf32(float x) {
    uint32_t r;
    asm("cvt.rna.tf32.f32 %0, %1;" : "=r"(r) : "f"(x));
    return r;
}
__device__ __forceinline__ float tf32v(float x) {
    return __uint_as_float(f2tf32(x));
}
// tf32 mma (attention only)
__device__ __forceinline__ void mma_tf32(float& c0, float& c1, float& c2, float& c3,
                                         uint32_t a0, uint32_t a1, uint32_t a2, uint32_t a3,
                                         uint32_t b0, uint32_t b1) {
    asm volatile(
        "mma.sync.aligned.m16n8k8.row.col.f32.tf32.tf32.f32 "
        "{%0,%1,%2,%3}, {%4,%5,%6,%7}, {%8,%9}, {%0,%1,%2,%3};"
        : "+f"(c0), "+f"(c1), "+f"(c2), "+f"(c3)
        : "r"(a0), "r"(a1), "r"(a2), "r"(a3), "r"(b0), "r"(b1));
}
// fp16 mma (GEMMs)
__device__ __forceinline__ void mma_f16(float& c0, float& c1, float& c2, float& c3,
                                        uint32_t a0, uint32_t a1, uint32_t a2, uint32_t a3,
                                        uint32_t b0, uint32_t b1) {
    asm volatile(
        "mma.sync.aligned.m16n8k16.row.col.f32.f16.f16.f32 "
        "{%0,%1,%2,%3}, {%4,%5,%6,%7}, {%8,%9}, {%0,%1,%2,%3};"
        : "+f"(c0), "+f"(c1), "+f"(c2), "+f"(c3)
        : "r"(a0), "r"(a1), "r"(a2), "r"(a3), "r"(b0), "r"(b1));
}

// ======================= merged weight fp16 pack (all 4 weights, one launch) =======================
// Wh[kp][n] = half2(W[2kp][n], W[2kp+1][n]); flat index j over [K/2 * N); base = 2j - n.
#define WE0 (1024*6144)     // wqkv
#define WE1 (1024*2048)     // wo
#define WE2 (1024*4096)     // w1
#define WE3 (2048*2048)     // w2
__global__ void wconv_all_kernel(const float* __restrict__ w0, const float* __restrict__ w1,
                                 const float* __restrict__ w2, const float* __restrict__ w3,
                                 __half2* __restrict__ o0, __half2* __restrict__ o1,
                                 __half2* __restrict__ o2, __half2* __restrict__ o3)
{
    const int total = WE0 + WE1 + WE2 + WE3;
    int i = blockIdx.x * 256 + threadIdx.x;
    const int stride = gridDim.x * 256;
    for (; i < total; i += stride) {
        const float* W; __half2* O; int j, N;
        if (i < WE0)                   { W = w0; O = o0; j = i;                 N = 6144; }
        else if (i < WE0 + WE1)        { W = w1; O = o1; j = i - WE0;           N = 2048; }
        else if (i < WE0 + WE1 + WE2)  { W = w2; O = o2; j = i - WE0 - WE1;     N = 4096; }
        else                           { W = w3; O = o3; j = i - WE0 - WE1 - WE2; N = 2048; }
        int n = j % N;
        size_t base = 2 * (size_t)j - n;
        O[j] = __floats2half2_rn(W[base], W[base + N]);
    }
}

// ======================= final residual join: out = a + b =======================
__global__ void add_kernel(const float* __restrict__ a, const float* __restrict__ b,
                           float* __restrict__ o) {
    int i = blockIdx.x * 256 + threadIdx.x;
    float4 va = ((const float4*)a)[i];
    float4 vb = ((const float4*)b)[i];
    ((float4*)o)[i] = make_float4(va.x + vb.x, va.y + vb.y, va.z + vb.z, va.w + vb.w);
}

// ======================= fp16 mma.sync GEMM =======================
#define BM 128
#define BN 128
#define BK 32
#define AE 20
#define BE 132
#define A_ENT (BM * AE)                  // 2560
#define B_ENT (16 * BE)                  // 2112
#define STG_ENT (A_ENT + B_ENT)          // 4672 entries = 18688 B
#define STAGES 3
#define SM_TOTAL (STAGES * STG_ENT * 4)  // 56064 bytes

__global__ __launch_bounds__(128, 2)
void tc_gemm_kernel(const __half* __restrict__ A, const __half2* __restrict__ Wh,
                    const float* __restrict__ bias, const float* __restrict__ res,
                    void* __restrict__ Cv, int M, int N, int K, int do_gelu, int out_half)
{
    extern __shared__ uint32_t smem[];
    const uint32_t sm0 = smem_u32(smem);
    const int tid  = threadIdx.x;
    const int wid  = tid >> 5;
    const int lane = tid & 31;
    const int gid  = lane >> 2;
    const int tig  = lane & 3;
    const int wm   = wid >> 1;
    const int wn   = wid & 1;
    const int row0 = blockIdx.y * BM;
    const int col0 = blockIdx.x * BN;

    float acc[4][8][4];
    #pragma unroll
    for (int mi = 0; mi < 4; mi++)
        #pragma unroll
        for (int ni = 0; ni < 8; ni++)
            #pragma unroll
            for (int e = 0; e < 4; e++) acc[mi][ni][e] = 0.f;

    const int niter = K >> 5;

    auto load_stage = [&](int buf, int iter) {
        const int k0  = iter << 5;
        const int kp0 = iter << 4;
        const uint32_t sb = sm0 + (uint32_t)buf * (STG_ENT * 4);
        #pragma unroll
        for (int t = 0; t < 8; t++) {
            int c = tid + t * 128;
            const void* g;
            uint32_t s;
            if (c < 512) {
                int row = c >> 2, ch = c & 3;
                g = A + (size_t)(row0 + row) * K + k0 + ch * 8;
                s = sb + (uint32_t)(row * 80 + ch * 16);
            } else {
                int cc = c - 512;
                int row = cc >> 5, c4 = cc & 31;
                g = Wh + (size_t)(kp0 + row) * N + col0 + c4 * 4;
                s = sb + (uint32_t)(A_ENT * 4 + row * 528 + c4 * 16);
            }
            CP_ASYNC16(s, g);
        }
        CP_COMMIT();
    };

    if (0 < niter) { load_stage(0, 0); }
    if (1 < niter) { load_stage(1, 1); }

    for (int i = 0; i < niter; i++) {
        if (i + 2 < niter) load_stage((i + 2) % STAGES, i + 2);
        if (i + 2 < niter)      { CP_WAIT2(); }
        else if (i + 1 < niter) { CP_WAIT1(); }
        else                    { CP_WAIT0(); }
        __syncthreads();

        const uint32_t* sA = smem + (i % STAGES) * STG_ENT;
        const uint32_t* sB = sA + A_ENT;
        const uint32_t* pa = sA + (wm * 64 + gid) * AE + tig;
        const uint32_t* pb = sB + tig * BE + wn * 64 + gid;

        #pragma unroll
        for (int s = 0; s < 2; s++) {
            uint32_t bfr[8][2];
            #pragma unroll
            for (int ni = 0; ni < 8; ni++) {
                bfr[ni][0] = pb[(s * 8)     * BE + ni * 8];
                bfr[ni][1] = pb[(s * 8 + 4) * BE + ni * 8];
            }
            #pragma unroll
            for (int mi = 0; mi < 4; mi++) {
                const uint32_t* p = pa + mi * 16 * AE + s * 8;
                uint32_t a0 = p[0];
                uint32_t a1 = p[8 * AE];
                uint32_t a2 = p[4];
                uint32_t a3 = p[8 * AE + 4];
                #pragma unroll
                for (int ni = 0; ni < 8; ni++)
                    mma_f16(acc[mi][ni][0], acc[mi][ni][1], acc[mi][ni][2], acc[mi][ni][3],
                            a0, a1, a2, a3, bfr[ni][0], bfr[ni][1]);
            }
        }
        __syncthreads();
    }

    #pragma unroll
    for (int mi = 0; mi < 4; mi++) {
        #pragma unroll
        for (int half = 0; half < 2; half++) {
            const size_t r = (size_t)(row0 + wm * 64 + mi * 16 + gid + half * 8);
            #pragma unroll
            for (int ni = 0; ni < 8; ni++) {
                const int cc = col0 + wn * 64 + ni * 8 + tig * 2;
                float v0 = acc[mi][ni][half * 2 + 0] + bias[cc];
                float v1 = acc[mi][ni][half * 2 + 1] + bias[cc + 1];
                if (do_gelu) {
                    v0 = 0.5f * v0 * (1.f + erff(v0 * 0.70710678118654752f));
                    v1 = 0.5f * v1 * (1.f + erff(v1 * 0.70710678118654752f));
                }
                if (res) {
                    float2 rr = *(const float2*)&res[r * N + cc];
                    v0 += rr.x; v1 += rr.y;
                }
                if (out_half) {
                    *(__half2*)((__half*)Cv + r * N + cc) = __floats2half2_rn(v0, v1);
                } else {
                    *(float2*)((float*)Cv + r * N + cc) = make_float2(v0, v1);
                }
            }
        }
    }
}

// ---------------- fused double LayerNorm (fp16 outputs) ----------------
__global__ void ln_kernel(const float* __restrict__ x,
                          const float* __restrict__ aw, const float* __restrict__ ab,
                          const float* __restrict__ fw, const float* __restrict__ fb,
                          __half* __restrict__ nx, __half* __restrict__ f)
{
    int row = blockIdx.x;
    int tid = threadIdx.x;
    const float4* xr = (const float4*)(x + (size_t)row * Dz);
    float4 a = xr[tid];
    float4 b = xr[tid + 256];
    float s  = a.x + a.y + a.z + a.w + b.x + b.y + b.z + b.w;
    float ss = a.x*a.x + a.y*a.y + a.z*a.z + a.w*a.w
             + b.x*b.x + b.y*b.y + b.z*b.z + b.w*b.w;
    #pragma unroll
    for (int o = 16; o; o >>= 1) {
        s  += __shfl_xor_sync(0xffffffffu, s,  o);
        ss += __shfl_xor_sync(0xffffffffu, ss, o);
    }
    __shared__ float r1[8], r2[8];
    __shared__ float mv[2];
    int wid = tid >> 5;
    if ((tid & 31) == 0) { r1[wid] = s; r2[wid] = ss; }
    __syncthreads();
    if (tid == 0) {
        float S = 0.f, SS = 0.f;
        #pragma unroll
        for (int i = 0; i < 8; i++) { S += r1[i]; SS += r2[i]; }
        float m   = S * (1.f / Dz);
        float var = SS * (1.f / Dz) - m * m;
        mv[0] = m;
        mv[1] = rsqrtf(var + EPSF);
    }
    __syncthreads();
    float m = mv[0], r = mv[1];

    __half* nxr = nx + (size_t)row * Dz;
    __half* fr  = f  + (size_t)row * Dz;
    const float4* aw4 = (const float4*)aw;  const float4* ab4 = (const float4*)ab;
    const float4* fw4 = (const float4*)fw;  const float4* fb4 = (const float4*)fb;
    #pragma unroll
    for (int e = 0; e < 2; e++) {
        int slot = tid + e * 256;
        float4 v = (e == 0) ? a : b;
        float4 w1 = aw4[slot], b1 = ab4[slot], w2 = fw4[slot], b2 = fb4[slot];
        __half2 h0 = __floats2half2_rn((v.x - m) * r * w1.x + b1.x, (v.y - m) * r * w1.y + b1.y);
        __half2 h1 = __floats2half2_rn((v.z - m) * r * w1.z + b1.z, (v.w - m) * r * w1.w + b1.w);
        __half2 g0 = __floats2half2_rn((v.x - m) * r * w2.x + b2.x, (v.y - m) * r * w2.y + b2.y);
        __half2 g1 = __floats2half2_rn((v.z - m) * r * w2.z + b2.z, (v.w - m) * r * w2.w + b2.w);
        *(__half2*)(nxr + slot * 4)     = h0;
        *(__half2*)(nxr + slot * 4 + 2) = h1;
        *(__half2*)(fr  + slot * 4)     = g0;
        *(__half2*)(fr  + slot * 4 + 2) = g1;
    }
}

// ---------------- per-head RMS norm + RoPE + q scaling + tf32 round (q,k only) ----------------
__global__ void qkrope_kernel(float* __restrict__ qkv, const float* __restrict__ fc,
                              const float* __restrict__ qn_w, const float* __restrict__ kn_w)
{
    int blk   = blockIdx.x;
    int token = blk >> 4;
    int h     = blk & 15;
    int s     = token & (Sz - 1);
    int sel   = threadIdx.x >> 7;       // 0=q, 1=k
    int d     = threadIdx.x & 127;
    float* ptr = qkv + (size_t)token * (3 * Dz) + sel * Dz + h * HDz;
    float v = ptr[d];
    float ss = v * v;
    #pragma unroll
    for (int o = 16; o; o >>= 1) ss += __shfl_xor_sync(0xffffffffu, ss, o);
    __shared__ float red[8];
    __shared__ float rstd_s[2];
    int wid = threadIdx.x >> 5;
    if ((threadIdx.x & 31) == 0) red[wid] = ss;
    __syncthreads();
    if (d == 0) {
        float t = red[sel * 4] + red[sel * 4 + 1] + red[sel * 4 + 2] + red[sel * 4 + 3];
        rstd_s[sel] = rsqrtf(t * (1.f / HDz) + EPSF);
    }
    __syncthreads();
    float rstd = rstd_s[sel];
    float w = sel ? kn_w[d] : qn_w[d];
    float nv = v * rstd * w;
    if (d < RNz) {
        int j = d >> 1;
        float c  = fc[(s * 16 + j) * 2];
        float sn = fc[(s * 16 + j) * 2 + 1];
        float a = __shfl_sync(0xffffffffu, nv, j);
        float b = __shfl_sync(0xffffffffu, nv, j + 16);
        nv = (d & 1) ? (b * c + a * sn) : (a * c - b * sn);
    }
    if (sel == 0) nv *= SCALEF;
    ptr[d] = tf32v(nv);
}

// ======================= FA2-style windowed attention =======================
#define AT_CK 32
#define KSTR 132
#define VSTR 136
#define AT_K_OFF(buf) ((buf) * (AT_CK * KSTR))
#define AT_V_OFF(buf) (2 * AT_CK * KSTR + (buf) * (AT_CK * VSTR))
#define AT_SMEM_FLOATS (2 * AT_CK * KSTR + 2 * AT_CK * VSTR)   // 17152
#define AT_SMEM_BYTES  (AT_SMEM_FLOATS * 4)                     // 68608

__global__ __launch_bounds__(128, 2)
void attn_mma_kernel(const float* __restrict__ qkv, __half* __restrict__ y)
{
    extern __shared__ float sm[];
    const uint32_t sm0 = smem_u32(sm);
    const int tid  = threadIdx.x;
    const int wi   = tid >> 5;
    const int lane = tid & 31;
    const int gid  = lane >> 2;
    const int tig  = lane & 3;
    const int qb0  = (blockIdx.x & 31) << 6;
    const int h    = (blockIdx.x >> 5) & 15;
    const int b    = blockIdx.x >> 9;
    const int qw   = qb0 + wi * 16;

    uint32_t qf[16][4];
    {
        const float* q0 = qkv + (size_t)(b * Sz + qw + gid) * (3 * Dz) + h * HDz;
        const float* q1 = q0 + (size_t)8 * (3 * Dz);
        #pragma unroll
        for (int kg = 0; kg < 16; kg++) {
            qf[kg][0] = __float_as_uint(q0[kg * 8 + tig]);
            qf[kg][1] = __float_as_uint(q1[kg * 8 + tig]);
            qf[kg][2] = __float_as_uint(q0[kg * 8 + tig + 4]);
            qf[kg][3] = __float_as_uint(q1[kg * 8 + tig + 4]);
        }
    }

    float o[16][4];
    #pragma unroll
    for (int dt = 0; dt < 16; dt++)
        #pragma unroll
        for (int e = 0; e < 4; e++) o[dt][e] = 0.f;
    float m0 = -1e30f, m1 = -1e30f, l0 = 0.f, l1 = 0.f;

    int cs = qb0 - (WINz - 1); if (cs < 0) cs = 0;
    cs &= ~31;
    const int nc = ((qb0 + 63 - cs) >> 5) + 1;

    auto load_chunk = [&](int buf, int jc) {
        #pragma unroll
        for (int i = 0; i < 8; i++) {
            int fidx = i * 128 + tid;
            int row = fidx >> 5, c4 = fidx & 31;
            const float* gk = qkv + (size_t)(b * Sz + jc + row) * (3 * Dz) + Dz + h * HDz + c4 * 4;
            CP_ASYNC16(sm0 + (uint32_t)(AT_K_OFF(buf) + row * KSTR + c4 * 4) * 4, gk);
        }
        #pragma unroll
        for (int i = 0; i < 8; i++) {
            int fidx = i * 128 + tid;
            int row = fidx >> 5, c4 = fidx & 31;
            const float* gv = qkv + (size_t)(b * Sz + jc + row) * (3 * Dz) + 2 * Dz + h * HDz + c4 * 4;
            CP_ASYNC16(sm0 + (uint32_t)(AT_V_OFF(buf) + row * VSTR + c4 * 4) * 4, gv);
        }
        CP_COMMIT();
    };

    load_chunk(0, cs);

    for (int c = 0; c < nc; c++) {
        const int jc  = cs + c * 32;
        const int buf = c & 1;
        if (c + 1 < nc) { load_chunk((c + 1) & 1, jc + 32); CP_WAIT1(); }
        else            { CP_WAIT0(); }
        __syncthreads();

        const bool act = (jc <= qw + 15) && (jc + 31 >= qw - (WINz - 1));
        if (act) {
            const uint32_t* Ks = (const uint32_t*)(sm + AT_K_OFF(buf));
            const uint32_t* Vs = (const uint32_t*)(sm + AT_V_OFF(buf));

            float sc[4][4];
            #pragma unroll
            for (int ng = 0; ng < 4; ng++)
                #pragma unroll
                for (int e = 0; e < 4; e++) sc[ng][e] = 0.f;
            #pragma unroll
            for (int kg = 0; kg < 16; kg++) {
                #pragma unroll
                for (int ng = 0; ng < 4; ng++) {
                    const uint32_t* kp = Ks + (ng * 8 + gid) * KSTR + kg * 8 + tig;
                    mma_tf32(sc[ng][0], sc[ng][1], sc[ng][2], sc[ng][3],
                             qf[kg][0], qf[kg][1], qf[kg][2], qf[kg][3],
                             kp[0], kp[4]);
                }
            }

            const int q0r = qw + gid, q1r = qw + gid + 8;
            float smax0 = -1e30f, smax1 = -1e30f;
            #pragma unroll
            for (int ng = 0; ng < 4; ng++) {
                int j0 = jc + ng * 8 + tig * 2;
                smax0 = fmaxf(smax0, ((unsigned)(q0r - j0)     < 256u) ? sc[ng][0] : -1e30f);
                smax0 = fmaxf(smax0, ((unsigned)(q0r - j0 - 1) < 256u) ? sc[ng][1] : -1e30f);
                smax1 = fmaxf(smax1, ((unsigned)(q1r - j0)     < 256u) ? sc[ng][2] : -1e30f);
                smax1 = fmaxf(smax1, ((unsigned)(q1r - j0 - 1) < 256u) ? sc[ng][3] : -1e30f);
            }
            smax0 = fmaxf(smax0, __shfl_xor_sync(0xffffffffu, smax0, 1));
            smax0 = fmaxf(smax0, __shfl_xor_sync(0xffffffffu, smax0, 2));
            smax1 = fmaxf(smax1, __shfl_xor_sync(0xffffffffu, smax1, 1));
            smax1 = fmaxf(smax1, __shfl_xor_sync(0xffffffffu, smax1, 2));
            float m0n = fmaxf(m0, smax0), m1n = fmaxf(m1, smax1);
            float cr0 = __expf(m0 - m0n), cr1 = __expf(m1 - m1n);
            m0 = m0n; m1 = m1n;

            float ps0 = 0.f, ps1 = 0.f;
            #pragma unroll
            for (int ng = 0; ng < 4; ng++) {
                int j0 = jc + ng * 8 + tig * 2;
                float e;
                e = ((unsigned)(q0r - j0)     < 256u) ? __expf(sc[ng][0] - m0) : 0.f;
                sc[ng][0] = e; ps0 += e;
                e = ((unsigned)(q0r - j0 - 1) < 256u) ? __expf(sc[ng][1] - m0) : 0.f;
                sc[ng][1] = e; ps0 += e;
                e = ((unsigned)(q1r - j0)     < 256u) ? __expf(sc[ng][2] - m1) : 0.f;
                sc[ng][2] = e; ps1 += e;
                e = ((unsigned)(q1r - j0 - 1) < 256u) ? __expf(sc[ng][3] - m1) : 0.f;
                sc[ng][3] = e; ps1 += e;
            }
            ps0 += __shfl_xor_sync(0xffffffffu, ps0, 1);
            ps0 += __shfl_xor_sync(0xffffffffu, ps0, 2);
            ps1 += __shfl_xor_sync(0xffffffffu, ps1, 1);
            ps1 += __shfl_xor_sync(0xffffffffu, ps1, 2);
            l0 = l0 * cr0 + ps0;
            l1 = l1 * cr1 + ps1;

            #pragma unroll
            for (int dt = 0; dt < 16; dt++) {
                o[dt][0] *= cr0; o[dt][1] *= cr0;
                o[dt][2] *= cr1; o[dt][3] *= cr1;
            }

            uint32_t af[4][4];
            const int src  = (lane & ~3) | (tig >> 1);
            const int src2 = src + 2;
            #pragma unroll
            for (int ng = 0; ng < 4; ng++) {
                float v0 = __shfl_sync(0xffffffffu, sc[ng][0], src);
                float v1 = __shfl_sync(0xffffffffu, sc[ng][1], src);
                float v2 = __shfl_sync(0xffffffffu, sc[ng][2], src);
                float v3 = __shfl_sync(0xffffffffu, sc[ng][3], src);
                float w0 = __shfl_sync(0xffffffffu, sc[ng][0], src2);
                float w1 = __shfl_sync(0xffffffffu, sc[ng][1], src2);
                float w2 = __shfl_sync(0xffffffffu, sc[ng][2], src2);
                float w3 = __shfl_sync(0xffffffffu, sc[ng][3], src2);
                af[ng][0] = f2tf32((tig & 1) ? v1 : v0);
                af[ng][1] = f2tf32((tig & 1) ? v3 : v2);
                af[ng][2] = f2tf32((tig & 1) ? w1 : w0);
                af[ng][3] = f2tf32((tig & 1) ? w3 : w2);
            }

            #pragma unroll
            for (int dt = 0; dt < 16; dt++) {
                #pragma unroll
                for (int ng = 0; ng < 4; ng++) {
                    const uint32_t* vp = Vs + (ng * 8 + tig) * VSTR + dt * 8 + gid;
                    mma_tf32(o[dt][0], o[dt][1], o[dt][2], o[dt][3],
                             af[ng][0], af[ng][1], af[ng][2], af[ng][3],
                             vp[0], vp[4 * VSTR]);
                }
            }
        }
        __syncthreads();
    }

    const float i0 = 1.f / l0, i1 = 1.f / l1;
    __half* y0 = y + (size_t)(b * Sz + qw + gid) * Dz + h * HDz;
    __half* y1 = y0 + (size_t)8 * Dz;
    #pragma unroll
    for (int dt = 0; dt < 16; dt++) {
        *(__half2*)(y0 + dt * 8 + tig * 2) = __floats2half2_rn(o[dt][0] * i0, o[dt][1] * i0);
        *(__half2*)(y1 + dt * 8 + tig * 2) = __floats2half2_rn(o[dt][2] * i1, o[dt][3] * i1);
    }
}

// ---------------- launch ----------------
extern "C" void kernel_launch(void* const* d_in, const int* in_sizes, int n_in,
                              void* d_out, int out_size)
{
    const float* x      = (const float*)d_in[0];
    const float* fc     = (const float*)d_in[1];
    // d_in[2] = mask (implicit: causal sliding window of 256)
    const float* wqkv_w = (const float*)d_in[3];
    const float* wqkv_b = (const float*)d_in[4];
    const float* wo_w   = (const float*)d_in[5];
    const float* wo_b   = (const float*)d_in[6];
    const float* qn_w   = (const float*)d_in[7];
    const float* kn_w   = (const float*)d_in[8];
    const float* aln_w  = (const float*)d_in[9];
    const float* aln_b  = (const float*)d_in[10];
    const float* fln_w  = (const float*)d_in[11];
    const float* fln_b  = (const float*)d_in[12];
    const float* w1_w   = (const float*)d_in[13];
    const float* w1_b   = (const float*)d_in[14];
    const float* w2_w   = (const float*)d_in[15];
    const float* w2_b   = (const float*)d_in[16];
    float* out = (float*)d_out;

    __half *nx, *f, *y, *ffn;
    float *qkv, *h, *ffo;
    __half2 *wqkvH, *woH, *w1H, *w2H;
    cudaGetSymbolAddress((void**)&nx,    g_nx);
    cudaGetSymbolAddress((void**)&f,     g_f);
    cudaGetSymbolAddress((void**)&qkv,   g_qkv);
    cudaGetSymbolAddress((void**)&y,     g_y);
    cudaGetSymbolAddress((void**)&h,     g_h);
    cudaGetSymbolAddress((void**)&ffn,   g_ffn);
    cudaGetSymbolAddress((void**)&ffo,   g_ffo);
    cudaGetSymbolAddress((void**)&wqkvH, g_wqkvH);
    cudaGetSymbolAddress((void**)&woH,   g_woH);
    cudaGetSymbolAddress((void**)&w1H,   g_w1H);
    cudaGetSymbolAddress((void**)&w2H,   g_w2H);

    static int init_done = 0;
    static cudaStream_t s2;
    static cudaEvent_t evL, evW, ev1;
    if (!init_done) {
        cudaFuncSetAttribute(tc_gemm_kernel,
                             cudaFuncAttributeMaxDynamicSharedMemorySize, SM_TOTAL);
        cudaFuncSetAttribute(attn_mma_kernel,
                             cudaFuncAttributeMaxDynamicSharedMemorySize, AT_SMEM_BYTES);
        cudaStreamCreateWithFlags(&s2, cudaStreamNonBlocking);
        cudaEventCreateWithFlags(&evL, cudaEventDisableTiming);
        cudaEventCreateWithFlags(&evW, cudaEventDisableTiming);
        cudaEventCreateWithFlags(&ev1, cudaEventDisableTiming);
        init_done = 1;
    }

    // ---- stream 0: LN first (first captured node), then fork to s2 ----
    ln_kernel<<<TOK, 256>>>(x, aln_w, aln_b, fln_w, fln_b, nx, f);
    cudaEventRecord(evL, 0);

    // ---- stream s2: merged weight pack -> evW, then FFN tower -> ev1 ----
    cudaStreamWaitEvent(s2, evL, 0);
    wconv_all_kernel<<<16384, 256, 0, s2>>>(wqkv_w, wo_w, w1_w, w2_w,
                                            wqkvH, woH, w1H, w2H);
    cudaEventRecord(evW, s2);
    tc_gemm_kernel<<<dim3(FFz / BN, TOK / BM), 128, SM_TOTAL, s2>>>(
        f, w1H, w1_b, nullptr, ffn, TOK, FFz, Dz, 1, 1);
    tc_gemm_kernel<<<dim3(Dz / BN, TOK / BM), 128, SM_TOTAL, s2>>>(
        ffn, w2H, w2_b, nullptr, ffo, TOK, Dz, FFz, 0, 0);
    cudaEventRecord(ev1, s2);

    // ---- stream 0: attention chain (QKV needs wqkvH -> wait evW only) ----
    cudaStreamWaitEvent(0, evW, 0);
    tc_gemm_kernel<<<dim3(3 * Dz / BN, TOK / BM), 128, SM_TOTAL>>>(
        nx, wqkvH, wqkv_b, nullptr, qkv, TOK, 3 * Dz, Dz, 0, 0);
    qkrope_kernel<<<TOK * Hz, 256>>>(qkv, fc, qn_w, kn_w);
    attn_mma_kernel<<<Bz * Hz * (Sz / 64), 128, AT_SMEM_BYTES>>>(qkv, y);
    tc_gemm_kernel<<<dim3(Dz / BN, TOK / BM), 128, SM_TOTAL>>>(
        y, woH, wo_b, x, h, TOK, Dz, Dz, 0, 0);

    // ---- join: out = h + ffo ----
    cudaStreamWaitEvent(0, ev1, 0);
    add_kernel<<<(TOK * Dz / 4) / 256, 256>>>(h, ffo, out);
}